// round 1
// baseline (speedup 1.0000x reference)
#include <cuda_runtime.h>
#include <cuda_bf16.h>

// Problem constants
#define H 12
#define D 768
#define DH 64
#define B 8
#define S 1024
#define M_TOT (B * S)            // 8192
#define BH (B * H)               // 96
#define OUT_ELEMS (B * S * D)    // 6291456
#define PROBS_ELEMS (B * H * S * S)

// Scratch (device globals — allocation-free per harness rules)
__device__ float g_q[BH * S * DH];
__device__ float g_k[BH * S * DH];
__device__ float g_v[BH * S * DH];
__device__ float g_ctx[M_TOT * D];

// ---------------------------------------------------------------------------
// K1: QKV projection.  q/k/v[b,h,s,e] = sum_d x[b,s,d]*W[h,d,e] + bias[h,e]
// grid (M_TOT/64, H), block 256. 64x64 tile, K-tile 32, 4x4 per thread.
// ---------------------------------------------------------------------------
__global__ __launch_bounds__(256) void qkv_kernel(
    const float* __restrict__ x,
    const float* __restrict__ Wq, const float* __restrict__ bq,
    const float* __restrict__ Wk, const float* __restrict__ bk,
    const float* __restrict__ Wv, const float* __restrict__ bv)
{
    __shared__ float xs[64][33];
    __shared__ float wqs[32][65];
    __shared__ float wks[32][65];
    __shared__ float wvs[32][65];

    const int tid = threadIdx.x;
    const int tx = tid & 15;        // 0..15 -> cols
    const int ty = tid >> 4;        // 0..15 -> rows
    const int m0 = blockIdx.x * 64;
    const int h  = blockIdx.y;

    const float* Wqh = Wq + h * D * DH;
    const float* Wkh = Wk + h * D * DH;
    const float* Wvh = Wv + h * D * DH;

    float aq[4][4] = {}, ak[4][4] = {}, av[4][4] = {};

    for (int k0 = 0; k0 < D; k0 += 32) {
        // load x tile 64x32
        #pragma unroll
        for (int i = 0; i < 8; i++) {
            int idx = tid + i * 256;
            int r = idx >> 5, c = idx & 31;
            xs[r][c] = x[(m0 + r) * D + k0 + c];
        }
        // load W tiles 32x64 each
        #pragma unroll
        for (int i = 0; i < 8; i++) {
            int idx = tid + i * 256;
            int r = idx >> 6, c = idx & 63;
            wqs[r][c] = Wqh[(k0 + r) * DH + c];
            wks[r][c] = Wkh[(k0 + r) * DH + c];
            wvs[r][c] = Wvh[(k0 + r) * DH + c];
        }
        __syncthreads();

        #pragma unroll
        for (int kk = 0; kk < 32; kk++) {
            float a[4], bqf[4], bkf[4], bvf[4];
            #pragma unroll
            for (int i = 0; i < 4; i++) a[i] = xs[ty * 4 + i][kk];
            #pragma unroll
            for (int j = 0; j < 4; j++) {
                bqf[j] = wqs[kk][tx * 4 + j];
                bkf[j] = wks[kk][tx * 4 + j];
                bvf[j] = wvs[kk][tx * 4 + j];
            }
            #pragma unroll
            for (int i = 0; i < 4; i++)
                #pragma unroll
                for (int j = 0; j < 4; j++) {
                    aq[i][j] += a[i] * bqf[j];
                    ak[i][j] += a[i] * bkf[j];
                    av[i][j] += a[i] * bvf[j];
                }
        }
        __syncthreads();
    }

    #pragma unroll
    for (int i = 0; i < 4; i++) {
        int m = m0 + ty * 4 + i;
        int b = m >> 10;            // / S
        int s = m & 1023;
        int base = ((b * H + h) * S + s) * DH;
        #pragma unroll
        for (int j = 0; j < 4; j++) {
            int e = tx * 4 + j;
            g_q[base + e] = aq[i][j] + bq[h * DH + e];
            g_k[base + e] = ak[i][j] + bk[h * DH + e];
            g_v[base + e] = av[i][j] + bv[h * DH + e];
        }
    }
}

// ---------------------------------------------------------------------------
// K2: scores[bh, s, t] = (1/8) * sum_e q[bh,s,e]*k[bh,t,e]
// grid (S/64 t-tiles, S/64 s-tiles, BH), block 256.  K=64 single phase.
// ---------------------------------------------------------------------------
__global__ __launch_bounds__(256) void scores_kernel(float* __restrict__ probs)
{
    __shared__ float qs[64][65];
    __shared__ float ks[64][65];

    const int tid = threadIdx.x;
    const int tx = tid & 15;
    const int ty = tid >> 4;
    const int t0 = blockIdx.x * 64;
    const int s0 = blockIdx.y * 64;
    const int bh = blockIdx.z;

    const float* qp = g_q + bh * S * DH;
    const float* kp = g_k + bh * S * DH;

    // load q tile [64 x 64] and k tile [64 x 64]
    #pragma unroll
    for (int i = 0; i < 16; i++) {
        int idx = tid + i * 256;
        int r = idx >> 6, c = idx & 63;
        qs[r][c] = qp[(s0 + r) * DH + c];
        ks[r][c] = kp[(t0 + r) * DH + c];
    }
    __syncthreads();

    float acc[4][4] = {};
    #pragma unroll
    for (int e = 0; e < 64; e++) {
        float a[4], bb[4];
        #pragma unroll
        for (int i = 0; i < 4; i++) a[i] = qs[ty * 4 + i][e];
        #pragma unroll
        for (int j = 0; j < 4; j++) bb[j] = ks[tx * 4 + j][e];
        #pragma unroll
        for (int i = 0; i < 4; i++)
            #pragma unroll
            for (int j = 0; j < 4; j++)
                acc[i][j] += a[i] * bb[j];
    }

    #pragma unroll
    for (int i = 0; i < 4; i++) {
        int s = s0 + ty * 4 + i;
        float* row = probs + (size_t)(bh * S + s) * S;
        #pragma unroll
        for (int j = 0; j < 4; j++)
            row[t0 + tx * 4 + j] = acc[i][j] * 0.125f;
    }
}

// ---------------------------------------------------------------------------
// K3: row softmax in place on probs.  one block of 256 per row (len S=1024).
// ---------------------------------------------------------------------------
__global__ __launch_bounds__(256) void softmax_kernel(float* __restrict__ probs)
{
    __shared__ float red[256];
    const int tid = threadIdx.x;
    float* row = probs + (size_t)blockIdx.x * S;

    float v[4];
    #pragma unroll
    for (int i = 0; i < 4; i++) v[i] = row[tid + i * 256];

    float m = fmaxf(fmaxf(v[0], v[1]), fmaxf(v[2], v[3]));
    red[tid] = m;
    __syncthreads();
    for (int off = 128; off > 0; off >>= 1) {
        if (tid < off) red[tid] = fmaxf(red[tid], red[tid + off]);
        __syncthreads();
    }
    m = red[0];
    __syncthreads();

    float sum = 0.f;
    #pragma unroll
    for (int i = 0; i < 4; i++) { v[i] = __expf(v[i] - m); sum += v[i]; }
    red[tid] = sum;
    __syncthreads();
    for (int off = 128; off > 0; off >>= 1) {
        if (tid < off) red[tid] += red[tid + off];
        __syncthreads();
    }
    float inv = 1.f / red[0];

    #pragma unroll
    for (int i = 0; i < 4; i++) row[tid + i * 256] = v[i] * inv;
}

// ---------------------------------------------------------------------------
// K4: ctx[b,s, h*64+e] = sum_t probs[bh,s,t] * v[bh,t,e]
// grid (S/64 s-tiles, BH).  M=64 tile, N=64 (full DH), K-tile 32.
// ---------------------------------------------------------------------------
__global__ __launch_bounds__(256) void ctx_kernel(const float* __restrict__ probs)
{
    __shared__ float ps[64][33];
    __shared__ float vs[32][65];

    const int tid = threadIdx.x;
    const int tx = tid & 15;
    const int ty = tid >> 4;
    const int s0 = blockIdx.x * 64;
    const int bh = blockIdx.y;

    const float* vp = g_v + bh * S * DH;

    float acc[4][4] = {};

    for (int k0 = 0; k0 < S; k0 += 32) {
        #pragma unroll
        for (int i = 0; i < 8; i++) {
            int idx = tid + i * 256;
            int r = idx >> 5, c = idx & 31;
            ps[r][c] = probs[(size_t)(bh * S + s0 + r) * S + k0 + c];
        }
        #pragma unroll
        for (int i = 0; i < 8; i++) {
            int idx = tid + i * 256;
            int r = idx >> 6, c = idx & 63;
            vs[r][c] = vp[(k0 + r) * DH + c];
        }
        __syncthreads();

        #pragma unroll
        for (int kk = 0; kk < 32; kk++) {
            float a[4], bb[4];
            #pragma unroll
            for (int i = 0; i < 4; i++) a[i] = ps[ty * 4 + i][kk];
            #pragma unroll
            for (int j = 0; j < 4; j++) bb[j] = vs[kk][tx * 4 + j];
            #pragma unroll
            for (int i = 0; i < 4; i++)
                #pragma unroll
                for (int j = 0; j < 4; j++)
                    acc[i][j] += a[i] * bb[j];
        }
        __syncthreads();
    }

    const int b = bh / H;
    const int h = bh % H;
    #pragma unroll
    for (int i = 0; i < 4; i++) {
        int s = s0 + ty * 4 + i;
        float* dst = g_ctx + (size_t)(b * S + s) * D + h * DH;
        #pragma unroll
        for (int j = 0; j < 4; j++)
            dst[tx * 4 + j] = acc[i][j];
    }
}

// ---------------------------------------------------------------------------
// K5: out[m,n] = sum_k ctx[m,k] * Wo[n,k] + bo[n]
// grid (M_TOT/64, D/64), block 256.
// ---------------------------------------------------------------------------
__global__ __launch_bounds__(256) void out_kernel(
    const float* __restrict__ Wo, const float* __restrict__ bo,
    float* __restrict__ out)
{
    __shared__ float As[64][33];
    __shared__ float Bs[32][65];

    const int tid = threadIdx.x;
    const int tx = tid & 15;
    const int ty = tid >> 4;
    const int m0 = blockIdx.x * 64;
    const int n0 = blockIdx.y * 64;

    float acc[4][4] = {};

    for (int k0 = 0; k0 < D; k0 += 32) {
        #pragma unroll
        for (int i = 0; i < 8; i++) {
            int idx = tid + i * 256;
            int r = idx >> 5, c = idx & 31;
            As[r][c] = g_ctx[(size_t)(m0 + r) * D + k0 + c];
        }
        // Wo tile: rows are n, cols are k; store transposed into Bs[k][n]
        #pragma unroll
        for (int i = 0; i < 8; i++) {
            int idx = tid + i * 256;
            int r = idx >> 5, c = idx & 31;   // r = n-offset, c = k-offset
            Bs[c][r] = Wo[(size_t)(n0 + r) * D + k0 + c];
        }
        __syncthreads();

        #pragma unroll
        for (int kk = 0; kk < 32; kk++) {
            float a[4], bb[4];
            #pragma unroll
            for (int i = 0; i < 4; i++) a[i] = As[ty * 4 + i][kk];
            #pragma unroll
            for (int j = 0; j < 4; j++) bb[j] = Bs[kk][tx * 4 + j];
            #pragma unroll
            for (int i = 0; i < 4; i++)
                #pragma unroll
                for (int j = 0; j < 4; j++)
                    acc[i][j] += a[i] * bb[j];
        }
        __syncthreads();
    }

    #pragma unroll
    for (int i = 0; i < 4; i++) {
        int m = m0 + ty * 4 + i;
        #pragma unroll
        for (int j = 0; j < 4; j++) {
            int n = n0 + tx * 4 + j;
            out[(size_t)m * D + n] = acc[i][j] + bo[n];
        }
    }
}

// ---------------------------------------------------------------------------
extern "C" void kernel_launch(void* const* d_in, const int* in_sizes, int n_in,
                              void* d_out, int out_size)
{
    const float* x  = (const float*)d_in[0];
    const float* Wq = (const float*)d_in[1];
    const float* bq = (const float*)d_in[2];
    const float* Wk = (const float*)d_in[3];
    const float* bk = (const float*)d_in[4];
    const float* Wv = (const float*)d_in[5];
    const float* bv = (const float*)d_in[6];
    const float* Wo = (const float*)d_in[7];
    const float* bo = (const float*)d_in[8];

    float* out   = (float*)d_out;
    float* probs = out + OUT_ELEMS;

    qkv_kernel<<<dim3(M_TOT / 64, H), 256>>>(x, Wq, bq, Wk, bk, Wv, bv);
    scores_kernel<<<dim3(S / 64, S / 64, BH), 256>>>(probs);
    softmax_kernel<<<B * H * S, 256>>>(probs);
    ctx_kernel<<<dim3(S / 64, BH), 256>>>(probs);
    out_kernel<<<dim3(M_TOT / 64, D / 64), 256>>>(Wo, bo, out);
}

// round 2
// speedup vs baseline: 2.1880x; 2.1880x over previous
#include <cuda_runtime.h>
#include <cuda_bf16.h>
#include <cstdint>

// Problem constants
#define H 12
#define D 768
#define DH 64
#define B 8
#define S 1024
#define M_TOT (B * S)            // 8192
#define BH (B * H)               // 96
#define OUT_ELEMS (B * S * D)    // 6291456
#define NQKV (H * 3 * DH)        // 2304 : packed [h][q|k|v][e] columns

// Scratch (device globals — allocation-free per harness rules)
__device__ float g_q[BH * S * DH];
__device__ float g_k[BH * S * DH];
__device__ float g_v[BH * S * DH];
__device__ float g_ctx[M_TOT * D];

// ---------------------------------------------------------------------------
// helpers
// ---------------------------------------------------------------------------
__device__ __forceinline__ uint32_t f2tf(float x) {
    uint32_t r;
    asm("cvt.rna.tf32.f32 %0, %1;" : "=r"(r) : "f"(x));
    return r;
}

__device__ __forceinline__ void mma_tf32(float c[4], const uint32_t a[4],
                                         const uint32_t b[2]) {
    asm volatile(
        "mma.sync.aligned.m16n8k8.row.col.f32.tf32.tf32.f32 "
        "{%0,%1,%2,%3}, {%4,%5,%6,%7}, {%8,%9}, {%0,%1,%2,%3};\n"
        : "+f"(c[0]), "+f"(c[1]), "+f"(c[2]), "+f"(c[3])
        : "r"(a[0]), "r"(a[1]), "r"(a[2]), "r"(a[3]), "r"(b[0]), "r"(b[1]));
}

// ---------------------------------------------------------------------------
// K1: fused QKV projection as ONE GEMM: [8192 x 2304] = x[8192x768] @ Wcat
// column n -> h = n/192, which = (n%192)/64 (0=q,1=k,2=v), e = n%64
// block tile 128x128, BLK_K=32, 8 warps (2m x 4n), warp tile 64x32
// ---------------------------------------------------------------------------
__global__ __launch_bounds__(256, 2) void qkv_kernel(
    const float* __restrict__ x,
    const float* __restrict__ Wq, const float* __restrict__ bq,
    const float* __restrict__ Wk, const float* __restrict__ bk,
    const float* __restrict__ Wv, const float* __restrict__ bv)
{
    __shared__ uint32_t As[128][36];    // stride 36: bank = (4r+c)%32, conflict-free frags
    __shared__ uint32_t Bs[32][132];    // stride 132: bank = (4k+n)%32

    const int tid  = threadIdx.x;
    const int lane = tid & 31;
    const int warp = tid >> 5;
    const int wm   = warp & 1;          // 0..1
    const int wn   = warp >> 1;         // 0..3
    const int m0   = blockIdx.x * 128;
    const int n0   = blockIdx.y * 128;
    const int lr   = lane >> 2;         // 0..7
    const int lc   = lane & 3;          // 0..3

    float acc[4][4][4];
    #pragma unroll
    for (int i = 0; i < 4; i++)
        #pragma unroll
        for (int j = 0; j < 4; j++)
            #pragma unroll
            for (int t = 0; t < 4; t++) acc[i][j][t] = 0.f;

    for (int k0 = 0; k0 < D; k0 += 32) {
        // A tile 128x32 (float4)
        #pragma unroll
        for (int i = 0; i < 4; i++) {
            int linear = tid + i * 256;                // 1024 float4 units
            int r = linear >> 3, c4 = (linear & 7) << 2;
            float4 v = *(const float4*)&x[(size_t)(m0 + r) * D + k0 + c4];
            As[r][c4 + 0] = f2tf(v.x); As[r][c4 + 1] = f2tf(v.y);
            As[r][c4 + 2] = f2tf(v.z); As[r][c4 + 3] = f2tf(v.w);
        }
        // B tile 32x128 with per-column routing into Wq/Wk/Wv
        #pragma unroll
        for (int i = 0; i < 16; i++) {
            int linear = tid + i * 256;                // 4096 elems
            int r = linear >> 7, c = linear & 127;
            int gn = n0 + c;
            int h = gn / 192, rem = gn % 192;
            int which = rem >> 6, e = rem & 63;
            const float* wp = (which == 0) ? Wq : (which == 1) ? Wk : Wv;
            Bs[r][c] = f2tf(wp[((size_t)h * D + (k0 + r)) * DH + e]);
        }
        __syncthreads();

        #pragma unroll
        for (int ks = 0; ks < 32; ks += 8) {
            uint32_t af[4][4], bf[4][2];
            #pragma unroll
            for (int mi = 0; mi < 4; mi++) {
                int r = wm * 64 + mi * 16 + lr;
                af[mi][0] = As[r][ks + lc];
                af[mi][1] = As[r + 8][ks + lc];
                af[mi][2] = As[r][ks + 4 + lc];
                af[mi][3] = As[r + 8][ks + 4 + lc];
            }
            #pragma unroll
            for (int nj = 0; nj < 4; nj++) {
                int n = wn * 32 + nj * 8 + lr;
                bf[nj][0] = Bs[ks + lc][n];
                bf[nj][1] = Bs[ks + 4 + lc][n];
            }
            #pragma unroll
            for (int mi = 0; mi < 4; mi++)
                #pragma unroll
                for (int nj = 0; nj < 4; nj++)
                    mma_tf32(acc[mi][nj], af[mi], bf[nj]);
        }
        __syncthreads();
    }

    // epilogue: route to g_q / g_k / g_v with bias
    #pragma unroll
    for (int mi = 0; mi < 4; mi++) {
        #pragma unroll
        for (int nj = 0; nj < 4; nj++) {
            #pragma unroll
            for (int t = 0; t < 4; t++) {
                int r  = m0 + wm * 64 + mi * 16 + lr + ((t >= 2) ? 8 : 0);
                int gn = n0 + wn * 32 + nj * 8 + (lc << 1) + (t & 1);
                int b = r >> 10, s = r & 1023;
                int h = gn / 192, rem = gn % 192;
                int which = rem >> 6, e = rem & 63;
                const float* bp = (which == 0) ? bq : (which == 1) ? bk : bv;
                float* dst = (which == 0) ? g_q : (which == 1) ? g_k : g_v;
                dst[(((size_t)b * H + h) * S + s) * DH + e] =
                    acc[mi][nj][t] + bp[h * DH + e];
            }
        }
    }
}

// ---------------------------------------------------------------------------
// K2: scores[bh,s,t] = (1/8) * q[bh,s,:] . k[bh,t,:]   (K = 64)
// block tile 128s x 128t, BLK_K=32
// ---------------------------------------------------------------------------
__global__ __launch_bounds__(256, 2) void scores_kernel(float* __restrict__ probs)
{
    __shared__ uint32_t As[128][36];
    __shared__ uint32_t Bs[32][132];

    const int tid  = threadIdx.x;
    const int lane = tid & 31;
    const int warp = tid >> 5;
    const int wm   = warp & 1;
    const int wn   = warp >> 1;
    const int t0   = blockIdx.x * 128;
    const int s0   = blockIdx.y * 128;
    const int bh   = blockIdx.z;
    const int lr   = lane >> 2;
    const int lc   = lane & 3;

    const float* qp = g_q + (size_t)bh * S * DH;
    const float* kp = g_k + (size_t)bh * S * DH;

    float acc[4][4][4];
    #pragma unroll
    for (int i = 0; i < 4; i++)
        #pragma unroll
        for (int j = 0; j < 4; j++)
            #pragma unroll
            for (int t = 0; t < 4; t++) acc[i][j][t] = 0.f;

    for (int k0 = 0; k0 < DH; k0 += 32) {
        // A: q tile 128x32
        #pragma unroll
        for (int i = 0; i < 4; i++) {
            int linear = tid + i * 256;
            int r = linear >> 3, c4 = (linear & 7) << 2;
            float4 v = *(const float4*)&qp[(size_t)(s0 + r) * DH + k0 + c4];
            As[r][c4 + 0] = f2tf(v.x); As[r][c4 + 1] = f2tf(v.y);
            As[r][c4 + 2] = f2tf(v.z); As[r][c4 + 3] = f2tf(v.w);
        }
        // B: transpose-load k tile -> Bs[k][n] = kp[(t0+n)*DH + k0+k]
        #pragma unroll
        for (int i = 0; i < 4; i++) {
            int linear = tid + i * 256;
            int n = linear >> 3, k4 = (linear & 7) << 2;
            float4 v = *(const float4*)&kp[(size_t)(t0 + n) * DH + k0 + k4];
            Bs[k4 + 0][n] = f2tf(v.x); Bs[k4 + 1][n] = f2tf(v.y);
            Bs[k4 + 2][n] = f2tf(v.z); Bs[k4 + 3][n] = f2tf(v.w);
        }
        __syncthreads();

        #pragma unroll
        for (int ks = 0; ks < 32; ks += 8) {
            uint32_t af[4][4], bf[4][2];
            #pragma unroll
            for (int mi = 0; mi < 4; mi++) {
                int r = wm * 64 + mi * 16 + lr;
                af[mi][0] = As[r][ks + lc];
                af[mi][1] = As[r + 8][ks + lc];
                af[mi][2] = As[r][ks + 4 + lc];
                af[mi][3] = As[r + 8][ks + 4 + lc];
            }
            #pragma unroll
            for (int nj = 0; nj < 4; nj++) {
                int n = wn * 32 + nj * 8 + lr;
                bf[nj][0] = Bs[ks + lc][n];
                bf[nj][1] = Bs[ks + 4 + lc][n];
            }
            #pragma unroll
            for (int mi = 0; mi < 4; mi++)
                #pragma unroll
                for (int nj = 0; nj < 4; nj++)
                    mma_tf32(acc[mi][nj], af[mi], bf[nj]);
        }
        __syncthreads();
    }

    #pragma unroll
    for (int mi = 0; mi < 4; mi++) {
        #pragma unroll
        for (int nj = 0; nj < 4; nj++) {
            #pragma unroll
            for (int half = 0; half < 2; half++) {
                int s = s0 + wm * 64 + mi * 16 + lr + half * 8;
                int t = t0 + wn * 32 + nj * 8 + (lc << 1);
                float2 v;
                v.x = acc[mi][nj][half * 2 + 0] * 0.125f;
                v.y = acc[mi][nj][half * 2 + 1] * 0.125f;
                *(float2*)&probs[((size_t)bh * S + s) * S + t] = v;
            }
        }
    }
}

// ---------------------------------------------------------------------------
// K3: row softmax in place.  one block of 256 per row (len S=1024).
// ---------------------------------------------------------------------------
__global__ __launch_bounds__(256) void softmax_kernel(float* __restrict__ probs)
{
    __shared__ float red[256];
    const int tid = threadIdx.x;
    float* row = probs + (size_t)blockIdx.x * S;

    float v[4];
    #pragma unroll
    for (int i = 0; i < 4; i++) v[i] = row[tid + i * 256];

    float m = fmaxf(fmaxf(v[0], v[1]), fmaxf(v[2], v[3]));
    red[tid] = m;
    __syncthreads();
    for (int off = 128; off > 0; off >>= 1) {
        if (tid < off) red[tid] = fmaxf(red[tid], red[tid + off]);
        __syncthreads();
    }
    m = red[0];
    __syncthreads();

    float sum = 0.f;
    #pragma unroll
    for (int i = 0; i < 4; i++) { v[i] = __expf(v[i] - m); sum += v[i]; }
    red[tid] = sum;
    __syncthreads();
    for (int off = 128; off > 0; off >>= 1) {
        if (tid < off) red[tid] += red[tid + off];
        __syncthreads();
    }
    float inv = 1.f / red[0];

    #pragma unroll
    for (int i = 0; i < 4; i++) row[tid + i * 256] = v[i] * inv;
}

// ---------------------------------------------------------------------------
// K4: ctx[b,s,h*64+e] = sum_t probs[bh,s,t] * v[bh,t,e]   (K = 1024, N = 64)
// block tile 128 x 64, 8 warps (4m x 2n), warp tile 32x32
// ---------------------------------------------------------------------------
__global__ __launch_bounds__(256, 2) void ctx_kernel(const float* __restrict__ probs)
{
    __shared__ uint32_t As[128][36];
    __shared__ uint32_t Bs[32][68];

    const int tid  = threadIdx.x;
    const int lane = tid & 31;
    const int warp = tid >> 5;
    const int wm   = warp & 3;          // 0..3 -> m offset *32
    const int wn   = warp >> 2;         // 0..1 -> n offset *32
    const int s0   = blockIdx.x * 128;
    const int bh   = blockIdx.y;
    const int lr   = lane >> 2;
    const int lc   = lane & 3;

    const float* vp = g_v + (size_t)bh * S * DH;
    const float* pp = probs + ((size_t)bh * S + s0) * S;

    float acc[2][4][4];
    #pragma unroll
    for (int i = 0; i < 2; i++)
        #pragma unroll
        for (int j = 0; j < 4; j++)
            #pragma unroll
            for (int t = 0; t < 4; t++) acc[i][j][t] = 0.f;

    for (int k0 = 0; k0 < S; k0 += 32) {
        // A: probs tile 128x32
        #pragma unroll
        for (int i = 0; i < 4; i++) {
            int linear = tid + i * 256;
            int r = linear >> 3, c4 = (linear & 7) << 2;
            float4 v = *(const float4*)&pp[(size_t)r * S + k0 + c4];
            As[r][c4 + 0] = f2tf(v.x); As[r][c4 + 1] = f2tf(v.y);
            As[r][c4 + 2] = f2tf(v.z); As[r][c4 + 3] = f2tf(v.w);
        }
        // B: v tile 32x64 (direct, k-major)
        #pragma unroll
        for (int i = 0; i < 2; i++) {
            int linear = tid + i * 256;                // 512 float4 units
            int r = linear >> 4, c4 = (linear & 15) << 2;
            float4 v = *(const float4*)&vp[(size_t)(k0 + r) * DH + c4];
            Bs[r][c4 + 0] = f2tf(v.x); Bs[r][c4 + 1] = f2tf(v.y);
            Bs[r][c4 + 2] = f2tf(v.z); Bs[r][c4 + 3] = f2tf(v.w);
        }
        __syncthreads();

        #pragma unroll
        for (int ks = 0; ks < 32; ks += 8) {
            uint32_t af[2][4], bf[4][2];
            #pragma unroll
            for (int mi = 0; mi < 2; mi++) {
                int r = wm * 32 + mi * 16 + lr;
                af[mi][0] = As[r][ks + lc];
                af[mi][1] = As[r + 8][ks + lc];
                af[mi][2] = As[r][ks + 4 + lc];
                af[mi][3] = As[r + 8][ks + 4 + lc];
            }
            #pragma unroll
            for (int nj = 0; nj < 4; nj++) {
                int n = wn * 32 + nj * 8 + lr;
                bf[nj][0] = Bs[ks + lc][n];
                bf[nj][1] = Bs[ks + 4 + lc][n];
            }
            #pragma unroll
            for (int mi = 0; mi < 2; mi++)
                #pragma unroll
                for (int nj = 0; nj < 4; nj++)
                    mma_tf32(acc[mi][nj], af[mi], bf[nj]);
        }
        __syncthreads();
    }

    const int b = bh / H;
    const int h = bh % H;
    #pragma unroll
    for (int mi = 0; mi < 2; mi++) {
        #pragma unroll
        for (int nj = 0; nj < 4; nj++) {
            #pragma unroll
            for (int half = 0; half < 2; half++) {
                int s = s0 + wm * 32 + mi * 16 + lr + half * 8;
                int e = wn * 32 + nj * 8 + (lc << 1);
                float2 v;
                v.x = acc[mi][nj][half * 2 + 0];
                v.y = acc[mi][nj][half * 2 + 1];
                *(float2*)&g_ctx[((size_t)b * S + s) * D + h * DH + e] = v;
            }
        }
    }
}

// ---------------------------------------------------------------------------
// K5: out[m,n] = sum_k ctx[m,k] * Wo[n,k] + bo[n]   (8192 x 768 x 768)
// block tile 128x128
// ---------------------------------------------------------------------------
__global__ __launch_bounds__(256, 2) void out_kernel(
    const float* __restrict__ Wo, const float* __restrict__ bo,
    float* __restrict__ out)
{
    __shared__ uint32_t As[128][36];
    __shared__ uint32_t Bs[32][132];

    const int tid  = threadIdx.x;
    const int lane = tid & 31;
    const int warp = tid >> 5;
    const int wm   = warp & 1;
    const int wn   = warp >> 1;
    const int m0   = blockIdx.x * 128;
    const int n0   = blockIdx.y * 128;
    const int lr   = lane >> 2;
    const int lc   = lane & 3;

    float acc[4][4][4];
    #pragma unroll
    for (int i = 0; i < 4; i++)
        #pragma unroll
        for (int j = 0; j < 4; j++)
            #pragma unroll
            for (int t = 0; t < 4; t++) acc[i][j][t] = 0.f;

    for (int k0 = 0; k0 < D; k0 += 32) {
        // A: ctx tile 128x32
        #pragma unroll
        for (int i = 0; i < 4; i++) {
            int linear = tid + i * 256;
            int r = linear >> 3, c4 = (linear & 7) << 2;
            float4 v = *(const float4*)&g_ctx[(size_t)(m0 + r) * D + k0 + c4];
            As[r][c4 + 0] = f2tf(v.x); As[r][c4 + 1] = f2tf(v.y);
            As[r][c4 + 2] = f2tf(v.z); As[r][c4 + 3] = f2tf(v.w);
        }
        // B: transpose-load Wo -> Bs[k][n] = Wo[(n0+n)*D + k0+k]
        #pragma unroll
        for (int i = 0; i < 4; i++) {
            int linear = tid + i * 256;
            int n = linear >> 3, k4 = (linear & 7) << 2;
            float4 v = *(const float4*)&Wo[(size_t)(n0 + n) * D + k0 + k4];
            Bs[k4 + 0][n] = f2tf(v.x); Bs[k4 + 1][n] = f2tf(v.y);
            Bs[k4 + 2][n] = f2tf(v.z); Bs[k4 + 3][n] = f2tf(v.w);
        }
        __syncthreads();

        #pragma unroll
        for (int ks = 0; ks < 32; ks += 8) {
            uint32_t af[4][4], bf[4][2];
            #pragma unroll
            for (int mi = 0; mi < 4; mi++) {
                int r = wm * 64 + mi * 16 + lr;
                af[mi][0] = As[r][ks + lc];
                af[mi][1] = As[r + 8][ks + lc];
                af[mi][2] = As[r][ks + 4 + lc];
                af[mi][3] = As[r + 8][ks + 4 + lc];
            }
            #pragma unroll
            for (int nj = 0; nj < 4; nj++) {
                int n = wn * 32 + nj * 8 + lr;
                bf[nj][0] = Bs[ks + lc][n];
                bf[nj][1] = Bs[ks + 4 + lc][n];
            }
            #pragma unroll
            for (int mi = 0; mi < 4; mi++)
                #pragma unroll
                for (int nj = 0; nj < 4; nj++)
                    mma_tf32(acc[mi][nj], af[mi], bf[nj]);
        }
        __syncthreads();
    }

    #pragma unroll
    for (int mi = 0; mi < 4; mi++) {
        #pragma unroll
        for (int nj = 0; nj < 4; nj++) {
            #pragma unroll
            for (int half = 0; half < 2; half++) {
                int m = m0 + wm * 64 + mi * 16 + lr + half * 8;
                int n = n0 + wn * 32 + nj * 8 + (lc << 1);
                float2 v;
                v.x = acc[mi][nj][half * 2 + 0] + bo[n];
                v.y = acc[mi][nj][half * 2 + 1] + bo[n + 1];
                *(float2*)&out[(size_t)m * D + n] = v;
            }
        }
    }
}

// ---------------------------------------------------------------------------
extern "C" void kernel_launch(void* const* d_in, const int* in_sizes, int n_in,
                              void* d_out, int out_size)
{
    const float* x  = (const float*)d_in[0];
    const float* Wq = (const float*)d_in[1];
    const float* bq = (const float*)d_in[2];
    const float* Wk = (const float*)d_in[3];
    const float* bk = (const float*)d_in[4];
    const float* Wv = (const float*)d_in[5];
    const float* bv = (const float*)d_in[6];
    const float* Wo = (const float*)d_in[7];
    const float* bo = (const float*)d_in[8];

    float* out   = (float*)d_out;
    float* probs = out + OUT_ELEMS;

    qkv_kernel<<<dim3(M_TOT / 128, NQKV / 128), 256>>>(x, Wq, bq, Wk, bk, Wv, bv);
    scores_kernel<<<dim3(S / 128, S / 128, BH), 256>>>(probs);
    softmax_kernel<<<BH * S, 256>>>(probs);
    ctx_kernel<<<dim3(S / 128, BH), 256>>>(probs);
    out_kernel<<<dim3(M_TOT / 128, D / 128), 256>>>(Wo, bo, out);
}

// round 4
// speedup vs baseline: 2.6013x; 1.1889x over previous
#include <cuda_runtime.h>
#include <cuda_bf16.h>
#include <cstdint>

// Problem constants
#define H 12
#define D 768
#define DH 64
#define B 8
#define S 1024
#define M_TOT (B * S)            // 8192
#define BH (B * H)               // 96
#define OUT_ELEMS (B * S * D)    // 6291456
#define NQKV (H * 3 * DH)        // 2304

// Scratch (device globals — allocation-free per harness rules)
__device__ float g_q[BH * S * DH];
__device__ float g_k[BH * S * DH];
__device__ float g_v[BH * S * DH];
__device__ float g_ctx[M_TOT * D];

// ---------------------------------------------------------------------------
__device__ __forceinline__ uint32_t f2tf(float x) {
    uint32_t r;
    asm("cvt.rna.tf32.f32 %0, %1;" : "=r"(r) : "f"(x));
    return r;
}

__device__ __forceinline__ void mma_tf32(float c[4], const uint32_t a[4],
                                         const uint32_t b[2]) {
    asm volatile(
        "mma.sync.aligned.m16n8k8.row.col.f32.tf32.tf32.f32 "
        "{%0,%1,%2,%3}, {%4,%5,%6,%7}, {%8,%9}, {%0,%1,%2,%3};\n"
        : "+f"(c[0]), "+f"(c[1]), "+f"(c[2]), "+f"(c[3])
        : "r"(a[0]), "r"(a[1]), "r"(a[2]), "r"(a[3]), "r"(b[0]), "r"(b[1]));
}

__device__ __forceinline__ float red4_max(float v) {
    v = fmaxf(v, __shfl_xor_sync(0xffffffffu, v, 1));
    v = fmaxf(v, __shfl_xor_sync(0xffffffffu, v, 2));
    return v;
}
__device__ __forceinline__ float red4_sum(float v) {
    v += __shfl_xor_sync(0xffffffffu, v, 1);
    v += __shfl_xor_sync(0xffffffffu, v, 2);
    return v;
}

// ---------------------------------------------------------------------------
// K1: fused QKV projection as ONE GEMM: [8192 x 2304] = x[8192x768] @ Wcat
// ---------------------------------------------------------------------------
__global__ __launch_bounds__(256, 2) void qkv_kernel(
    const float* __restrict__ x,
    const float* __restrict__ Wq, const float* __restrict__ bq,
    const float* __restrict__ Wk, const float* __restrict__ bk,
    const float* __restrict__ Wv, const float* __restrict__ bv)
{
    __shared__ uint32_t As[128][36];    // A-frag reads: (4*lr+lc)%32 distinct
    __shared__ uint32_t Bs[32][136];    // B-frag reads: (8*lc+lr)%32 distinct

    const int tid  = threadIdx.x;
    const int lane = tid & 31;
    const int warp = tid >> 5;
    const int wm   = warp & 1;
    const int wn   = warp >> 1;
    const int m0   = blockIdx.x * 128;
    const int n0   = blockIdx.y * 128;
    const int lr   = lane >> 2;
    const int lc   = lane & 3;

    float acc[4][4][4];
    #pragma unroll
    for (int i = 0; i < 4; i++)
        #pragma unroll
        for (int j = 0; j < 4; j++)
            #pragma unroll
            for (int t = 0; t < 4; t++) acc[i][j][t] = 0.f;

    for (int k0 = 0; k0 < D; k0 += 32) {
        #pragma unroll
        for (int i = 0; i < 4; i++) {
            int linear = tid + i * 256;
            int r = linear >> 3, c4 = (linear & 7) << 2;
            float4 v = *(const float4*)&x[(size_t)(m0 + r) * D + k0 + c4];
            As[r][c4 + 0] = f2tf(v.x); As[r][c4 + 1] = f2tf(v.y);
            As[r][c4 + 2] = f2tf(v.z); As[r][c4 + 3] = f2tf(v.w);
        }
        #pragma unroll
        for (int i = 0; i < 16; i++) {
            int linear = tid + i * 256;
            int r = linear >> 7, c = linear & 127;
            int gn = n0 + c;
            int h = gn / 192, rem = gn % 192;
            int which = rem >> 6, e = rem & 63;
            const float* wp = (which == 0) ? Wq : (which == 1) ? Wk : Wv;
            Bs[r][c] = f2tf(wp[((size_t)h * D + (k0 + r)) * DH + e]);
        }
        __syncthreads();

        #pragma unroll
        for (int ks = 0; ks < 32; ks += 8) {
            uint32_t af[4][4], bf[4][2];
            #pragma unroll
            for (int mi = 0; mi < 4; mi++) {
                int r = wm * 64 + mi * 16 + lr;
                af[mi][0] = As[r][ks + lc];
                af[mi][1] = As[r + 8][ks + lc];
                af[mi][2] = As[r][ks + 4 + lc];
                af[mi][3] = As[r + 8][ks + 4 + lc];
            }
            #pragma unroll
            for (int nj = 0; nj < 4; nj++) {
                int n = wn * 32 + nj * 8 + lr;
                bf[nj][0] = Bs[ks + lc][n];
                bf[nj][1] = Bs[ks + 4 + lc][n];
            }
            #pragma unroll
            for (int mi = 0; mi < 4; mi++)
                #pragma unroll
                for (int nj = 0; nj < 4; nj++)
                    mma_tf32(acc[mi][nj], af[mi], bf[nj]);
        }
        __syncthreads();
    }

    #pragma unroll
    for (int mi = 0; mi < 4; mi++) {
        #pragma unroll
        for (int nj = 0; nj < 4; nj++) {
            #pragma unroll
            for (int t = 0; t < 4; t++) {
                int r  = m0 + wm * 64 + mi * 16 + lr + ((t >= 2) ? 8 : 0);
                int gn = n0 + wn * 32 + nj * 8 + (lc << 1) + (t & 1);
                int b = r >> 10, s = r & 1023;
                int h = gn / 192, rem = gn % 192;
                int which = rem >> 6, e = rem & 63;
                const float* bp = (which == 0) ? bq : (which == 1) ? bk : bv;
                float* dst = (which == 0) ? g_q : (which == 1) ? g_k : g_v;
                dst[(((size_t)b * H + h) * S + s) * DH + e] =
                    acc[mi][nj][t] + bp[h * DH + e];
            }
        }
    }
}

// ---------------------------------------------------------------------------
// K2: fused attention: scores + online softmax + ctx, then probs recompute.
// grid (S/128, BH), 256 thr, 8 warps; warp w owns rows w*16..w*16+15.
// Dynamic smem: qs[128][68], kt[64][68] ([n][k]!), vs[64][72], ps[128][36]
// ---------------------------------------------------------------------------
#define BT 64
#define QS(r, c) sh_q[(r) * 68 + (c)]
#define KT(n, c) sh_k[(n) * 68 + (c)]
#define VS(t, e) sh_v[(t) * 72 + (e)]
#define PS(r, c) sh_p[(r) * 36 + (c)]
#define ATTN_SMEM ((128 * 68 + 64 * 68 + 64 * 72 + 128 * 36) * 4)

__global__ __launch_bounds__(256, 2) void attn_kernel(float* __restrict__ probs)
{
    extern __shared__ uint32_t sh[];
    uint32_t* sh_q = sh;                       // 8704
    uint32_t* sh_k = sh_q + 128 * 68;          // 4352
    uint32_t* sh_v = sh_k + 64 * 68;           // 4608
    uint32_t* sh_p = sh_v + 64 * 72;           // 4608

    const int tid  = threadIdx.x;
    const int lane = tid & 31;
    const int warp = tid >> 5;
    const int lr   = lane >> 2;
    const int lc   = lane & 3;
    const int s0   = blockIdx.x * 128;
    const int bh   = blockIdx.y;
    const int r0   = warp * 16;

    const float* qp = g_q + (size_t)bh * S * DH;
    const float* kp = g_k + (size_t)bh * S * DH;
    const float* vp = g_v + (size_t)bh * S * DH;

    // load q tile 128x64
    #pragma unroll
    for (int i = 0; i < 8; i++) {
        int linear = tid + i * 256;
        int r = linear >> 4, c4 = (linear & 15) << 2;
        float4 v = *(const float4*)&qp[(size_t)(s0 + r) * DH + c4];
        QS(r, c4 + 0) = f2tf(v.x); QS(r, c4 + 1) = f2tf(v.y);
        QS(r, c4 + 2) = f2tf(v.z); QS(r, c4 + 3) = f2tf(v.w);
    }
    __syncthreads();

    float m0 = -1e30f, m1 = -1e30f, l0 = 0.f, l1 = 0.f;
    float co[8][4];
    #pragma unroll
    for (int nj = 0; nj < 8; nj++)
        #pragma unroll
        for (int t = 0; t < 4; t++) co[nj][t] = 0.f;

    // ---------------- Pass A ----------------
    for (int t0 = 0; t0 < S; t0 += BT) {
        // K tile as [n][k] (row-major, no transpose) + V tile [t][e]
        #pragma unroll
        for (int i = 0; i < 4; i++) {
            int linear = tid + i * 256;
            int n = linear >> 4, k4 = (linear & 15) << 2;
            float4 v = *(const float4*)&kp[(size_t)(t0 + n) * DH + k4];
            KT(n, k4 + 0) = f2tf(v.x); KT(n, k4 + 1) = f2tf(v.y);
            KT(n, k4 + 2) = f2tf(v.z); KT(n, k4 + 3) = f2tf(v.w);
            float4 u = *(const float4*)&vp[(size_t)(t0 + n) * DH + k4];
            VS(n, k4 + 0) = f2tf(u.x); VS(n, k4 + 1) = f2tf(u.y);
            VS(n, k4 + 2) = f2tf(u.z); VS(n, k4 + 3) = f2tf(u.w);
        }
        __syncthreads();

        // scores: warp tile 16 x 64
        float sa[8][4];
        #pragma unroll
        for (int nj = 0; nj < 8; nj++)
            #pragma unroll
            for (int t = 0; t < 4; t++) sa[nj][t] = 0.f;

        #pragma unroll
        for (int ks8 = 0; ks8 < DH; ks8 += 8) {
            uint32_t af[4];
            af[0] = QS(r0 + lr, ks8 + lc);
            af[1] = QS(r0 + 8 + lr, ks8 + lc);
            af[2] = QS(r0 + lr, ks8 + 4 + lc);
            af[3] = QS(r0 + 8 + lr, ks8 + 4 + lc);
            #pragma unroll
            for (int nj = 0; nj < 8; nj++) {
                uint32_t bf[2];
                bf[0] = KT(nj * 8 + lr, ks8 + lc);
                bf[1] = KT(nj * 8 + lr, ks8 + 4 + lc);
                mma_tf32(sa[nj], af, bf);
            }
        }

        // online softmax
        float tmax0 = -1e30f, tmax1 = -1e30f;
        #pragma unroll
        for (int nj = 0; nj < 8; nj++) {
            sa[nj][0] *= 0.125f; sa[nj][1] *= 0.125f;
            sa[nj][2] *= 0.125f; sa[nj][3] *= 0.125f;
            tmax0 = fmaxf(tmax0, fmaxf(sa[nj][0], sa[nj][1]));
            tmax1 = fmaxf(tmax1, fmaxf(sa[nj][2], sa[nj][3]));
        }
        tmax0 = red4_max(tmax0); tmax1 = red4_max(tmax1);
        float nm0 = fmaxf(m0, tmax0), nm1 = fmaxf(m1, tmax1);
        float sc0 = __expf(m0 - nm0), sc1 = __expf(m1 - nm1);
        float ts0 = 0.f, ts1 = 0.f;
        #pragma unroll
        for (int nj = 0; nj < 8; nj++) {
            sa[nj][0] = __expf(sa[nj][0] - nm0); ts0 += sa[nj][0];
            sa[nj][1] = __expf(sa[nj][1] - nm0); ts0 += sa[nj][1];
            sa[nj][2] = __expf(sa[nj][2] - nm1); ts1 += sa[nj][2];
            sa[nj][3] = __expf(sa[nj][3] - nm1); ts1 += sa[nj][3];
        }
        ts0 = red4_sum(ts0); ts1 = red4_sum(ts1);
        l0 = l0 * sc0 + ts0; l1 = l1 * sc1 + ts1;
        m0 = nm0; m1 = nm1;
        #pragma unroll
        for (int nj = 0; nj < 8; nj++) {
            co[nj][0] *= sc0; co[nj][1] *= sc0;
            co[nj][2] *= sc1; co[nj][3] *= sc1;
        }

        // ctx accumulate: P (16 x 64) * V (64 x 64), two k-chunks of 32
        #pragma unroll
        for (int kc = 0; kc < BT / 32; kc++) {
            __syncwarp();
            #pragma unroll
            for (int j = 0; j < 4; j++) {
                int nj = kc * 4 + j;
                PS(r0 + lr,     j * 8 + 2 * lc)     = f2tf(sa[nj][0]);
                PS(r0 + lr,     j * 8 + 2 * lc + 1) = f2tf(sa[nj][1]);
                PS(r0 + 8 + lr, j * 8 + 2 * lc)     = f2tf(sa[nj][2]);
                PS(r0 + 8 + lr, j * 8 + 2 * lc + 1) = f2tf(sa[nj][3]);
            }
            __syncwarp();
            #pragma unroll
            for (int ks8 = 0; ks8 < 32; ks8 += 8) {
                uint32_t af[4];
                af[0] = PS(r0 + lr, ks8 + lc);
                af[1] = PS(r0 + 8 + lr, ks8 + lc);
                af[2] = PS(r0 + lr, ks8 + 4 + lc);
                af[3] = PS(r0 + 8 + lr, ks8 + 4 + lc);
                #pragma unroll
                for (int nj8 = 0; nj8 < 8; nj8++) {
                    uint32_t bf[2];
                    bf[0] = VS(kc * 32 + ks8 + lc,     nj8 * 8 + lr);
                    bf[1] = VS(kc * 32 + ks8 + 4 + lc, nj8 * 8 + lr);
                    mma_tf32(co[nj8], af, bf);
                }
            }
        }
        __syncthreads();
    }

    // write ctx (normalized)
    const float invl0 = 1.f / l0, invl1 = 1.f / l1;
    const int b = bh / H, h = bh % H;
    #pragma unroll
    for (int nj = 0; nj < 8; nj++) {
        int sA = s0 + r0 + lr;
        int e = h * DH + nj * 8 + 2 * lc;
        float2 v0, v1;
        v0.x = co[nj][0] * invl0; v0.y = co[nj][1] * invl0;
        v1.x = co[nj][2] * invl1; v1.y = co[nj][3] * invl1;
        *(float2*)&g_ctx[((size_t)b * S + sA) * D + e] = v0;
        *(float2*)&g_ctx[((size_t)b * S + sA + 8) * D + e] = v1;
    }

    // ---------------- Pass B: recompute scores, write probs ----------------
    float* prow = probs + (size_t)bh * S * S;
    for (int t0 = 0; t0 < S; t0 += BT) {
        #pragma unroll
        for (int i = 0; i < 4; i++) {
            int linear = tid + i * 256;
            int n = linear >> 4, k4 = (linear & 15) << 2;
            float4 v = *(const float4*)&kp[(size_t)(t0 + n) * DH + k4];
            KT(n, k4 + 0) = f2tf(v.x); KT(n, k4 + 1) = f2tf(v.y);
            KT(n, k4 + 2) = f2tf(v.z); KT(n, k4 + 3) = f2tf(v.w);
        }
        __syncthreads();

        float sa[8][4];
        #pragma unroll
        for (int nj = 0; nj < 8; nj++)
            #pragma unroll
            for (int t = 0; t < 4; t++) sa[nj][t] = 0.f;

        #pragma unroll
        for (int ks8 = 0; ks8 < DH; ks8 += 8) {
            uint32_t af[4];
            af[0] = QS(r0 + lr, ks8 + lc);
            af[1] = QS(r0 + 8 + lr, ks8 + lc);
            af[2] = QS(r0 + lr, ks8 + 4 + lc);
            af[3] = QS(r0 + 8 + lr, ks8 + 4 + lc);
            #pragma unroll
            for (int nj = 0; nj < 8; nj++) {
                uint32_t bf[2];
                bf[0] = KT(nj * 8 + lr, ks8 + lc);
                bf[1] = KT(nj * 8 + lr, ks8 + 4 + lc);
                mma_tf32(sa[nj], af, bf);
            }
        }

        #pragma unroll
        for (int nj = 0; nj < 8; nj++) {
            int t = t0 + nj * 8 + 2 * lc;
            float2 v0, v1;
            v0.x = __expf(sa[nj][0] * 0.125f - m0) * invl0;
            v0.y = __expf(sa[nj][1] * 0.125f - m0) * invl0;
            v1.x = __expf(sa[nj][2] * 0.125f - m1) * invl1;
            v1.y = __expf(sa[nj][3] * 0.125f - m1) * invl1;
            *(float2*)&prow[(size_t)(s0 + r0 + lr) * S + t] = v0;
            *(float2*)&prow[(size_t)(s0 + r0 + 8 + lr) * S + t] = v1;
        }
        __syncthreads();
    }
}

// ---------------------------------------------------------------------------
// K5: out[m,n] = sum_k ctx[m,k] * Wo[n,k] + bo[n]   (8192 x 768 x 768)
// B tile kept row-major [n][k] — coalesced loads, conflict-free frag reads
// ---------------------------------------------------------------------------
__global__ __launch_bounds__(256, 2) void out_kernel(
    const float* __restrict__ Wo, const float* __restrict__ bo,
    float* __restrict__ out)
{
    __shared__ uint32_t As[128][36];
    __shared__ uint32_t Bs[128][36];

    const int tid  = threadIdx.x;
    const int lane = tid & 31;
    const int warp = tid >> 5;
    const int wm   = warp & 1;
    const int wn   = warp >> 1;
    const int m0   = blockIdx.x * 128;
    const int n0   = blockIdx.y * 128;
    const int lr   = lane >> 2;
    const int lc   = lane & 3;

    float acc[4][4][4];
    #pragma unroll
    for (int i = 0; i < 4; i++)
        #pragma unroll
        for (int j = 0; j < 4; j++)
            #pragma unroll
            for (int t = 0; t < 4; t++) acc[i][j][t] = 0.f;

    for (int k0 = 0; k0 < D; k0 += 32) {
        #pragma unroll
        for (int i = 0; i < 4; i++) {
            int linear = tid + i * 256;
            int r = linear >> 3, c4 = (linear & 7) << 2;
            float4 v = *(const float4*)&g_ctx[(size_t)(m0 + r) * D + k0 + c4];
            As[r][c4 + 0] = f2tf(v.x); As[r][c4 + 1] = f2tf(v.y);
            As[r][c4 + 2] = f2tf(v.z); As[r][c4 + 3] = f2tf(v.w);
        }
        #pragma unroll
        for (int i = 0; i < 4; i++) {
            int linear = tid + i * 256;
            int n = linear >> 3, k4 = (linear & 7) << 2;
            float4 v = *(const float4*)&Wo[(size_t)(n0 + n) * D + k0 + k4];
            Bs[n][k4 + 0] = f2tf(v.x); Bs[n][k4 + 1] = f2tf(v.y);
            Bs[n][k4 + 2] = f2tf(v.z); Bs[n][k4 + 3] = f2tf(v.w);
        }
        __syncthreads();

        #pragma unroll
        for (int ks = 0; ks < 32; ks += 8) {
            uint32_t af[4][4], bf[4][2];
            #pragma unroll
            for (int mi = 0; mi < 4; mi++) {
                int r = wm * 64 + mi * 16 + lr;
                af[mi][0] = As[r][ks + lc];
                af[mi][1] = As[r + 8][ks + lc];
                af[mi][2] = As[r][ks + 4 + lc];
                af[mi][3] = As[r + 8][ks + 4 + lc];
            }
            #pragma unroll
            for (int nj = 0; nj < 4; nj++) {
                int n = wn * 32 + nj * 8 + lr;
                bf[nj][0] = Bs[n][ks + lc];
                bf[nj][1] = Bs[n][ks + 4 + lc];
            }
            #pragma unroll
            for (int mi = 0; mi < 4; mi++)
                #pragma unroll
                for (int nj = 0; nj < 4; nj++)
                    mma_tf32(acc[mi][nj], af[mi], bf[nj]);
        }
        __syncthreads();
    }

    #pragma unroll
    for (int mi = 0; mi < 4; mi++) {
        #pragma unroll
        for (int nj = 0; nj < 4; nj++) {
            #pragma unroll
            for (int half = 0; half < 2; half++) {
                int m = m0 + wm * 64 + mi * 16 + lr + half * 8;
                int n = n0 + wn * 32 + nj * 8 + (lc << 1);
                float2 v;
                v.x = acc[mi][nj][half * 2 + 0] + bo[n];
                v.y = acc[mi][nj][half * 2 + 1] + bo[n + 1];
                *(float2*)&out[(size_t)m * D + n] = v;
            }
        }
    }
}

// ---------------------------------------------------------------------------
extern "C" void kernel_launch(void* const* d_in, const int* in_sizes, int n_in,
                              void* d_out, int out_size)
{
    const float* x  = (const float*)d_in[0];
    const float* Wq = (const float*)d_in[1];
    const float* bq = (const float*)d_in[2];
    const float* Wk = (const float*)d_in[3];
    const float* bk = (const float*)d_in[4];
    const float* Wv = (const float*)d_in[5];
    const float* bv = (const float*)d_in[6];
    const float* Wo = (const float*)d_in[7];
    const float* bo = (const float*)d_in[8];

    float* out   = (float*)d_out;
    float* probs = out + OUT_ELEMS;

    cudaFuncSetAttribute(attn_kernel,
                         cudaFuncAttributeMaxDynamicSharedMemorySize, ATTN_SMEM);

    qkv_kernel<<<dim3(M_TOT / 128, NQKV / 128), 256>>>(x, Wq, bq, Wk, bk, Wv, bv);
    attn_kernel<<<dim3(S / 128, BH), 256, ATTN_SMEM>>>(probs);
    out_kernel<<<dim3(M_TOT / 128, D / 128), 256>>>(Wo, bo, out);
}

// round 5
// speedup vs baseline: 3.2274x; 1.2407x over previous
#include <cuda_runtime.h>
#include <cstdint>

// Problem constants
#define H 12
#define D 768
#define DH 64
#define B 8
#define S 1024
#define M_TOT (B * S)            // 8192
#define BH (B * H)               // 96
#define OUT_ELEMS (B * S * D)    // 6291456
#define NQKV (H * 3 * DH)        // 2304

// Scratch (device globals — allocation-free per harness rules)
__device__ float g_q[BH * S * DH];
__device__ float g_k[BH * S * DH];
__device__ float g_v[BH * S * DH];
__device__ float g_ctx[M_TOT * D];
__device__ uint32_t g_wcat[(size_t)D * NQKV];   // tf32-rounded packed W
__device__ float g_bcat[NQKV];

// ---------------------------------------------------------------------------
__device__ __forceinline__ uint32_t f2tf(float x) {
    uint32_t r;
    asm("cvt.rna.tf32.f32 %0, %1;" : "=r"(r) : "f"(x));
    return r;
}

__device__ __forceinline__ void mma_tf32(float c[4], const uint32_t a[4],
                                         const uint32_t b[2]) {
    asm volatile(
        "mma.sync.aligned.m16n8k8.row.col.f32.tf32.tf32.f32 "
        "{%0,%1,%2,%3}, {%4,%5,%6,%7}, {%8,%9}, {%0,%1,%2,%3};\n"
        : "+f"(c[0]), "+f"(c[1]), "+f"(c[2]), "+f"(c[3])
        : "r"(a[0]), "r"(a[1]), "r"(a[2]), "r"(a[3]), "r"(b[0]), "r"(b[1]));
}

__device__ __forceinline__ void cp16(uint32_t saddr, const void* gptr) {
    asm volatile("cp.async.ca.shared.global [%0], [%1], 16;\n"
                 :: "r"(saddr), "l"(gptr));
}
__device__ __forceinline__ void cp_commit() {
    asm volatile("cp.async.commit_group;\n");
}
template <int N> __device__ __forceinline__ void cp_wait() {
    asm volatile("cp.async.wait_group %0;\n" :: "n"(N));
}

__device__ __forceinline__ float red4_max(float v) {
    v = fmaxf(v, __shfl_xor_sync(0xffffffffu, v, 1));
    v = fmaxf(v, __shfl_xor_sync(0xffffffffu, v, 2));
    return v;
}
__device__ __forceinline__ float red4_sum(float v) {
    v += __shfl_xor_sync(0xffffffffu, v, 1);
    v += __shfl_xor_sync(0xffffffffu, v, 2);
    return v;
}

// ---------------------------------------------------------------------------
// K0: repack Wq/Wk/Wv -> g_wcat [k][n] (tf32-rounded), biases -> g_bcat
// column n -> h = n/192, which = (n%192)/64, e = n%64
// ---------------------------------------------------------------------------
__global__ __launch_bounds__(256) void repack_kernel(
    const float* __restrict__ Wq, const float* __restrict__ Wk,
    const float* __restrict__ Wv, const float* __restrict__ bq,
    const float* __restrict__ bk, const float* __restrict__ bv)
{
    int idx = blockIdx.x * 256 + threadIdx.x;
    if (idx < D * NQKV) {
        int k = idx / NQKV, n = idx - k * NQKV;
        int h = n / 192, rem = n % 192;
        int which = rem >> 6, e = rem & 63;
        const float* wp = (which == 0) ? Wq : (which == 1) ? Wk : Wv;
        g_wcat[idx] = f2tf(wp[((size_t)h * D + k) * DH + e]);
    }
    if (idx < NQKV) {
        int h = idx / 192, rem = idx % 192;
        int which = rem >> 6, e = rem & 63;
        const float* bp = (which == 0) ? bq : (which == 1) ? bk : bv;
        g_bcat[idx] = bp[h * DH + e];
    }
}

// ---------------------------------------------------------------------------
// K1: QKV GEMM [8192 x 2304] = x[8192x768] @ g_wcat, cp.async 2-stage
// block tile 128x128, BLK_K=32, 8 warps (2m x 4n)
// ---------------------------------------------------------------------------
#define QKV_BSOFF (128 * 36)
#define QKV_STAGE (128 * 36 + 32 * 136)     // 8960 words
#define QKV_SMEM  (2 * QKV_STAGE * 4)       // 71680 B
#define QKV_KT    (D / 32)                  // 24

__global__ __launch_bounds__(256, 2) void qkv_kernel(const float* __restrict__ x)
{
    extern __shared__ uint32_t sm[];
    const uint32_t sb = (uint32_t)__cvta_generic_to_shared(sm);

    const int tid  = threadIdx.x;
    const int lane = tid & 31;
    const int warp = tid >> 5;
    const int wm   = warp & 1;
    const int wn   = warp >> 1;
    const int m0   = blockIdx.x * 128;
    const int n0   = blockIdx.y * 128;
    const int lr   = lane >> 2;
    const int lc   = lane & 3;

    auto issue = [&](int kt, int stg) {
        uint32_t as = sb + (uint32_t)(stg * QKV_STAGE) * 4;
        uint32_t bs = as + QKV_BSOFF * 4;
        #pragma unroll
        for (int i = 0; i < 4; i++) {
            int linear = tid + i * 256;
            int r = linear >> 3, c4 = (linear & 7) << 2;
            cp16(as + (uint32_t)(r * 36 + c4) * 4,
                 &x[(size_t)(m0 + r) * D + kt * 32 + c4]);
        }
        #pragma unroll
        for (int i = 0; i < 4; i++) {
            int linear = tid + i * 256;
            int r = linear >> 5, c4 = (linear & 31) << 2;
            cp16(bs + (uint32_t)(r * 136 + c4) * 4,
                 &g_wcat[(size_t)(kt * 32 + r) * NQKV + n0 + c4]);
        }
        cp_commit();
    };

    float acc[4][4][4];
    #pragma unroll
    for (int i = 0; i < 4; i++)
        #pragma unroll
        for (int j = 0; j < 4; j++)
            #pragma unroll
            for (int t = 0; t < 4; t++) acc[i][j][t] = 0.f;

    issue(0, 0);
    for (int kt = 0; kt < QKV_KT; kt++) {
        int cur = kt & 1;
        if (kt + 1 < QKV_KT) { issue(kt + 1, cur ^ 1); cp_wait<1>(); }
        else cp_wait<0>();
        __syncthreads();

        const uint32_t* As = sm + cur * QKV_STAGE;
        const uint32_t* Bs = As + QKV_BSOFF;

        #pragma unroll
        for (int ks = 0; ks < 32; ks += 8) {
            uint32_t af[4][4], bf[4][2];
            #pragma unroll
            for (int mi = 0; mi < 4; mi++) {
                int r = wm * 64 + mi * 16 + lr;
                af[mi][0] = As[r * 36 + ks + lc];
                af[mi][1] = As[(r + 8) * 36 + ks + lc];
                af[mi][2] = As[r * 36 + ks + 4 + lc];
                af[mi][3] = As[(r + 8) * 36 + ks + 4 + lc];
            }
            #pragma unroll
            for (int nj = 0; nj < 4; nj++) {
                int n = wn * 32 + nj * 8 + lr;
                bf[nj][0] = Bs[(ks + lc) * 136 + n];
                bf[nj][1] = Bs[(ks + 4 + lc) * 136 + n];
            }
            #pragma unroll
            for (int mi = 0; mi < 4; mi++)
                #pragma unroll
                for (int nj = 0; nj < 4; nj++)
                    mma_tf32(acc[mi][nj], af[mi], bf[nj]);
        }
        __syncthreads();
    }

    #pragma unroll
    for (int mi = 0; mi < 4; mi++) {
        #pragma unroll
        for (int nj = 0; nj < 4; nj++) {
            #pragma unroll
            for (int t = 0; t < 4; t++) {
                int r  = m0 + wm * 64 + mi * 16 + lr + ((t >= 2) ? 8 : 0);
                int gn = n0 + wn * 32 + nj * 8 + (lc << 1) + (t & 1);
                int b = r >> 10, s = r & 1023;
                int h = gn / 192, rem = gn % 192;
                int which = rem >> 6, e = rem & 63;
                float* dst = (which == 0) ? g_q : (which == 1) ? g_k : g_v;
                dst[(((size_t)b * H + h) * S + s) * DH + e] =
                    acc[mi][nj][t] + g_bcat[gn];
            }
        }
    }
}

// ---------------------------------------------------------------------------
// K2: fused attention, cp.async 2-stage K/V tiles of 32 rows
// grid (S/128, BH), 256 thr, 8 warps; warp w owns rows w*16..w*16+15.
// ---------------------------------------------------------------------------
#define BT 32
#define NT (S / BT)                         // 32
#define A_PSOFF (128 * 68)
#define A_KVOFF (128 * 68 + 128 * 36)
#define KV_STAGE (32 * 68 + 32 * 72)        // 4480 words
#define ATTN_SMEM ((128 * 68 + 128 * 36 + 2 * KV_STAGE) * 4)   // 89088 B

__global__ __launch_bounds__(256, 2) void attn_kernel(float* __restrict__ probs)
{
    extern __shared__ uint32_t sm[];
    uint32_t* sh_q = sm;
    uint32_t* sh_p = sm + A_PSOFF;
    const uint32_t sb = (uint32_t)__cvta_generic_to_shared(sm);

    const int tid  = threadIdx.x;
    const int lane = tid & 31;
    const int warp = tid >> 5;
    const int lr   = lane >> 2;
    const int lc   = lane & 3;
    const int s0   = blockIdx.x * 128;
    const int bh   = blockIdx.y;
    const int r0   = warp * 16;

    const float* qp = g_q + (size_t)bh * S * DH;
    const float* kp = g_k + (size_t)bh * S * DH;
    const float* vp = g_v + (size_t)bh * S * DH;

    // Q tile 128x64 (raw fp32; mma truncates to tf32)
    #pragma unroll
    for (int i = 0; i < 8; i++) {
        int linear = tid + i * 256;
        int r = linear >> 4, c4 = (linear & 15) << 2;
        float4 v = *(const float4*)&qp[(size_t)(s0 + r) * DH + c4];
        *(float4*)&sh_q[r * 68 + c4] = v;
    }

    auto issueKV = [&](int it, int stg) {
        uint32_t kb = sb + (uint32_t)(A_KVOFF + stg * KV_STAGE) * 4;
        uint32_t vb = kb + (uint32_t)(32 * 68) * 4;
        int t0 = it * BT;
        #pragma unroll
        for (int i = 0; i < 2; i++) {
            int linear = tid + i * 256;
            int n = linear >> 4, k4 = (linear & 15) << 2;
            cp16(kb + (uint32_t)(n * 68 + k4) * 4, &kp[(size_t)(t0 + n) * DH + k4]);
            cp16(vb + (uint32_t)(n * 72 + k4) * 4, &vp[(size_t)(t0 + n) * DH + k4]);
        }
        cp_commit();
    };
    auto issueK = [&](int it, int stg) {
        uint32_t kb = sb + (uint32_t)(A_KVOFF + stg * KV_STAGE) * 4;
        int t0 = it * BT;
        #pragma unroll
        for (int i = 0; i < 2; i++) {
            int linear = tid + i * 256;
            int n = linear >> 4, k4 = (linear & 15) << 2;
            cp16(kb + (uint32_t)(n * 68 + k4) * 4, &kp[(size_t)(t0 + n) * DH + k4]);
        }
        cp_commit();
    };

    float m0 = -1e30f, m1 = -1e30f, l0 = 0.f, l1 = 0.f;
    float co[8][4];
    #pragma unroll
    for (int nj = 0; nj < 8; nj++)
        #pragma unroll
        for (int t = 0; t < 4; t++) co[nj][t] = 0.f;

    // ---------------- Pass A ----------------
    issueKV(0, 0);
    __syncthreads();    // Q tile visible (and stage-0 issue ordered)

    for (int it = 0; it < NT; it++) {
        int cur = it & 1;
        if (it + 1 < NT) { issueKV(it + 1, cur ^ 1); cp_wait<1>(); }
        else cp_wait<0>();
        __syncthreads();

        const uint32_t* KT_ = sm + A_KVOFF + cur * KV_STAGE;
        const uint32_t* VS_ = KT_ + 32 * 68;

        // scores: warp tile 16 x 32
        float sa[4][4];
        #pragma unroll
        for (int nj = 0; nj < 4; nj++)
            #pragma unroll
            for (int t = 0; t < 4; t++) sa[nj][t] = 0.f;

        #pragma unroll
        for (int ks8 = 0; ks8 < DH; ks8 += 8) {
            uint32_t af[4];
            af[0] = sh_q[(r0 + lr) * 68 + ks8 + lc];
            af[1] = sh_q[(r0 + 8 + lr) * 68 + ks8 + lc];
            af[2] = sh_q[(r0 + lr) * 68 + ks8 + 4 + lc];
            af[3] = sh_q[(r0 + 8 + lr) * 68 + ks8 + 4 + lc];
            #pragma unroll
            for (int nj = 0; nj < 4; nj++) {
                uint32_t bf[2];
                bf[0] = KT_[(nj * 8 + lr) * 68 + ks8 + lc];
                bf[1] = KT_[(nj * 8 + lr) * 68 + ks8 + 4 + lc];
                mma_tf32(sa[nj], af, bf);
            }
        }

        // online softmax
        float tmax0 = -1e30f, tmax1 = -1e30f;
        #pragma unroll
        for (int nj = 0; nj < 4; nj++) {
            sa[nj][0] *= 0.125f; sa[nj][1] *= 0.125f;
            sa[nj][2] *= 0.125f; sa[nj][3] *= 0.125f;
            tmax0 = fmaxf(tmax0, fmaxf(sa[nj][0], sa[nj][1]));
            tmax1 = fmaxf(tmax1, fmaxf(sa[nj][2], sa[nj][3]));
        }
        tmax0 = red4_max(tmax0); tmax1 = red4_max(tmax1);
        float nm0 = fmaxf(m0, tmax0), nm1 = fmaxf(m1, tmax1);
        float sc0 = __expf(m0 - nm0), sc1 = __expf(m1 - nm1);
        float ts0 = 0.f, ts1 = 0.f;
        #pragma unroll
        for (int nj = 0; nj < 4; nj++) {
            sa[nj][0] = __expf(sa[nj][0] - nm0); ts0 += sa[nj][0];
            sa[nj][1] = __expf(sa[nj][1] - nm0); ts0 += sa[nj][1];
            sa[nj][2] = __expf(sa[nj][2] - nm1); ts1 += sa[nj][2];
            sa[nj][3] = __expf(sa[nj][3] - nm1); ts1 += sa[nj][3];
        }
        ts0 = red4_sum(ts0); ts1 = red4_sum(ts1);
        l0 = l0 * sc0 + ts0; l1 = l1 * sc1 + ts1;
        m0 = nm0; m1 = nm1;
        #pragma unroll
        for (int nj = 0; nj < 8; nj++) {
            co[nj][0] *= sc0; co[nj][1] *= sc0;
            co[nj][2] *= sc1; co[nj][3] *= sc1;
        }

        // stage P (16x32 per warp) and accumulate P @ V (32x64)
        __syncwarp();
        #pragma unroll
        for (int j = 0; j < 4; j++) {
            sh_p[(r0 + lr) * 36 + j * 8 + 2 * lc]     = f2tf(sa[j][0]);
            sh_p[(r0 + lr) * 36 + j * 8 + 2 * lc + 1] = f2tf(sa[j][1]);
            sh_p[(r0 + 8 + lr) * 36 + j * 8 + 2 * lc]     = f2tf(sa[j][2]);
            sh_p[(r0 + 8 + lr) * 36 + j * 8 + 2 * lc + 1] = f2tf(sa[j][3]);
        }
        __syncwarp();
        #pragma unroll
        for (int ks8 = 0; ks8 < BT; ks8 += 8) {
            uint32_t af[4];
            af[0] = sh_p[(r0 + lr) * 36 + ks8 + lc];
            af[1] = sh_p[(r0 + 8 + lr) * 36 + ks8 + lc];
            af[2] = sh_p[(r0 + lr) * 36 + ks8 + 4 + lc];
            af[3] = sh_p[(r0 + 8 + lr) * 36 + ks8 + 4 + lc];
            #pragma unroll
            for (int nj8 = 0; nj8 < 8; nj8++) {
                uint32_t bf[2];
                bf[0] = VS_[(ks8 + lc) * 72 + nj8 * 8 + lr];
                bf[1] = VS_[(ks8 + 4 + lc) * 72 + nj8 * 8 + lr];
                mma_tf32(co[nj8], af, bf);
            }
        }
        __syncthreads();
    }

    // write ctx (normalized)
    const float invl0 = 1.f / l0, invl1 = 1.f / l1;
    const int b = bh / H, h = bh % H;
    #pragma unroll
    for (int nj = 0; nj < 8; nj++) {
        int sA = s0 + r0 + lr;
        int e = h * DH + nj * 8 + 2 * lc;
        float2 v0, v1;
        v0.x = co[nj][0] * invl0; v0.y = co[nj][1] * invl0;
        v1.x = co[nj][2] * invl1; v1.y = co[nj][3] * invl1;
        *(float2*)&g_ctx[((size_t)b * S + sA) * D + e] = v0;
        *(float2*)&g_ctx[((size_t)b * S + sA + 8) * D + e] = v1;
    }

    // ---------------- Pass B: recompute scores, write probs ----------------
    float* prow = probs + (size_t)bh * S * S;
    issueK(0, 0);
    for (int it = 0; it < NT; it++) {
        int cur = it & 1;
        if (it + 1 < NT) { issueK(it + 1, cur ^ 1); cp_wait<1>(); }
        else cp_wait<0>();
        __syncthreads();

        const uint32_t* KT_ = sm + A_KVOFF + cur * KV_STAGE;

        float sa[4][4];
        #pragma unroll
        for (int nj = 0; nj < 4; nj++)
            #pragma unroll
            for (int t = 0; t < 4; t++) sa[nj][t] = 0.f;

        #pragma unroll
        for (int ks8 = 0; ks8 < DH; ks8 += 8) {
            uint32_t af[4];
            af[0] = sh_q[(r0 + lr) * 68 + ks8 + lc];
            af[1] = sh_q[(r0 + 8 + lr) * 68 + ks8 + lc];
            af[2] = sh_q[(r0 + lr) * 68 + ks8 + 4 + lc];
            af[3] = sh_q[(r0 + 8 + lr) * 68 + ks8 + 4 + lc];
            #pragma unroll
            for (int nj = 0; nj < 4; nj++) {
                uint32_t bf[2];
                bf[0] = KT_[(nj * 8 + lr) * 68 + ks8 + lc];
                bf[1] = KT_[(nj * 8 + lr) * 68 + ks8 + 4 + lc];
                mma_tf32(sa[nj], af, bf);
            }
        }

        #pragma unroll
        for (int nj = 0; nj < 4; nj++) {
            int t = it * BT + nj * 8 + 2 * lc;
            float2 v0, v1;
            v0.x = __expf(sa[nj][0] * 0.125f - m0) * invl0;
            v0.y = __expf(sa[nj][1] * 0.125f - m0) * invl0;
            v1.x = __expf(sa[nj][2] * 0.125f - m1) * invl1;
            v1.y = __expf(sa[nj][3] * 0.125f - m1) * invl1;
            *(float2*)&prow[(size_t)(s0 + r0 + lr) * S + t] = v0;
            *(float2*)&prow[(size_t)(s0 + r0 + 8 + lr) * S + t] = v1;
        }
        __syncthreads();
    }
}

// ---------------------------------------------------------------------------
// K3: out[m,n] = sum_k ctx[m,k]*Wo[n,k] + bo[n], cp.async 2-stage
// ---------------------------------------------------------------------------
#define OUT_BSOFF (128 * 36)
#define OUT_STAGE (2 * 128 * 36)            // 9216 words
#define OUT_SMEM  (2 * OUT_STAGE * 4)       // 73728 B
#define OUT_KT    (D / 32)                  // 24

__global__ __launch_bounds__(256, 2) void out_kernel(
    const float* __restrict__ Wo, const float* __restrict__ bo,
    float* __restrict__ out)
{
    extern __shared__ uint32_t sm[];
    const uint32_t sb = (uint32_t)__cvta_generic_to_shared(sm);

    const int tid  = threadIdx.x;
    const int lane = tid & 31;
    const int warp = tid >> 5;
    const int wm   = warp & 1;
    const int wn   = warp >> 1;
    const int m0   = blockIdx.x * 128;
    const int n0   = blockIdx.y * 128;
    const int lr   = lane >> 2;
    const int lc   = lane & 3;

    auto issue = [&](int kt, int stg) {
        uint32_t as = sb + (uint32_t)(stg * OUT_STAGE) * 4;
        uint32_t bs = as + OUT_BSOFF * 4;
        #pragma unroll
        for (int i = 0; i < 4; i++) {
            int linear = tid + i * 256;
            int r = linear >> 3, c4 = (linear & 7) << 2;
            cp16(as + (uint32_t)(r * 36 + c4) * 4,
                 &g_ctx[(size_t)(m0 + r) * D + kt * 32 + c4]);
        }
        #pragma unroll
        for (int i = 0; i < 4; i++) {
            int linear = tid + i * 256;
            int n = linear >> 3, k4 = (linear & 7) << 2;
            cp16(bs + (uint32_t)(n * 36 + k4) * 4,
                 &Wo[(size_t)(n0 + n) * D + kt * 32 + k4]);
        }
        cp_commit();
    };

    float acc[4][4][4];
    #pragma unroll
    for (int i = 0; i < 4; i++)
        #pragma unroll
        for (int j = 0; j < 4; j++)
            #pragma unroll
            for (int t = 0; t < 4; t++) acc[i][j][t] = 0.f;

    issue(0, 0);
    for (int kt = 0; kt < OUT_KT; kt++) {
        int cur = kt & 1;
        if (kt + 1 < OUT_KT) { issue(kt + 1, cur ^ 1); cp_wait<1>(); }
        else cp_wait<0>();
        __syncthreads();

        const uint32_t* As = sm + cur * OUT_STAGE;
        const uint32_t* Bs = As + OUT_BSOFF;

        #pragma unroll
        for (int ks = 0; ks < 32; ks += 8) {
            uint32_t af[4][4], bf[4][2];
            #pragma unroll
            for (int mi = 0; mi < 4; mi++) {
                int r = wm * 64 + mi * 16 + lr;
                af[mi][0] = As[r * 36 + ks + lc];
                af[mi][1] = As[(r + 8) * 36 + ks + lc];
                af[mi][2] = As[r * 36 + ks + 4 + lc];
                af[mi][3] = As[(r + 8) * 36 + ks + 4 + lc];
            }
            #pragma unroll
            for (int nj = 0; nj < 4; nj++) {
                int n = wn * 32 + nj * 8 + lr;
                bf[nj][0] = Bs[n * 36 + ks + lc];
                bf[nj][1] = Bs[n * 36 + ks + 4 + lc];
            }
            #pragma unroll
            for (int mi = 0; mi < 4; mi++)
                #pragma unroll
                for (int nj = 0; nj < 4; nj++)
                    mma_tf32(acc[mi][nj], af[mi], bf[nj]);
        }
        __syncthreads();
    }

    #pragma unroll
    for (int mi = 0; mi < 4; mi++) {
        #pragma unroll
        for (int nj = 0; nj < 4; nj++) {
            #pragma unroll
            for (int half = 0; half < 2; half++) {
                int m = m0 + wm * 64 + mi * 16 + lr + half * 8;
                int n = n0 + wn * 32 + nj * 8 + (lc << 1);
                float2 v;
                v.x = acc[mi][nj][half * 2 + 0] + bo[n];
                v.y = acc[mi][nj][half * 2 + 1] + bo[n + 1];
                *(float2*)&out[(size_t)m * D + n] = v;
            }
        }
    }
}

// ---------------------------------------------------------------------------
extern "C" void kernel_launch(void* const* d_in, const int* in_sizes, int n_in,
                              void* d_out, int out_size)
{
    const float* x  = (const float*)d_in[0];
    const float* Wq = (const float*)d_in[1];
    const float* bq = (const float*)d_in[2];
    const float* Wk = (const float*)d_in[3];
    const float* bk = (const float*)d_in[4];
    const float* Wv = (const float*)d_in[5];
    const float* bv = (const float*)d_in[6];
    const float* Wo = (const float*)d_in[7];
    const float* bo = (const float*)d_in[8];

    float* out   = (float*)d_out;
    float* probs = out + OUT_ELEMS;

    static bool attr_done = false;
    if (!attr_done) {
        cudaFuncSetAttribute(qkv_kernel,
                             cudaFuncAttributeMaxDynamicSharedMemorySize, QKV_SMEM);
        cudaFuncSetAttribute(attn_kernel,
                             cudaFuncAttributeMaxDynamicSharedMemorySize, ATTN_SMEM);
        cudaFuncSetAttribute(out_kernel,
                             cudaFuncAttributeMaxDynamicSharedMemorySize, OUT_SMEM);
        attr_done = true;
    }

    repack_kernel<<<(D * NQKV + 255) / 256, 256>>>(Wq, Wk, Wv, bq, bk, bv);
    qkv_kernel<<<dim3(M_TOT / 128, NQKV / 128), 256, QKV_SMEM>>>(x);
    attn_kernel<<<dim3(S / 128, BH), 256, ATTN_SMEM>>>(probs);
    out_kernel<<<dim3(M_TOT / 128, D / 128), 256, OUT_SMEM>>>(Wo, bo, out);
}

// round 6
// speedup vs baseline: 3.2436x; 1.0050x over previous
#include <cuda_runtime.h>
#include <cstdint>

// Problem constants
#define H 12
#define D 768
#define DH 64
#define B 8
#define S 1024
#define M_TOT (B * S)            // 8192
#define BH (B * H)               // 96
#define OUT_ELEMS (B * S * D)    // 6291456
#define NQKV (H * 3 * DH)        // 2304
#define XE (M_TOT * D)           // 6291456
#define WOE (D * D)              // 589824

// Scratch (device globals — allocation-free per harness rules)
__device__ float g_q[BH * S * DH];          // tf32-rounded bit patterns
__device__ float g_k[BH * S * DH];
__device__ float g_v[BH * S * DH];
__device__ float g_ctx[M_TOT * D];          // tf32-rounded
__device__ uint32_t g_wcat[(size_t)D * NQKV];
__device__ float g_bcat[NQKV];
__device__ uint32_t g_xr[XE];               // tf32-rounded x
__device__ uint32_t g_wor[WOE];             // tf32-rounded Wo (same [n][k] layout)

// ---------------------------------------------------------------------------
__device__ __forceinline__ uint32_t f2tf(float x) {
    uint32_t r;
    asm("cvt.rna.tf32.f32 %0, %1;" : "=r"(r) : "f"(x));
    return r;
}

__device__ __forceinline__ void mma_tf32(float c[4], const uint32_t a[4],
                                         const uint32_t b[2]) {
    asm volatile(
        "mma.sync.aligned.m16n8k8.row.col.f32.tf32.tf32.f32 "
        "{%0,%1,%2,%3}, {%4,%5,%6,%7}, {%8,%9}, {%0,%1,%2,%3};\n"
        : "+f"(c[0]), "+f"(c[1]), "+f"(c[2]), "+f"(c[3])
        : "r"(a[0]), "r"(a[1]), "r"(a[2]), "r"(a[3]), "r"(b[0]), "r"(b[1]));
}

__device__ __forceinline__ void cp16(uint32_t saddr, const void* gptr) {
    asm volatile("cp.async.ca.shared.global [%0], [%1], 16;\n"
                 :: "r"(saddr), "l"(gptr));
}
__device__ __forceinline__ void cp_commit() {
    asm volatile("cp.async.commit_group;\n");
}
template <int N> __device__ __forceinline__ void cp_wait() {
    asm volatile("cp.async.wait_group %0;\n" :: "n"(N));
}

__device__ __forceinline__ float red4_max(float v) {
    v = fmaxf(v, __shfl_xor_sync(0xffffffffu, v, 1));
    v = fmaxf(v, __shfl_xor_sync(0xffffffffu, v, 2));
    return v;
}
__device__ __forceinline__ float red4_sum(float v) {
    v += __shfl_xor_sync(0xffffffffu, v, 1);
    v += __shfl_xor_sync(0xffffffffu, v, 2);
    return v;
}

// ---------------------------------------------------------------------------
// K0: repack. wcat [k][n] (tf32), bcat, xr (tf32 x), wor (tf32 Wo)
// ---------------------------------------------------------------------------
__global__ __launch_bounds__(256) void repack_kernel(
    const float* __restrict__ Wq, const float* __restrict__ Wk,
    const float* __restrict__ Wv, const float* __restrict__ bq,
    const float* __restrict__ bk, const float* __restrict__ bv,
    const float* __restrict__ x,  const float* __restrict__ Wo)
{
    int idx = blockIdx.x * 256 + threadIdx.x;
    if (idx < D * NQKV) {
        int k = idx / NQKV, n = idx - k * NQKV;
        int h = n / 192, rem = n % 192;
        int which = rem >> 6, e = rem & 63;
        const float* wp = (which == 0) ? Wq : (which == 1) ? Wk : Wv;
        g_wcat[idx] = f2tf(wp[((size_t)h * D + k) * DH + e]);
    }
    if (idx < NQKV) {
        int h = idx / 192, rem = idx % 192;
        int which = rem >> 6, e = rem & 63;
        const float* bp = (which == 0) ? bq : (which == 1) ? bk : bv;
        g_bcat[idx] = bp[h * DH + e];
    }
    if (idx < XE)  g_xr[idx]  = f2tf(x[idx]);
    if (idx < WOE) g_wor[idx] = f2tf(Wo[idx]);
}

// ---------------------------------------------------------------------------
// K1: QKV GEMM [8192 x 2304] = xr @ wcat, cp.async 3-stage
// ---------------------------------------------------------------------------
#define QKV_BSOFF (128 * 36)
#define QKV_STAGE (128 * 36 + 32 * 136)     // 8960 words
#define QKV_SMEM  (3 * QKV_STAGE * 4)       // 107520 B
#define QKV_KT    (D / 32)                  // 24

__global__ __launch_bounds__(256, 2) void qkv_kernel()
{
    extern __shared__ uint32_t sm[];
    const uint32_t sb = (uint32_t)__cvta_generic_to_shared(sm);

    const int tid  = threadIdx.x;
    const int lane = tid & 31;
    const int warp = tid >> 5;
    const int wm   = warp & 1;
    const int wn   = warp >> 1;
    const int m0   = blockIdx.x * 128;
    const int n0   = blockIdx.y * 128;
    const int lr   = lane >> 2;
    const int lc   = lane & 3;

    auto issue = [&](int kt, int stg) {
        uint32_t as = sb + (uint32_t)(stg * QKV_STAGE) * 4;
        uint32_t bs = as + QKV_BSOFF * 4;
        #pragma unroll
        for (int i = 0; i < 4; i++) {
            int linear = tid + i * 256;
            int r = linear >> 3, c4 = (linear & 7) << 2;
            cp16(as + (uint32_t)(r * 36 + c4) * 4,
                 &g_xr[(size_t)(m0 + r) * D + kt * 32 + c4]);
        }
        #pragma unroll
        for (int i = 0; i < 4; i++) {
            int linear = tid + i * 256;
            int r = linear >> 5, c4 = (linear & 31) << 2;
            cp16(bs + (uint32_t)(r * 136 + c4) * 4,
                 &g_wcat[(size_t)(kt * 32 + r) * NQKV + n0 + c4]);
        }
        cp_commit();
    };

    float acc[4][4][4];
    #pragma unroll
    for (int i = 0; i < 4; i++)
        #pragma unroll
        for (int j = 0; j < 4; j++)
            #pragma unroll
            for (int t = 0; t < 4; t++) acc[i][j][t] = 0.f;

    issue(0, 0); issue(1, 1);
    for (int kt = 0; kt < QKV_KT; kt++) {
        int cur = kt % 3;
        if (kt + 2 < QKV_KT)      { issue(kt + 2, (kt + 2) % 3); cp_wait<2>(); }
        else if (kt + 1 < QKV_KT) cp_wait<1>();
        else                      cp_wait<0>();
        __syncthreads();

        const uint32_t* As = sm + cur * QKV_STAGE;
        const uint32_t* Bs = As + QKV_BSOFF;

        #pragma unroll
        for (int ks = 0; ks < 32; ks += 8) {
            uint32_t af[4][4], bf[4][2];
            #pragma unroll
            for (int mi = 0; mi < 4; mi++) {
                int r = wm * 64 + mi * 16 + lr;
                af[mi][0] = As[r * 36 + ks + lc];
                af[mi][1] = As[(r + 8) * 36 + ks + lc];
                af[mi][2] = As[r * 36 + ks + 4 + lc];
                af[mi][3] = As[(r + 8) * 36 + ks + 4 + lc];
            }
            #pragma unroll
            for (int nj = 0; nj < 4; nj++) {
                int n = wn * 32 + nj * 8 + lr;
                bf[nj][0] = Bs[(ks + lc) * 136 + n];
                bf[nj][1] = Bs[(ks + 4 + lc) * 136 + n];
            }
            #pragma unroll
            for (int mi = 0; mi < 4; mi++)
                #pragma unroll
                for (int nj = 0; nj < 4; nj++)
                    mma_tf32(acc[mi][nj], af[mi], bf[nj]);
        }
        __syncthreads();
    }

    #pragma unroll
    for (int mi = 0; mi < 4; mi++) {
        #pragma unroll
        for (int nj = 0; nj < 4; nj++) {
            #pragma unroll
            for (int t = 0; t < 4; t++) {
                int r  = m0 + wm * 64 + mi * 16 + lr + ((t >= 2) ? 8 : 0);
                int gn = n0 + wn * 32 + nj * 8 + (lc << 1) + (t & 1);
                int b = r >> 10, s = r & 1023;
                int h = gn / 192, rem = gn % 192;
                int which = rem >> 6, e = rem & 63;
                float* dst = (which == 0) ? g_q : (which == 1) ? g_k : g_v;
                dst[(((size_t)b * H + h) * S + s) * DH + e] =
                    __uint_as_float(f2tf(acc[mi][nj][t] + g_bcat[gn]));
            }
        }
    }
}

// ---------------------------------------------------------------------------
// K2: fused attention. Q fragments in registers; smem = P + 2-stage KV,
// Q staging region aliased over it. grid (S/128, BH), 256 thr, 8 warps.
// ---------------------------------------------------------------------------
#define BT 32
#define NT (S / BT)                         // 32
#define A_KVOFF (128 * 36)                  // KV stages start after P
#define KV_STAGE (32 * 68 + 32 * 72)        // 4480 words
#define ATTN_WORDS (128 * 36 + 2 * KV_STAGE)           // 13568
#define ATTN_SMEM (ATTN_WORDS * 4)                     // 54272 B

__global__ __launch_bounds__(256, 2) void attn_kernel(float* __restrict__ probs)
{
    extern __shared__ uint32_t sm[];
    uint32_t* sh_p = sm;                    // [128][36]
    const uint32_t sb = (uint32_t)__cvta_generic_to_shared(sm);

    const int tid  = threadIdx.x;
    const int lane = tid & 31;
    const int warp = tid >> 5;
    const int lr   = lane >> 2;
    const int lc   = lane & 3;
    const int s0   = blockIdx.x * 128;
    const int bh   = blockIdx.y;
    const int r0   = warp * 16;

    const float* qp = g_q + (size_t)bh * S * DH;
    const float* kp = g_k + (size_t)bh * S * DH;
    const float* vp = g_v + (size_t)bh * S * DH;

    // ---- stage Q (aliased region, stride 68), then hoist frags to regs ----
    #pragma unroll
    for (int i = 0; i < 8; i++) {
        int linear = tid + i * 256;
        int r = linear >> 4, c4 = (linear & 15) << 2;
        float4 v = *(const float4*)&qp[(size_t)(s0 + r) * DH + c4];
        *(float4*)&sm[r * 68 + c4] = v;
    }
    __syncthreads();
    uint32_t qf[8][4];
    #pragma unroll
    for (int ks8 = 0; ks8 < 8; ks8++) {
        qf[ks8][0] = sm[(r0 + lr) * 68 + ks8 * 8 + lc];
        qf[ks8][1] = sm[(r0 + 8 + lr) * 68 + ks8 * 8 + lc];
        qf[ks8][2] = sm[(r0 + lr) * 68 + ks8 * 8 + 4 + lc];
        qf[ks8][3] = sm[(r0 + 8 + lr) * 68 + ks8 * 8 + 4 + lc];
    }
    __syncthreads();

    auto issueKV = [&](int it, int stg) {
        uint32_t kb = sb + (uint32_t)(A_KVOFF + stg * KV_STAGE) * 4;
        uint32_t vb = kb + (uint32_t)(32 * 68) * 4;
        int t0 = it * BT;
        #pragma unroll
        for (int i = 0; i < 2; i++) {
            int linear = tid + i * 256;
            int n = linear >> 4, k4 = (linear & 15) << 2;
            cp16(kb + (uint32_t)(n * 68 + k4) * 4, &kp[(size_t)(t0 + n) * DH + k4]);
            cp16(vb + (uint32_t)(n * 72 + k4) * 4, &vp[(size_t)(t0 + n) * DH + k4]);
        }
        cp_commit();
    };
    auto issueK = [&](int it, int stg) {
        uint32_t kb = sb + (uint32_t)(A_KVOFF + stg * KV_STAGE) * 4;
        int t0 = it * BT;
        #pragma unroll
        for (int i = 0; i < 2; i++) {
            int linear = tid + i * 256;
            int n = linear >> 4, k4 = (linear & 15) << 2;
            cp16(kb + (uint32_t)(n * 68 + k4) * 4, &kp[(size_t)(t0 + n) * DH + k4]);
        }
        cp_commit();
    };

    float m0 = -1e30f, m1 = -1e30f, l0 = 0.f, l1 = 0.f;
    float co[8][4];
    #pragma unroll
    for (int nj = 0; nj < 8; nj++)
        #pragma unroll
        for (int t = 0; t < 4; t++) co[nj][t] = 0.f;

    // ---------------- Pass A ----------------
    issueKV(0, 0);
    for (int it = 0; it < NT; it++) {
        int cur = it & 1;
        if (it + 1 < NT) { issueKV(it + 1, cur ^ 1); cp_wait<1>(); }
        else cp_wait<0>();
        __syncthreads();

        const uint32_t* KT_ = sm + A_KVOFF + cur * KV_STAGE;
        const uint32_t* VS_ = KT_ + 32 * 68;

        float sa[4][4];
        #pragma unroll
        for (int nj = 0; nj < 4; nj++)
            #pragma unroll
            for (int t = 0; t < 4; t++) sa[nj][t] = 0.f;

        #pragma unroll
        for (int ks8 = 0; ks8 < 8; ks8++) {
            #pragma unroll
            for (int nj = 0; nj < 4; nj++) {
                uint32_t bf[2];
                bf[0] = KT_[(nj * 8 + lr) * 68 + ks8 * 8 + lc];
                bf[1] = KT_[(nj * 8 + lr) * 68 + ks8 * 8 + 4 + lc];
                mma_tf32(sa[nj], qf[ks8], bf);
            }
        }

        // online softmax
        float tmax0 = -1e30f, tmax1 = -1e30f;
        #pragma unroll
        for (int nj = 0; nj < 4; nj++) {
            sa[nj][0] *= 0.125f; sa[nj][1] *= 0.125f;
            sa[nj][2] *= 0.125f; sa[nj][3] *= 0.125f;
            tmax0 = fmaxf(tmax0, fmaxf(sa[nj][0], sa[nj][1]));
            tmax1 = fmaxf(tmax1, fmaxf(sa[nj][2], sa[nj][3]));
        }
        tmax0 = red4_max(tmax0); tmax1 = red4_max(tmax1);
        float nm0 = fmaxf(m0, tmax0), nm1 = fmaxf(m1, tmax1);
        float sc0 = __expf(m0 - nm0), sc1 = __expf(m1 - nm1);
        float ts0 = 0.f, ts1 = 0.f;
        #pragma unroll
        for (int nj = 0; nj < 4; nj++) {
            sa[nj][0] = __expf(sa[nj][0] - nm0); ts0 += sa[nj][0];
            sa[nj][1] = __expf(sa[nj][1] - nm0); ts0 += sa[nj][1];
            sa[nj][2] = __expf(sa[nj][2] - nm1); ts1 += sa[nj][2];
            sa[nj][3] = __expf(sa[nj][3] - nm1); ts1 += sa[nj][3];
        }
        ts0 = red4_sum(ts0); ts1 = red4_sum(ts1);
        l0 = l0 * sc0 + ts0; l1 = l1 * sc1 + ts1;
        m0 = nm0; m1 = nm1;
        #pragma unroll
        for (int nj = 0; nj < 8; nj++) {
            co[nj][0] *= sc0; co[nj][1] *= sc0;
            co[nj][2] *= sc1; co[nj][3] *= sc1;
        }

        // stage P (16x32, warp-private rows) and accumulate P @ V
        __syncwarp();
        #pragma unroll
        for (int j = 0; j < 4; j++) {
            sh_p[(r0 + lr) * 36 + j * 8 + 2 * lc]         = f2tf(sa[j][0]);
            sh_p[(r0 + lr) * 36 + j * 8 + 2 * lc + 1]     = f2tf(sa[j][1]);
            sh_p[(r0 + 8 + lr) * 36 + j * 8 + 2 * lc]     = f2tf(sa[j][2]);
            sh_p[(r0 + 8 + lr) * 36 + j * 8 + 2 * lc + 1] = f2tf(sa[j][3]);
        }
        __syncwarp();
        #pragma unroll
        for (int ks8 = 0; ks8 < BT; ks8 += 8) {
            uint32_t af[4];
            af[0] = sh_p[(r0 + lr) * 36 + ks8 + lc];
            af[1] = sh_p[(r0 + 8 + lr) * 36 + ks8 + lc];
            af[2] = sh_p[(r0 + lr) * 36 + ks8 + 4 + lc];
            af[3] = sh_p[(r0 + 8 + lr) * 36 + ks8 + 4 + lc];
            #pragma unroll
            for (int nj8 = 0; nj8 < 8; nj8++) {
                uint32_t bf[2];
                bf[0] = VS_[(ks8 + lc) * 72 + nj8 * 8 + lr];
                bf[1] = VS_[(ks8 + 4 + lc) * 72 + nj8 * 8 + lr];
                mma_tf32(co[nj8], af, bf);
            }
        }
        __syncthreads();
    }

    // write ctx (normalized, tf32-rounded for out_kernel)
    const float invl0 = 1.f / l0, invl1 = 1.f / l1;
    const int b = bh / H, h = bh % H;
    #pragma unroll
    for (int nj = 0; nj < 8; nj++) {
        int sA = s0 + r0 + lr;
        int e = h * DH + nj * 8 + 2 * lc;
        float2 v0, v1;
        v0.x = __uint_as_float(f2tf(co[nj][0] * invl0));
        v0.y = __uint_as_float(f2tf(co[nj][1] * invl0));
        v1.x = __uint_as_float(f2tf(co[nj][2] * invl1));
        v1.y = __uint_as_float(f2tf(co[nj][3] * invl1));
        *(float2*)&g_ctx[((size_t)b * S + sA) * D + e] = v0;
        *(float2*)&g_ctx[((size_t)b * S + sA + 8) * D + e] = v1;
    }

    // ---------------- Pass B: recompute scores, write probs ----------------
    float* prow = probs + (size_t)bh * S * S;
    issueK(0, 0);
    for (int it = 0; it < NT; it++) {
        int cur = it & 1;
        if (it + 1 < NT) { issueK(it + 1, cur ^ 1); cp_wait<1>(); }
        else cp_wait<0>();
        __syncthreads();

        const uint32_t* KT_ = sm + A_KVOFF + cur * KV_STAGE;

        float sa[4][4];
        #pragma unroll
        for (int nj = 0; nj < 4; nj++)
            #pragma unroll
            for (int t = 0; t < 4; t++) sa[nj][t] = 0.f;

        #pragma unroll
        for (int ks8 = 0; ks8 < 8; ks8++) {
            #pragma unroll
            for (int nj = 0; nj < 4; nj++) {
                uint32_t bf[2];
                bf[0] = KT_[(nj * 8 + lr) * 68 + ks8 * 8 + lc];
                bf[1] = KT_[(nj * 8 + lr) * 68 + ks8 * 8 + 4 + lc];
                mma_tf32(sa[nj], qf[ks8], bf);
            }
        }

        #pragma unroll
        for (int nj = 0; nj < 4; nj++) {
            int t = it * BT + nj * 8 + 2 * lc;
            float2 v0, v1;
            v0.x = __expf(sa[nj][0] * 0.125f - m0) * invl0;
            v0.y = __expf(sa[nj][1] * 0.125f - m0) * invl0;
            v1.x = __expf(sa[nj][2] * 0.125f - m1) * invl1;
            v1.y = __expf(sa[nj][3] * 0.125f - m1) * invl1;
            *(float2*)&prow[(size_t)(s0 + r0 + lr) * S + t] = v0;
            *(float2*)&prow[(size_t)(s0 + r0 + 8 + lr) * S + t] = v1;
        }
        __syncthreads();
    }
}

// ---------------------------------------------------------------------------
// K3: out[m,n] = sum_k ctx[m,k]*wor[n,k] + bo[n], cp.async 3-stage
// ---------------------------------------------------------------------------
#define OUT_BSOFF (128 * 36)
#define OUT_STAGE (2 * 128 * 36)            // 9216 words
#define OUT_SMEM  (3 * OUT_STAGE * 4)       // 110592 B
#define OUT_KT    (D / 32)                  // 24

__global__ __launch_bounds__(256, 2) void out_kernel(
    const float* __restrict__ bo, float* __restrict__ out)
{
    extern __shared__ uint32_t sm[];
    const uint32_t sb = (uint32_t)__cvta_generic_to_shared(sm);

    const int tid  = threadIdx.x;
    const int lane = tid & 31;
    const int warp = tid >> 5;
    const int wm   = warp & 1;
    const int wn   = warp >> 1;
    const int m0   = blockIdx.x * 128;
    const int n0   = blockIdx.y * 128;
    const int lr   = lane >> 2;
    const int lc   = lane & 3;

    auto issue = [&](int kt, int stg) {
        uint32_t as = sb + (uint32_t)(stg * OUT_STAGE) * 4;
        uint32_t bs = as + OUT_BSOFF * 4;
        #pragma unroll
        for (int i = 0; i < 4; i++) {
            int linear = tid + i * 256;
            int r = linear >> 3, c4 = (linear & 7) << 2;
            cp16(as + (uint32_t)(r * 36 + c4) * 4,
                 &g_ctx[(size_t)(m0 + r) * D + kt * 32 + c4]);
        }
        #pragma unroll
        for (int i = 0; i < 4; i++) {
            int linear = tid + i * 256;
            int n = linear >> 3, k4 = (linear & 7) << 2;
            cp16(bs + (uint32_t)(n * 36 + k4) * 4,
                 &g_wor[(size_t)(n0 + n) * D + kt * 32 + k4]);
        }
        cp_commit();
    };

    float acc[4][4][4];
    #pragma unroll
    for (int i = 0; i < 4; i++)
        #pragma unroll
        for (int j = 0; j < 4; j++)
            #pragma unroll
            for (int t = 0; t < 4; t++) acc[i][j][t] = 0.f;

    issue(0, 0); issue(1, 1);
    for (int kt = 0; kt < OUT_KT; kt++) {
        int cur = kt % 3;
        if (kt + 2 < OUT_KT)      { issue(kt + 2, (kt + 2) % 3); cp_wait<2>(); }
        else if (kt + 1 < OUT_KT) cp_wait<1>();
        else                      cp_wait<0>();
        __syncthreads();

        const uint32_t* As = sm + cur * OUT_STAGE;
        const uint32_t* Bs = As + OUT_BSOFF;

        #pragma unroll
        for (int ks = 0; ks < 32; ks += 8) {
            uint32_t af[4][4], bf[4][2];
            #pragma unroll
            for (int mi = 0; mi < 4; mi++) {
                int r = wm * 64 + mi * 16 + lr;
                af[mi][0] = As[r * 36 + ks + lc];
                af[mi][1] = As[(r + 8) * 36 + ks + lc];
                af[mi][2] = As[r * 36 + ks + 4 + lc];
                af[mi][3] = As[(r + 8) * 36 + ks + 4 + lc];
            }
            #pragma unroll
            for (int nj = 0; nj < 4; nj++) {
                int n = wn * 32 + nj * 8 + lr;
                bf[nj][0] = Bs[n * 36 + ks + lc];
                bf[nj][1] = Bs[n * 36 + ks + 4 + lc];
            }
            #pragma unroll
            for (int mi = 0; mi < 4; mi++)
                #pragma unroll
                for (int nj = 0; nj < 4; nj++)
                    mma_tf32(acc[mi][nj], af[mi], bf[nj]);
        }
        __syncthreads();
    }

    #pragma unroll
    for (int mi = 0; mi < 4; mi++) {
        #pragma unroll
        for (int nj = 0; nj < 4; nj++) {
            #pragma unroll
            for (int half = 0; half < 2; half++) {
                int m = m0 + wm * 64 + mi * 16 + lr + half * 8;
                int n = n0 + wn * 32 + nj * 8 + (lc << 1);
                float2 v;
                v.x = acc[mi][nj][half * 2 + 0] + bo[n];
                v.y = acc[mi][nj][half * 2 + 1] + bo[n + 1];
                *(float2*)&out[(size_t)m * D + n] = v;
            }
        }
    }
}

// ---------------------------------------------------------------------------
extern "C" void kernel_launch(void* const* d_in, const int* in_sizes, int n_in,
                              void* d_out, int out_size)
{
    const float* x  = (const float*)d_in[0];
    const float* Wq = (const float*)d_in[1];
    const float* bq = (const float*)d_in[2];
    const float* Wk = (const float*)d_in[3];
    const float* bk = (const float*)d_in[4];
    const float* Wv = (const float*)d_in[5];
    const float* bv = (const float*)d_in[6];
    const float* Wo = (const float*)d_in[7];
    const float* bo = (const float*)d_in[8];

    float* out   = (float*)d_out;
    float* probs = out + OUT_ELEMS;

    static bool attr_done = false;
    if (!attr_done) {
        cudaFuncSetAttribute(qkv_kernel,
                             cudaFuncAttributeMaxDynamicSharedMemorySize, QKV_SMEM);
        cudaFuncSetAttribute(attn_kernel,
                             cudaFuncAttributeMaxDynamicSharedMemorySize, ATTN_SMEM);
        cudaFuncSetAttribute(out_kernel,
                             cudaFuncAttributeMaxDynamicSharedMemorySize, OUT_SMEM);
        attr_done = true;
    }

    repack_kernel<<<(XE + 255) / 256, 256>>>(Wq, Wk, Wv, bq, bk, bv, x, Wo);
    qkv_kernel<<<dim3(M_TOT / 128, NQKV / 128), 256, QKV_SMEM>>>();
    attn_kernel<<<dim3(S / 128, BH), 256, ATTN_SMEM>>>(probs);
    out_kernel<<<dim3(M_TOT / 128, D / 128), 256, OUT_SMEM>>>(bo, out);
}

// round 9
// speedup vs baseline: 3.4085x; 1.0509x over previous
#include <cuda_runtime.h>
#include <cstdint>

// Problem constants
#define H 12
#define D 768
#define DH 64
#define B 8
#define S 1024
#define M_TOT (B * S)            // 8192
#define BH (B * H)               // 96
#define OUT_ELEMS (B * S * D)    // 6291456
#define NQKV (H * 3 * DH)        // 2304
#define XE (M_TOT * D)           // 6291456
#define WOE (D * D)              // 589824

// Scratch (device globals — allocation-free per harness rules)
__device__ float g_q[BH * S * DH];          // tf32-rounded bit patterns
__device__ float g_k[BH * S * DH];
__device__ float g_v[BH * S * DH];
__device__ float g_ctx[M_TOT * D];          // tf32-rounded
__device__ uint32_t g_wcat[(size_t)D * NQKV];
__device__ float g_bcat[NQKV];
__device__ uint32_t g_xr[XE];               // tf32-rounded x
__device__ uint32_t g_wor[WOE];             // tf32-rounded Wo ([n][k] layout)

// ---------------------------------------------------------------------------
__device__ __forceinline__ uint32_t f2tf(float x) {
    uint32_t r;
    asm("cvt.rna.tf32.f32 %0, %1;" : "=r"(r) : "f"(x));
    return r;
}
__device__ __forceinline__ float ex2(float x) {
    float y;
    asm("ex2.approx.ftz.f32 %0, %1;" : "=f"(y) : "f"(x));
    return y;
}

__device__ __forceinline__ void mma_tf32(float c[4], const uint32_t a[4],
                                         const uint32_t b[2]) {
    asm volatile(
        "mma.sync.aligned.m16n8k8.row.col.f32.tf32.tf32.f32 "
        "{%0,%1,%2,%3}, {%4,%5,%6,%7}, {%8,%9}, {%0,%1,%2,%3};\n"
        : "+f"(c[0]), "+f"(c[1]), "+f"(c[2]), "+f"(c[3])
        : "r"(a[0]), "r"(a[1]), "r"(a[2]), "r"(a[3]), "r"(b[0]), "r"(b[1]));
}

__device__ __forceinline__ void cp16(uint32_t saddr, const void* gptr) {
    asm volatile("cp.async.ca.shared.global [%0], [%1], 16;\n"
                 :: "r"(saddr), "l"(gptr));
}
__device__ __forceinline__ void cp_commit() {
    asm volatile("cp.async.commit_group;\n");
}
template <int N> __device__ __forceinline__ void cp_wait() {
    asm volatile("cp.async.wait_group %0;\n" :: "n"(N));
}

__device__ __forceinline__ float red4_max(float v) {
    v = fmaxf(v, __shfl_xor_sync(0xffffffffu, v, 1));
    v = fmaxf(v, __shfl_xor_sync(0xffffffffu, v, 2));
    return v;
}
__device__ __forceinline__ float red4_sum(float v) {
    v += __shfl_xor_sync(0xffffffffu, v, 1);
    v += __shfl_xor_sync(0xffffffffu, v, 2);
    return v;
}

// ---------------------------------------------------------------------------
// K0: repack. wcat [k][n] (tf32), bcat, xr (tf32 x), wor (tf32 Wo)
// ---------------------------------------------------------------------------
__global__ __launch_bounds__(256) void repack_kernel(
    const float* __restrict__ Wq, const float* __restrict__ Wk,
    const float* __restrict__ Wv, const float* __restrict__ bq,
    const float* __restrict__ bk, const float* __restrict__ bv,
    const float* __restrict__ x,  const float* __restrict__ Wo)
{
    int idx = blockIdx.x * 256 + threadIdx.x;
    if (idx < D * NQKV) {
        int k = idx / NQKV, n = idx - k * NQKV;
        int h = n / 192, rem = n % 192;
        int which = rem >> 6, e = rem & 63;
        const float* wp = (which == 0) ? Wq : (which == 1) ? Wk : Wv;
        g_wcat[idx] = f2tf(wp[((size_t)h * D + k) * DH + e]);
    }
    if (idx < NQKV) {
        int h = idx / 192, rem = idx % 192;
        int which = rem >> 6, e = rem & 63;
        const float* bp = (which == 0) ? bq : (which == 1) ? bk : bv;
        g_bcat[idx] = bp[h * DH + e];
    }
    if (idx < XE)  g_xr[idx]  = f2tf(x[idx]);
    if (idx < WOE) g_wor[idx] = f2tf(Wo[idx]);
}

// ---------------------------------------------------------------------------
// K1: QKV GEMM [8192 x 2304] = xr @ wcat
// 3-stage cp.async ring, prefetch dist 1, ONE barrier per k-tile
// ---------------------------------------------------------------------------
#define QKV_BSOFF (128 * 36)
#define QKV_STAGE (128 * 36 + 32 * 136)     // 8960 words
#define QKV_SMEM  (3 * QKV_STAGE * 4)       // 107520 B
#define QKV_KT    (D / 32)                  // 24

__global__ __launch_bounds__(256, 2) void qkv_kernel()
{
    extern __shared__ uint32_t sm[];
    const uint32_t sb = (uint32_t)__cvta_generic_to_shared(sm);

    const int tid  = threadIdx.x;
    const int lane = tid & 31;
    const int warp = tid >> 5;
    const int wm   = warp & 1;
    const int wn   = warp >> 1;
    const int m0   = blockIdx.x * 128;
    const int n0   = blockIdx.y * 128;
    const int lr   = lane >> 2;
    const int lc   = lane & 3;

    auto issue = [&](int kt, int stg) {
        uint32_t as = sb + (uint32_t)(stg * QKV_STAGE) * 4;
        uint32_t bs = as + QKV_BSOFF * 4;
        #pragma unroll
        for (int i = 0; i < 4; i++) {
            int linear = tid + i * 256;
            int r = linear >> 3, c4 = (linear & 7) << 2;
            cp16(as + (uint32_t)(r * 36 + c4) * 4,
                 &g_xr[(size_t)(m0 + r) * D + kt * 32 + c4]);
        }
        #pragma unroll
        for (int i = 0; i < 4; i++) {
            int linear = tid + i * 256;
            int r = linear >> 5, c4 = (linear & 31) << 2;
            cp16(bs + (uint32_t)(r * 136 + c4) * 4,
                 &g_wcat[(size_t)(kt * 32 + r) * NQKV + n0 + c4]);
        }
        cp_commit();
    };

    float acc[4][4][4];
    #pragma unroll
    for (int i = 0; i < 4; i++)
        #pragma unroll
        for (int j = 0; j < 4; j++)
            #pragma unroll
            for (int t = 0; t < 4; t++) acc[i][j][t] = 0.f;

    issue(0, 0);
    for (int kt = 0; kt < QKV_KT; kt++) {
        int cur = kt % 3;
        if (kt + 1 < QKV_KT) { issue(kt + 1, (kt + 1) % 3); cp_wait<1>(); }
        else                 cp_wait<0>();
        __syncthreads();

        const uint32_t* As = sm + cur * QKV_STAGE;
        const uint32_t* Bs = As + QKV_BSOFF;

        #pragma unroll
        for (int ks = 0; ks < 32; ks += 8) {
            uint32_t af[4][4], bf[4][2];
            #pragma unroll
            for (int mi = 0; mi < 4; mi++) {
                int r = wm * 64 + mi * 16 + lr;
                af[mi][0] = As[r * 36 + ks + lc];
                af[mi][1] = As[(r + 8) * 36 + ks + lc];
                af[mi][2] = As[r * 36 + ks + 4 + lc];
                af[mi][3] = As[(r + 8) * 36 + ks + 4 + lc];
            }
            #pragma unroll
            for (int nj = 0; nj < 4; nj++) {
                int n = wn * 32 + nj * 8 + lr;
                bf[nj][0] = Bs[(ks + lc) * 136 + n];
                bf[nj][1] = Bs[(ks + 4 + lc) * 136 + n];
            }
            #pragma unroll
            for (int mi = 0; mi < 4; mi++)
                #pragma unroll
                for (int nj = 0; nj < 4; nj++)
                    mma_tf32(acc[mi][nj], af[mi], bf[nj]);
        }
        // no trailing barrier: ring depth 3 + dist 1 makes WAR safe
    }

    #pragma unroll
    for (int mi = 0; mi < 4; mi++) {
        #pragma unroll
        for (int nj = 0; nj < 4; nj++) {
            #pragma unroll
            for (int t = 0; t < 4; t++) {
                int r  = m0 + wm * 64 + mi * 16 + lr + ((t >= 2) ? 8 : 0);
                int gn = n0 + wn * 32 + nj * 8 + (lc << 1) + (t & 1);
                int b = r >> 10, s = r & 1023;
                int h = gn / 192, rem = gn % 192;
                int which = rem >> 6, e = rem & 63;
                float* dst = (which == 0) ? g_q : (which == 1) ? g_k : g_v;
                dst[(((size_t)b * H + h) * S + s) * DH + e] =
                    __uint_as_float(f2tf(acc[mi][nj][t] + g_bcat[gn]));
            }
        }
    }
}

// ---------------------------------------------------------------------------
// K2: fused attention. Q frags in registers; 4-stage KV ring, prefetch dist 2,
// ONE barrier per tile. grid (S/128, BH), 256 thr, 8 warps.
// ---------------------------------------------------------------------------
#define BT 32
#define NT (S / BT)                         // 32
#define A_KVOFF (128 * 36)                  // KV stages start after P
#define KV_STAGE (32 * 68 + 32 * 72)        // 4480 words
#define ATTN_WORDS (128 * 36 + 4 * KV_STAGE)           // 22528
#define ATTN_SMEM (ATTN_WORDS * 4)                     // 90112 B
#define C_L2E8 0.18033688f                  // 0.125 * log2(e)

__global__ __launch_bounds__(256, 2) void attn_kernel(float* __restrict__ probs)
{
    extern __shared__ uint32_t sm[];
    uint32_t* sh_p = sm;                    // [128][36]
    const uint32_t sb = (uint32_t)__cvta_generic_to_shared(sm);

    const int tid  = threadIdx.x;
    const int lane = tid & 31;
    const int warp = tid >> 5;
    const int lr   = lane >> 2;
    const int lc   = lane & 3;
    const int s0   = blockIdx.x * 128;
    const int bh   = blockIdx.y;
    const int r0   = warp * 16;

    const float* qp = g_q + (size_t)bh * S * DH;
    const float* kp = g_k + (size_t)bh * S * DH;
    const float* vp = g_v + (size_t)bh * S * DH;

    // ---- stage Q (aliased over P+KV region), hoist frags to registers ----
    #pragma unroll
    for (int i = 0; i < 8; i++) {
        int linear = tid + i * 256;
        int r = linear >> 4, c4 = (linear & 15) << 2;
        float4 v = *(const float4*)&qp[(size_t)(s0 + r) * DH + c4];
        *(float4*)&sm[r * 68 + c4] = v;
    }
    __syncthreads();
    uint32_t qf[8][4];
    #pragma unroll
    for (int ks8 = 0; ks8 < 8; ks8++) {
        qf[ks8][0] = sm[(r0 + lr) * 68 + ks8 * 8 + lc];
        qf[ks8][1] = sm[(r0 + 8 + lr) * 68 + ks8 * 8 + lc];
        qf[ks8][2] = sm[(r0 + lr) * 68 + ks8 * 8 + 4 + lc];
        qf[ks8][3] = sm[(r0 + 8 + lr) * 68 + ks8 * 8 + 4 + lc];
    }
    __syncthreads();

    auto issueKV = [&](int it, int stg) {
        uint32_t kb = sb + (uint32_t)(A_KVOFF + stg * KV_STAGE) * 4;
        uint32_t vb = kb + (uint32_t)(32 * 68) * 4;
        int t0 = it * BT;
        #pragma unroll
        for (int i = 0; i < 2; i++) {
            int linear = tid + i * 256;
            int n = linear >> 4, k4 = (linear & 15) << 2;
            cp16(kb + (uint32_t)(n * 68 + k4) * 4, &kp[(size_t)(t0 + n) * DH + k4]);
            cp16(vb + (uint32_t)(n * 72 + k4) * 4, &vp[(size_t)(t0 + n) * DH + k4]);
        }
        cp_commit();
    };
    auto issueK = [&](int it, int stg) {
        uint32_t kb = sb + (uint32_t)(A_KVOFF + stg * KV_STAGE) * 4;
        int t0 = it * BT;
        #pragma unroll
        for (int i = 0; i < 2; i++) {
            int linear = tid + i * 256;
            int n = linear >> 4, k4 = (linear & 15) << 2;
            cp16(kb + (uint32_t)(n * 68 + k4) * 4, &kp[(size_t)(t0 + n) * DH + k4]);
        }
        cp_commit();
    };

    float m0 = -1e30f, m1 = -1e30f, l0 = 0.f, l1 = 0.f;   // log2 domain
    float co[8][4];
    #pragma unroll
    for (int nj = 0; nj < 8; nj++)
        #pragma unroll
        for (int t = 0; t < 4; t++) co[nj][t] = 0.f;

    // ---------------- Pass A ----------------
    issueKV(0, 0); issueKV(1, 1);
    for (int it = 0; it < NT; it++) {
        int cur = it & 3;
        if (it + 2 < NT)      { issueKV(it + 2, (it + 2) & 3); cp_wait<2>(); }
        else if (it + 1 < NT) cp_wait<1>();
        else                  cp_wait<0>();
        __syncthreads();

        const uint32_t* KT_ = sm + A_KVOFF + cur * KV_STAGE;
        const uint32_t* VS_ = KT_ + 32 * 68;

        float sa[4][4];
        #pragma unroll
        for (int nj = 0; nj < 4; nj++)
            #pragma unroll
            for (int t = 0; t < 4; t++) sa[nj][t] = 0.f;

        #pragma unroll
        for (int ks8 = 0; ks8 < 8; ks8++) {
            #pragma unroll
            for (int nj = 0; nj < 4; nj++) {
                uint32_t bf[2];
                bf[0] = KT_[(nj * 8 + lr) * 68 + ks8 * 8 + lc];
                bf[1] = KT_[(nj * 8 + lr) * 68 + ks8 * 8 + 4 + lc];
                mma_tf32(sa[nj], qf[ks8], bf);
            }
        }

        // online softmax (log2 domain, ex2)
        float tmax0 = -1e30f, tmax1 = -1e30f;
        #pragma unroll
        for (int nj = 0; nj < 4; nj++) {
            sa[nj][0] *= C_L2E8; sa[nj][1] *= C_L2E8;
            sa[nj][2] *= C_L2E8; sa[nj][3] *= C_L2E8;
            tmax0 = fmaxf(tmax0, fmaxf(sa[nj][0], sa[nj][1]));
            tmax1 = fmaxf(tmax1, fmaxf(sa[nj][2], sa[nj][3]));
        }
        tmax0 = red4_max(tmax0); tmax1 = red4_max(tmax1);
        float nm0 = fmaxf(m0, tmax0), nm1 = fmaxf(m1, tmax1);
        float sc0 = ex2(m0 - nm0), sc1 = ex2(m1 - nm1);
        float ts0 = 0.f, ts1 = 0.f;
        #pragma unroll
        for (int nj = 0; nj < 4; nj++) {
            sa[nj][0] = ex2(sa[nj][0] - nm0); ts0 += sa[nj][0];
            sa[nj][1] = ex2(sa[nj][1] - nm0); ts0 += sa[nj][1];
            sa[nj][2] = ex2(sa[nj][2] - nm1); ts1 += sa[nj][2];
            sa[nj][3] = ex2(sa[nj][3] - nm1); ts1 += sa[nj][3];
        }
        ts0 = red4_sum(ts0); ts1 = red4_sum(ts1);
        l0 = l0 * sc0 + ts0; l1 = l1 * sc1 + ts1;
        m0 = nm0; m1 = nm1;
        #pragma unroll
        for (int nj = 0; nj < 8; nj++) {
            co[nj][0] *= sc0; co[nj][1] *= sc0;
            co[nj][2] *= sc1; co[nj][3] *= sc1;
        }

        // stage P (16x32, warp-private rows) and accumulate P @ V
        __syncwarp();
        #pragma unroll
        for (int j = 0; j < 4; j++) {
            sh_p[(r0 + lr) * 36 + j * 8 + 2 * lc]         = f2tf(sa[j][0]);
            sh_p[(r0 + lr) * 36 + j * 8 + 2 * lc + 1]     = f2tf(sa[j][1]);
            sh_p[(r0 + 8 + lr) * 36 + j * 8 + 2 * lc]     = f2tf(sa[j][2]);
            sh_p[(r0 + 8 + lr) * 36 + j * 8 + 2 * lc + 1] = f2tf(sa[j][3]);
        }
        __syncwarp();
        #pragma unroll
        for (int ks8 = 0; ks8 < BT; ks8 += 8) {
            uint32_t af[4];
            af[0] = sh_p[(r0 + lr) * 36 + ks8 + lc];
            af[1] = sh_p[(r0 + 8 + lr) * 36 + ks8 + lc];
            af[2] = sh_p[(r0 + lr) * 36 + ks8 + 4 + lc];
            af[3] = sh_p[(r0 + 8 + lr) * 36 + ks8 + 4 + lc];
            #pragma unroll
            for (int nj8 = 0; nj8 < 8; nj8++) {
                uint32_t bf[2];
                bf[0] = VS_[(ks8 + lc) * 72 + nj8 * 8 + lr];
                bf[1] = VS_[(ks8 + 4 + lc) * 72 + nj8 * 8 + lr];
                mma_tf32(co[nj8], af, bf);
            }
        }
        // no trailing barrier: 4-stage ring + dist-2 prefetch keeps WAR safe
    }

    // write ctx (normalized, tf32-rounded for out_kernel)
    const float invl0 = 1.f / l0, invl1 = 1.f / l1;
    const int b = bh / H, h = bh % H;
    #pragma unroll
    for (int nj = 0; nj < 8; nj++) {
        int sA = s0 + r0 + lr;
        int e = h * DH + nj * 8 + 2 * lc;
        float2 v0, v1;
        v0.x = __uint_as_float(f2tf(co[nj][0] * invl0));
        v0.y = __uint_as_float(f2tf(co[nj][1] * invl0));
        v1.x = __uint_as_float(f2tf(co[nj][2] * invl1));
        v1.y = __uint_as_float(f2tf(co[nj][3] * invl1));
        *(float2*)&g_ctx[((size_t)b * S + sA) * D + e] = v0;
        *(float2*)&g_ctx[((size_t)b * S + sA + 8) * D + e] = v1;
    }

    // ---------------- Pass B: recompute scores, write probs ----------------
    float* prow = probs + (size_t)bh * S * S;
    issueK(0, 0); issueK(1, 1);
    for (int it = 0; it < NT; it++) {
        int cur = it & 3;
        if (it + 2 < NT)      { issueK(it + 2, (it + 2) & 3); cp_wait<2>(); }
        else if (it + 1 < NT) cp_wait<1>();
        else                  cp_wait<0>();
        __syncthreads();

        const uint32_t* KT_ = sm + A_KVOFF + cur * KV_STAGE;

        float sa[4][4];
        #pragma unroll
        for (int nj = 0; nj < 4; nj++)
            #pragma unroll
            for (int t = 0; t < 4; t++) sa[nj][t] = 0.f;

        #pragma unroll
        for (int ks8 = 0; ks8 < 8; ks8++) {
            #pragma unroll
            for (int nj = 0; nj < 4; nj++) {
                uint32_t bf[2];
                bf[0] = KT_[(nj * 8 + lr) * 68 + ks8 * 8 + lc];
                bf[1] = KT_[(nj * 8 + lr) * 68 + ks8 * 8 + 4 + lc];
                mma_tf32(sa[nj], qf[ks8], bf);
            }
        }

        #pragma unroll
        for (int nj = 0; nj < 4; nj++) {
            int t = it * BT + nj * 8 + 2 * lc;
            float2 v0, v1;
            v0.x = ex2(sa[nj][0] * C_L2E8 - m0) * invl0;
            v0.y = ex2(sa[nj][1] * C_L2E8 - m0) * invl0;
            v1.x = ex2(sa[nj][2] * C_L2E8 - m1) * invl1;
            v1.y = ex2(sa[nj][3] * C_L2E8 - m1) * invl1;
            *(float2*)&prow[(size_t)(s0 + r0 + lr) * S + t] = v0;
            *(float2*)&prow[(size_t)(s0 + r0 + 8 + lr) * S + t] = v1;
        }
    }
}

// ---------------------------------------------------------------------------
// K3: out[m,n] = sum_k ctx[m,k]*wor[n,k] + bo[n]
// block tile 128x64 (grid 768 -> better wave balance), 3-stage, one barrier
// 8 warps as 4m x 2n, warp tile 32x32
// ---------------------------------------------------------------------------
#define OUT_BSOFF (128 * 36)
#define OUT_STAGE (128 * 36 + 64 * 36)      // 6912 words
#define OUT_SMEM  (3 * OUT_STAGE * 4)       // 82944 B
#define OUT_KT    (D / 32)                  // 24

__global__ __launch_bounds__(256, 2) void out_kernel(
    const float* __restrict__ bo, float* __restrict__ out)
{
    extern __shared__ uint32_t sm[];
    const uint32_t sb = (uint32_t)__cvta_generic_to_shared(sm);

    const int tid  = threadIdx.x;
    const int lane = tid & 31;
    const int warp = tid >> 5;
    const int wm   = warp & 3;              // 4 m-subtiles of 32
    const int wn   = warp >> 2;             // 2 n-subtiles of 32
    const int m0   = blockIdx.x * 128;
    const int n0   = blockIdx.y * 64;
    const int lr   = lane >> 2;
    const int lc   = lane & 3;

    auto issue = [&](int kt, int stg) {
        uint32_t as = sb + (uint32_t)(stg * OUT_STAGE) * 4;
        uint32_t bs = as + OUT_BSOFF * 4;
        #pragma unroll
        for (int i = 0; i < 4; i++) {
            int linear = tid + i * 256;
            int r = linear >> 3, c4 = (linear & 7) << 2;
            cp16(as + (uint32_t)(r * 36 + c4) * 4,
                 &g_ctx[(size_t)(m0 + r) * D + kt * 32 + c4]);
        }
        #pragma unroll
        for (int i = 0; i < 2; i++) {
            int linear = tid + i * 256;
            int n = linear >> 3, k4 = (linear & 7) << 2;
            cp16(bs + (uint32_t)(n * 36 + k4) * 4,
                 &g_wor[(size_t)(n0 + n) * D + kt * 32 + k4]);
        }
        cp_commit();
    };

    float acc[2][4][4];
    #pragma unroll
    for (int i = 0; i < 2; i++)
        #pragma unroll
        for (int j = 0; j < 4; j++)
            #pragma unroll
            for (int t = 0; t < 4; t++) acc[i][j][t] = 0.f;

    issue(0, 0);
    for (int kt = 0; kt < OUT_KT; kt++) {
        int cur = kt % 3;
        if (kt + 1 < OUT_KT) { issue(kt + 1, (kt + 1) % 3); cp_wait<1>(); }
        else                 cp_wait<0>();
        __syncthreads();

        const uint32_t* As = sm + cur * OUT_STAGE;
        const uint32_t* Bs = As + OUT_BSOFF;

        #pragma unroll
        for (int ks = 0; ks < 32; ks += 8) {
            uint32_t af[2][4], bf[4][2];
            #pragma unroll
            for (int mi = 0; mi < 2; mi++) {
                int r = wm * 32 + mi * 16 + lr;
                af[mi][0] = As[r * 36 + ks + lc];
                af[mi][1] = As[(r + 8) * 36 + ks + lc];
                af[mi][2] = As[r * 36 + ks + 4 + lc];
                af[mi][3] = As[(r + 8) * 36 + ks + 4 + lc];
            }
            #pragma unroll
            for (int nj = 0; nj < 4; nj++) {
                int n = wn * 32 + nj * 8 + lr;
                bf[nj][0] = Bs[n * 36 + ks + lc];
                bf[nj][1] = Bs[n * 36 + ks + 4 + lc];
            }
            #pragma unroll
            for (int mi = 0; mi < 2; mi++)
                #pragma unroll
                for (int nj = 0; nj < 4; nj++)
                    mma_tf32(acc[mi][nj], af[mi], bf[nj]);
        }
        // no trailing barrier (3-stage ring, dist 1)
    }

    #pragma unroll
    for (int mi = 0; mi < 2; mi++) {
        #pragma unroll
        for (int nj = 0; nj < 4; nj++) {
            #pragma unroll
            for (int half = 0; half < 2; half++) {
                int m = m0 + wm * 32 + mi * 16 + lr + half * 8;
                int n = n0 + wn * 32 + nj * 8 + (lc << 1);
                float2 v;
                v.x = acc[mi][nj][half * 2 + 0] + bo[n];
                v.y = acc[mi][nj][half * 2 + 1] + bo[n + 1];
                *(float2*)&out[(size_t)m * D + n] = v;
            }
        }
    }
}

// ---------------------------------------------------------------------------
extern "C" void kernel_launch(void* const* d_in, const int* in_sizes, int n_in,
                              void* d_out, int out_size)
{
    const float* x  = (const float*)d_in[0];
    const float* Wq = (const float*)d_in[1];
    const float* bq = (const float*)d_in[2];
    const float* Wk = (const float*)d_in[3];
    const float* bk = (const float*)d_in[4];
    const float* Wv = (const float*)d_in[5];
    const float* bv = (const float*)d_in[6];
    const float* Wo = (const float*)d_in[7];
    const float* bo = (const float*)d_in[8];

    float* out   = (float*)d_out;
    float* probs = out + OUT_ELEMS;

    static bool attr_done = false;
    if (!attr_done) {
        cudaFuncSetAttribute(qkv_kernel,
                             cudaFuncAttributeMaxDynamicSharedMemorySize, QKV_SMEM);
        cudaFuncSetAttribute(attn_kernel,
                             cudaFuncAttributeMaxDynamicSharedMemorySize, ATTN_SMEM);
        cudaFuncSetAttribute(out_kernel,
                             cudaFuncAttributeMaxDynamicSharedMemorySize, OUT_SMEM);
        attr_done = true;
    }

    repack_kernel<<<(XE + 255) / 256, 256>>>(Wq, Wk, Wv, bq, bk, bv, x, Wo);
    qkv_kernel<<<dim3(M_TOT / 128, NQKV / 128), 256, QKV_SMEM>>>();
    attn_kernel<<<dim3(S / 128, BH), 256, ATTN_SMEM>>>(probs);
    out_kernel<<<dim3(M_TOT / 128, D / 64), 256, OUT_SMEM>>>(bo, out);
}

// round 10
// speedup vs baseline: 3.6021x; 1.0568x over previous
#include <cuda_runtime.h>
#include <cstdint>

// Problem constants
#define H 12
#define D 768
#define DH 64
#define B 8
#define S 1024
#define M_TOT (B * S)            // 8192
#define BH (B * H)               // 96
#define OUT_ELEMS (B * S * D)    // 6291456
#define NQKV (H * 3 * DH)        // 2304
#define XE (M_TOT * D)           // 6291456
#define WOE (D * D)              // 589824
#define KTILES (D / 32)          // 24

// Packed-layout scratch (device globals — allocation-free per harness rules)
// A-pack (128x32 tile, 4096 words): word = ((rb*4+ks)*32 + lr*4+lc)*4 + (hi+2*chi)
//   where r=rb*16+hi*8+lr, c=ks*8+chi*4+lc
// B-pack (Nx32 tile): word = ((nb*4+ks)*32 + lr*4+lc)*2 + chi ; n=nb*8+lr, k=ks*8+chi*4+lc
__device__ float    g_q[BH * S * DH];          // k-col-paired within 8-groups
__device__ float    g_k[BH * S * DH];          // k-col-paired within 8-groups
__device__ uint32_t g_vp[BH * S * DH];         // B-frag packed per (bh, t-tile32)
__device__ uint32_t g_ctxp[(size_t)M_TOT * D]; // A-frag packed per (mt, kt)
__device__ uint32_t g_xrp[XE];                 // A-frag packed x
__device__ uint32_t g_wcatp[(size_t)D * NQKV]; // B-frag packed Wcat
__device__ uint32_t g_worp[WOE];               // B-frag packed Wo
__device__ float    g_bcat[NQKV];

// ---------------------------------------------------------------------------
__device__ __forceinline__ uint32_t f2tf(float x) {
    uint32_t r;
    asm("cvt.rna.tf32.f32 %0, %1;" : "=r"(r) : "f"(x));
    return r;
}
__device__ __forceinline__ float ex2(float x) {
    float y;
    asm("ex2.approx.ftz.f32 %0, %1;" : "=f"(y) : "f"(x));
    return y;
}
__device__ __forceinline__ void mma_tf32(float c[4], const uint32_t a[4],
                                         const uint32_t b[2]) {
    asm volatile(
        "mma.sync.aligned.m16n8k8.row.col.f32.tf32.tf32.f32 "
        "{%0,%1,%2,%3}, {%4,%5,%6,%7}, {%8,%9}, {%0,%1,%2,%3};\n"
        : "+f"(c[0]), "+f"(c[1]), "+f"(c[2]), "+f"(c[3])
        : "r"(a[0]), "r"(a[1]), "r"(a[2]), "r"(a[3]), "r"(b[0]), "r"(b[1]));
}
__device__ __forceinline__ void cp16(uint32_t saddr, const void* gptr) {
    asm volatile("cp.async.ca.shared.global [%0], [%1], 16;\n"
                 :: "r"(saddr), "l"(gptr));
}
__device__ __forceinline__ void cp_commit() {
    asm volatile("cp.async.commit_group;\n");
}
template <int N> __device__ __forceinline__ void cp_wait() {
    asm volatile("cp.async.wait_group %0;\n" :: "n"(N));
}
__device__ __forceinline__ float red4_sum(float v) {
    v += __shfl_xor_sync(0xffffffffu, v, 1);
    v += __shfl_xor_sync(0xffffffffu, v, 2);
    return v;
}

// ---------------------------------------------------------------------------
// K0: repack into fragment-packed layouts
// ---------------------------------------------------------------------------
__global__ __launch_bounds__(256) void repack_kernel(
    const float* __restrict__ Wq, const float* __restrict__ Wk,
    const float* __restrict__ Wv, const float* __restrict__ bq,
    const float* __restrict__ bk, const float* __restrict__ bv,
    const float* __restrict__ x,  const float* __restrict__ Wo)
{
    int idx = blockIdx.x * 256 + threadIdx.x;

    if (idx < XE) {   // x -> A-pack
        int m = idx / D, k = idx - m * D;
        int mt = m >> 7, r = m & 127, kt = k >> 5, c = k & 31;
        int rb = r >> 4, rr = r & 15, lr = rr & 7, hi = rr >> 3;
        int ks = c >> 3, c8 = c & 7, lc = c8 & 3, chi = c8 >> 2;
        int word = ((rb * 4 + ks) * 32 + lr * 4 + lc) * 4 + hi + 2 * chi;
        g_xrp[(size_t)(mt * KTILES + kt) * 4096 + word] = f2tf(x[idx]);
    }
    if (idx < D * NQKV) {   // Wcat -> B-pack
        int k = idx / NQKV, n = idx - k * NQKV;
        int h = n / 192, rem = n % 192;
        int which = rem >> 6, e = rem & 63;
        const float* wp = (which == 0) ? Wq : (which == 1) ? Wk : Wv;
        uint32_t val = f2tf(wp[((size_t)h * D + k) * DH + e]);
        int nt = n >> 7, n128 = n & 127, kt = k >> 5, c = k & 31;
        int nb = n128 >> 3, lr = n128 & 7;
        int ks = c >> 3, c8 = c & 7, lc = c8 & 3, chi = c8 >> 2;
        int word = ((nb * 4 + ks) * 32 + lr * 4 + lc) * 2 + chi;
        g_wcatp[(size_t)(nt * KTILES + kt) * 4096 + word] = val;
    }
    if (idx < WOE) {   // Wo[n][k] -> B-pack
        int n = idx / D, k = idx - n * D;
        int nt = n >> 6, n64 = n & 63, kt = k >> 5, c = k & 31;
        int nb = n64 >> 3, lr = n64 & 7;
        int ks = c >> 3, c8 = c & 7, lc = c8 & 3, chi = c8 >> 2;
        int word = ((nb * 4 + ks) * 32 + lr * 4 + lc) * 2 + chi;
        g_worp[(size_t)(nt * KTILES + kt) * 2048 + word] = f2tf(Wo[idx]);
    }
    if (idx < NQKV) {
        int h = idx / 192, rem = idx % 192;
        int which = rem >> 6, e = rem & 63;
        const float* bp = (which == 0) ? bq : (which == 1) ? bk : bv;
        g_bcat[idx] = bp[h * DH + e];
    }
}

// ---------------------------------------------------------------------------
// K1: QKV GEMM [8192 x 2304], packed operands, 3-stage ring, one barrier
// ---------------------------------------------------------------------------
#define QKV_STAGE 8192                      // 4096 A + 4096 B words
#define QKV_SMEM  (3 * QKV_STAGE * 4)       // 98304 B

__global__ __launch_bounds__(256, 2) void qkv_kernel()
{
    extern __shared__ uint32_t sm[];
    const uint32_t sb = (uint32_t)__cvta_generic_to_shared(sm);

    const int tid  = threadIdx.x;
    const int lane = tid & 31;
    const int warp = tid >> 5;
    const int wm   = warp & 1;
    const int wn   = warp >> 1;
    const int mt   = blockIdx.x;
    const int nt   = blockIdx.y;
    const int lr   = lane >> 2;
    const int lc   = lane & 3;

    const uint32_t* gA = g_xrp  + (size_t)(mt * KTILES) * 4096;
    const uint32_t* gB = g_wcatp + (size_t)(nt * KTILES) * 4096;

    auto issue = [&](int kt, int stg) {
        uint32_t as = sb + (uint32_t)(stg * QKV_STAGE) * 4;
        uint32_t bs = as + 4096 * 4;
        #pragma unroll
        for (int i = 0; i < 4; i++) {
            int linear = tid + i * 256;
            cp16(as + linear * 16, gA + (size_t)kt * 4096 + linear * 4);
            cp16(bs + linear * 16, gB + (size_t)kt * 4096 + linear * 4);
        }
        cp_commit();
    };

    float acc[4][4][4];
    #pragma unroll
    for (int i = 0; i < 4; i++)
        #pragma unroll
        for (int j = 0; j < 4; j++)
            #pragma unroll
            for (int t = 0; t < 4; t++) acc[i][j][t] = 0.f;

    issue(0, 0);
    for (int kt = 0; kt < KTILES; kt++) {
        int cur = kt % 3;
        if (kt + 1 < KTILES) { issue(kt + 1, (kt + 1) % 3); cp_wait<1>(); }
        else                 cp_wait<0>();
        __syncthreads();

        const uint32_t* As = sm + cur * QKV_STAGE;
        const uint32_t* Bs = As + 4096;

        #pragma unroll
        for (int ks8 = 0; ks8 < 4; ks8++) {
            uint32_t af[4][4], bf[4][2];
            #pragma unroll
            for (int mi = 0; mi < 4; mi++) {
                uint4 v = *(const uint4*)&As[((wm * 4 + mi) * 4 + ks8) * 128 + lane * 4];
                af[mi][0] = v.x; af[mi][1] = v.y; af[mi][2] = v.z; af[mi][3] = v.w;
            }
            #pragma unroll
            for (int nj = 0; nj < 4; nj++) {
                uint2 v = *(const uint2*)&Bs[((wn * 4 + nj) * 4 + ks8) * 64 + lane * 2];
                bf[nj][0] = v.x; bf[nj][1] = v.y;
            }
            #pragma unroll
            for (int mi = 0; mi < 4; mi++)
                #pragma unroll
                for (int nj = 0; nj < 4; nj++)
                    mma_tf32(acc[mi][nj], af[mi], bf[nj]);
        }
    }

    // epilogue: q/k with k-col pairing perm; v fragment-packed
    #pragma unroll
    for (int mi = 0; mi < 4; mi++) {
        #pragma unroll
        for (int nj = 0; nj < 4; nj++) {
            #pragma unroll
            for (int t = 0; t < 4; t++) {
                int r  = mt * 128 + wm * 64 + mi * 16 + lr + ((t >= 2) ? 8 : 0);
                int gn = nt * 128 + wn * 32 + nj * 8 + (lc << 1) + (t & 1);
                int b = r >> 10, s = r & 1023;
                int h = gn / 192, rem = gn % 192;
                int which = rem >> 6, e = rem & 63;
                uint32_t val = f2tf(acc[mi][nj][t] + g_bcat[gn]);
                if (which < 2) {
                    int e8 = e & 7;
                    int ep = (e & ~7) | (((e8 & 3) << 1) | (e8 >> 2));
                    float* dst = (which == 0) ? g_q : g_k;
                    dst[(((size_t)b * H + h) * S + s) * DH + ep] =
                        __uint_as_float(val);
                } else {
                    int tt = s >> 5, t32 = s & 31;
                    int ks = t32 >> 3, t8 = t32 & 7;
                    int lct = t8 & 3, chit = t8 >> 2;
                    int nb = e >> 3, lre = e & 7;
                    int word = ((nb * 4 + ks) * 32 + lre * 4 + lct) * 2 + chit;
                    g_vp[((size_t)(b * H + h) * 32 + tt) * 2048 + word] = val;
                }
            }
        }
    }
}

// ---------------------------------------------------------------------------
// K2: fused attention, max-free softmax, packed K/V/P frags
// grid (S/128, BH), 256 thr, 8 warps; warp w owns rows w*16..w*16+15.
// ---------------------------------------------------------------------------
#define NT 32                               // S / 32
#define A_KVOFF 4096                        // P pack: 8 warps * 512 words
#define K_WORDS (32 * 72)                   // 2304 (stride-72 rows)
#define KV_STAGE (K_WORDS + 2048)           // 4352
#define ATTN_SMEM ((4096 + 4 * KV_STAGE) * 4)   // 86016 B
#define C_L2E8 0.18033688f                  // 0.125 * log2(e)

__global__ __launch_bounds__(256, 2) void attn_kernel(float* __restrict__ probs)
{
    extern __shared__ uint32_t sm[];
    uint32_t* sh_p = sm;                    // P pack region
    const uint32_t sb = (uint32_t)__cvta_generic_to_shared(sm);

    const int tid  = threadIdx.x;
    const int lane = tid & 31;
    const int warp = tid >> 5;
    const int lr   = lane >> 2;
    const int lc   = lane & 3;
    const int s0   = blockIdx.x * 128;
    const int bh   = blockIdx.y;
    const int r0   = warp * 16;

    const float* qp = g_q + (size_t)bh * S * DH;
    const float* kp = g_k + (size_t)bh * S * DH;
    const uint32_t* vp = g_vp + (size_t)bh * 32 * 2048;

    // stage Q (stride 72), hoist frags (paired cols: 2lc, 2lc+1)
    #pragma unroll
    for (int i = 0; i < 8; i++) {
        int linear = tid + i * 256;
        int r = linear >> 4, c4 = (linear & 15) << 2;
        float4 v = *(const float4*)&qp[(size_t)(s0 + r) * DH + c4];
        *(float4*)&sm[r * 72 + c4] = v;
    }
    __syncthreads();
    uint32_t qf[8][4];
    #pragma unroll
    for (int ks8 = 0; ks8 < 8; ks8++) {
        uint2 qa = *(const uint2*)&sm[(r0 + lr) * 72 + ks8 * 8 + 2 * lc];
        uint2 qb = *(const uint2*)&sm[(r0 + 8 + lr) * 72 + ks8 * 8 + 2 * lc];
        qf[ks8][0] = qa.x; qf[ks8][1] = qb.x; qf[ks8][2] = qa.y; qf[ks8][3] = qb.y;
    }
    __syncthreads();

    auto issueKV = [&](int it, int stg) {
        uint32_t kb = sb + (uint32_t)(A_KVOFF + stg * KV_STAGE) * 4;
        uint32_t vb = kb + (uint32_t)K_WORDS * 4;
        #pragma unroll
        for (int i = 0; i < 2; i++) {
            int linear = tid + i * 256;
            int n = linear >> 4, k4 = (linear & 15) << 2;
            cp16(kb + (uint32_t)(n * 72 + k4) * 4,
                 &kp[(size_t)(it * 32 + n) * DH + k4]);
            cp16(vb + (uint32_t)linear * 16, vp + (size_t)it * 2048 + linear * 4);
        }
        cp_commit();
    };
    auto issueK = [&](int it, int stg) {
        uint32_t kb = sb + (uint32_t)(A_KVOFF + stg * KV_STAGE) * 4;
        #pragma unroll
        for (int i = 0; i < 2; i++) {
            int linear = tid + i * 256;
            int n = linear >> 4, k4 = (linear & 15) << 2;
            cp16(kb + (uint32_t)(n * 72 + k4) * 4,
                 &kp[(size_t)(it * 32 + n) * DH + k4]);
        }
        cp_commit();
    };

    float l0 = 0.f, l1 = 0.f;               // per-thread partials
    float co[8][4];
    #pragma unroll
    for (int nj = 0; nj < 8; nj++)
        #pragma unroll
        for (int t = 0; t < 4; t++) co[nj][t] = 0.f;

    // ---------------- Pass A ----------------
    issueKV(0, 0); issueKV(1, 1);
    for (int it = 0; it < NT; it++) {
        int cur = it & 3;
        if (it + 2 < NT)      { issueKV(it + 2, (it + 2) & 3); cp_wait<2>(); }
        else if (it + 1 < NT) cp_wait<1>();
        else                  cp_wait<0>();
        __syncthreads();

        const uint32_t* KT_ = sm + A_KVOFF + cur * KV_STAGE;
        const uint32_t* VS_ = KT_ + K_WORDS;

        float sa[4][4];
        #pragma unroll
        for (int nj = 0; nj < 4; nj++)
            #pragma unroll
            for (int t = 0; t < 4; t++) sa[nj][t] = 0.f;

        #pragma unroll
        for (int ks8 = 0; ks8 < 8; ks8++) {
            #pragma unroll
            for (int nj = 0; nj < 4; nj++) {
                uint2 kk = *(const uint2*)&KT_[(nj * 8 + lr) * 72 + ks8 * 8 + 2 * lc];
                uint32_t bf[2] = {kk.x, kk.y};
                mma_tf32(sa[nj], qf[ks8], bf);
            }
        }

        // max-free softmax: p = exp2(s * C); accumulate per-thread l
        #pragma unroll
        for (int nj = 0; nj < 4; nj++) {
            sa[nj][0] = ex2(sa[nj][0] * C_L2E8); l0 += sa[nj][0];
            sa[nj][1] = ex2(sa[nj][1] * C_L2E8); l0 += sa[nj][1];
            sa[nj][2] = ex2(sa[nj][2] * C_L2E8); l1 += sa[nj][2];
            sa[nj][3] = ex2(sa[nj][3] * C_L2E8); l1 += sa[nj][3];
        }

        // stage P fragment-packed (warp-private): 2 STS.64 per j
        __syncwarp();
        uint32_t pbase = warp * 512;
        #pragma unroll
        for (int j = 0; j < 4; j++) {
            int chi = lc >> 1;
            int lcb = (2 * lc) & 3;
            uint2 u0 = {f2tf(sa[j][0]), f2tf(sa[j][2])};
            uint2 u1 = {f2tf(sa[j][1]), f2tf(sa[j][3])};
            *(uint2*)&sh_p[pbase + j * 128 + (lr * 4 + lcb) * 4 + 2 * chi] = u0;
            *(uint2*)&sh_p[pbase + j * 128 + (lr * 4 + lcb + 1) * 4 + 2 * chi] = u1;
        }
        __syncwarp();
        #pragma unroll
        for (int ks8 = 0; ks8 < 4; ks8++) {
            uint4 pa = *(const uint4*)&sh_p[pbase + ks8 * 128 + lane * 4];
            uint32_t af[4] = {pa.x, pa.y, pa.z, pa.w};
            #pragma unroll
            for (int nj8 = 0; nj8 < 8; nj8++) {
                uint2 vv = *(const uint2*)&VS_[((nj8 * 4 + ks8) * 32 + lane) * 2];
                uint32_t bf[2] = {vv.x, vv.y};
                mma_tf32(co[nj8], af, bf);
            }
        }
    }

    l0 = red4_sum(l0); l1 = red4_sum(l1);
    const float invl0 = 1.f / l0, invl1 = 1.f / l1;
    const int b = bh / H, h = bh % H;
    const int mt = b * 8 + (s0 >> 7);

    // write ctx fragment-packed for out_kernel
    #pragma unroll
    for (int nj = 0; nj < 8; nj++) {
        int kt = h * 2 + (nj >> 2);
        int ks = nj & 3;
        size_t tbase = ((size_t)mt * KTILES + kt) * 4096;
        #pragma unroll
        for (int t = 0; t < 4; t++) {
            int hi = t >> 1, bb = t & 1;
            int c8 = 2 * lc + bb;
            int lcb = c8 & 3, chi = c8 >> 2;
            int word = ((warp * 4 + ks) * 32 + lr * 4 + lcb) * 4 + hi + 2 * chi;
            float inv = hi ? invl1 : invl0;
            g_ctxp[tbase + word] = f2tf(co[nj][t] * inv);
        }
    }

    // ---------------- Pass B: recompute scores, write probs ----------------
    float* prow = probs + (size_t)bh * S * S;
    issueK(0, 0); issueK(1, 1);
    for (int it = 0; it < NT; it++) {
        int cur = it & 3;
        if (it + 2 < NT)      { issueK(it + 2, (it + 2) & 3); cp_wait<2>(); }
        else if (it + 1 < NT) cp_wait<1>();
        else                  cp_wait<0>();
        __syncthreads();

        const uint32_t* KT_ = sm + A_KVOFF + cur * KV_STAGE;

        float sa[4][4];
        #pragma unroll
        for (int nj = 0; nj < 4; nj++)
            #pragma unroll
            for (int t = 0; t < 4; t++) sa[nj][t] = 0.f;

        #pragma unroll
        for (int ks8 = 0; ks8 < 8; ks8++) {
            #pragma unroll
            for (int nj = 0; nj < 4; nj++) {
                uint2 kk = *(const uint2*)&KT_[(nj * 8 + lr) * 72 + ks8 * 8 + 2 * lc];
                uint32_t bf[2] = {kk.x, kk.y};
                mma_tf32(sa[nj], qf[ks8], bf);
            }
        }

        #pragma unroll
        for (int nj = 0; nj < 4; nj++) {
            int t = it * 32 + nj * 8 + 2 * lc;
            float2 v0, v1;
            v0.x = ex2(sa[nj][0] * C_L2E8) * invl0;
            v0.y = ex2(sa[nj][1] * C_L2E8) * invl0;
            v1.x = ex2(sa[nj][2] * C_L2E8) * invl1;
            v1.y = ex2(sa[nj][3] * C_L2E8) * invl1;
            *(float2*)&prow[(size_t)(s0 + r0 + lr) * S + t] = v0;
            *(float2*)&prow[(size_t)(s0 + r0 + 8 + lr) * S + t] = v1;
        }
    }
}

// ---------------------------------------------------------------------------
// K3: out = ctx @ Wo^T + bo, packed operands, 128x64 tiles, 3-stage ring
// ---------------------------------------------------------------------------
#define OUT_STAGE 6144                      // 4096 A + 2048 B words
#define OUT_SMEM  (3 * OUT_STAGE * 4)       // 73728 B

__global__ __launch_bounds__(256, 2) void out_kernel(
    const float* __restrict__ bo, float* __restrict__ out)
{
    extern __shared__ uint32_t sm[];
    const uint32_t sb = (uint32_t)__cvta_generic_to_shared(sm);

    const int tid  = threadIdx.x;
    const int lane = tid & 31;
    const int warp = tid >> 5;
    const int wm   = warp & 3;
    const int wn   = warp >> 2;
    const int mt   = blockIdx.x;
    const int nt   = blockIdx.y;
    const int lr   = lane >> 2;
    const int lc   = lane & 3;

    const uint32_t* gA = g_ctxp + (size_t)(mt * KTILES) * 4096;
    const uint32_t* gB = g_worp + (size_t)(nt * KTILES) * 2048;

    auto issue = [&](int kt, int stg) {
        uint32_t as = sb + (uint32_t)(stg * OUT_STAGE) * 4;
        uint32_t bs = as + 4096 * 4;
        #pragma unroll
        for (int i = 0; i < 4; i++) {
            int linear = tid + i * 256;
            cp16(as + linear * 16, gA + (size_t)kt * 4096 + linear * 4);
        }
        #pragma unroll
        for (int i = 0; i < 2; i++) {
            int linear = tid + i * 256;
            cp16(bs + linear * 16, gB + (size_t)kt * 2048 + linear * 4);
        }
        cp_commit();
    };

    float acc[2][4][4];
    #pragma unroll
    for (int i = 0; i < 2; i++)
        #pragma unroll
        for (int j = 0; j < 4; j++)
            #pragma unroll
            for (int t = 0; t < 4; t++) acc[i][j][t] = 0.f;

    issue(0, 0);
    for (int kt = 0; kt < KTILES; kt++) {
        int cur = kt % 3;
        if (kt + 1 < KTILES) { issue(kt + 1, (kt + 1) % 3); cp_wait<1>(); }
        else                 cp_wait<0>();
        __syncthreads();

        const uint32_t* As = sm + cur * OUT_STAGE;
        const uint32_t* Bs = As + 4096;

        #pragma unroll
        for (int ks8 = 0; ks8 < 4; ks8++) {
            uint32_t af[2][4], bf[4][2];
            #pragma unroll
            for (int mi = 0; mi < 2; mi++) {
                uint4 v = *(const uint4*)&As[((wm * 2 + mi) * 4 + ks8) * 128 + lane * 4];
                af[mi][0] = v.x; af[mi][1] = v.y; af[mi][2] = v.z; af[mi][3] = v.w;
            }
            #pragma unroll
            for (int nj = 0; nj < 4; nj++) {
                uint2 v = *(const uint2*)&Bs[((wn * 4 + nj) * 4 + ks8) * 64 + lane * 2];
                bf[nj][0] = v.x; bf[nj][1] = v.y;
            }
            #pragma unroll
            for (int mi = 0; mi < 2; mi++)
                #pragma unroll
                for (int nj = 0; nj < 4; nj++)
                    mma_tf32(acc[mi][nj], af[mi], bf[nj]);
        }
    }

    #pragma unroll
    for (int mi = 0; mi < 2; mi++) {
        #pragma unroll
        for (int nj = 0; nj < 4; nj++) {
            #pragma unroll
            for (int half = 0; half < 2; half++) {
                int m = mt * 128 + wm * 32 + mi * 16 + lr + half * 8;
                int n = nt * 64 + wn * 32 + nj * 8 + (lc << 1);
                float2 v;
                v.x = acc[mi][nj][half * 2 + 0] + bo[n];
                v.y = acc[mi][nj][half * 2 + 1] + bo[n + 1];
                *(float2*)&out[(size_t)m * D + n] = v;
            }
        }
    }
}

// ---------------------------------------------------------------------------
extern "C" void kernel_launch(void* const* d_in, const int* in_sizes, int n_in,
                              void* d_out, int out_size)
{
    const float* x  = (const float*)d_in[0];
    const float* Wq = (const float*)d_in[1];
    const float* bq = (const float*)d_in[2];
    const float* Wk = (const float*)d_in[3];
    const float* bk = (const float*)d_in[4];
    const float* Wv = (const float*)d_in[5];
    const float* bv = (const float*)d_in[6];
    const float* Wo = (const float*)d_in[7];
    const float* bo = (const float*)d_in[8];

    float* out   = (float*)d_out;
    float* probs = out + OUT_ELEMS;

    static bool attr_done = false;
    if (!attr_done) {
        cudaFuncSetAttribute(qkv_kernel,
                             cudaFuncAttributeMaxDynamicSharedMemorySize, QKV_SMEM);
        cudaFuncSetAttribute(attn_kernel,
                             cudaFuncAttributeMaxDynamicSharedMemorySize, ATTN_SMEM);
        cudaFuncSetAttribute(out_kernel,
                             cudaFuncAttributeMaxDynamicSharedMemorySize, OUT_SMEM);
        attr_done = true;
    }

    repack_kernel<<<(XE + 255) / 256, 256>>>(Wq, Wk, Wv, bq, bk, bv, x, Wo);
    qkv_kernel<<<dim3(M_TOT / 128, NQKV / 128), 256, QKV_SMEM>>>();
    attn_kernel<<<dim3(S / 128, BH), 256, ATTN_SMEM>>>(probs);
    out_kernel<<<dim3(M_TOT / 128, D / 64), 256, OUT_SMEM>>>(bo, out);
}

// round 11
// speedup vs baseline: 3.6342x; 1.0089x over previous
#include <cuda_runtime.h>
#include <cstdint>

// Problem constants
#define H 12
#define D 768
#define DH 64
#define B 8
#define S 1024
#define M_TOT (B * S)            // 8192
#define BH (B * H)               // 96
#define OUT_ELEMS (B * S * D)    // 6291456
#define NQKV (H * 3 * DH)        // 2304
#define XE (M_TOT * D)           // 6291456
#define WOE (D * D)              // 589824
#define KTILES (D / 32)          // 24

// Packed-layout scratch (device globals — allocation-free per harness rules)
__device__ float    g_q[BH * S * DH];          // k-col-paired within 8-groups
__device__ float    g_k[BH * S * DH];          // k-col-paired within 8-groups
__device__ uint32_t g_vp[BH * S * DH];         // B-frag packed per (bh, t-tile32)
__device__ uint32_t g_ctxp[(size_t)M_TOT * D]; // A-frag packed per (mt, kt)
__device__ uint32_t g_xrp[XE];                 // A-frag packed x
__device__ uint32_t g_wcatp[(size_t)D * NQKV]; // B-frag packed Wcat
__device__ uint32_t g_worp[WOE];               // B-frag packed Wo
__device__ float    g_bcat[NQKV];

// ---------------------------------------------------------------------------
__device__ __forceinline__ uint32_t f2tf(float x) {
    uint32_t r;
    asm("cvt.rna.tf32.f32 %0, %1;" : "=r"(r) : "f"(x));
    return r;
}
__device__ __forceinline__ float ex2(float x) {
    float y;
    asm("ex2.approx.ftz.f32 %0, %1;" : "=f"(y) : "f"(x));
    return y;
}
__device__ __forceinline__ void mma_tf32(float c[4], const uint32_t a[4],
                                         const uint32_t b[2]) {
    asm volatile(
        "mma.sync.aligned.m16n8k8.row.col.f32.tf32.tf32.f32 "
        "{%0,%1,%2,%3}, {%4,%5,%6,%7}, {%8,%9}, {%0,%1,%2,%3};\n"
        : "+f"(c[0]), "+f"(c[1]), "+f"(c[2]), "+f"(c[3])
        : "r"(a[0]), "r"(a[1]), "r"(a[2]), "r"(a[3]), "r"(b[0]), "r"(b[1]));
}
__device__ __forceinline__ void cp16(uint32_t saddr, const void* gptr) {
    asm volatile("cp.async.ca.shared.global [%0], [%1], 16;\n"
                 :: "r"(saddr), "l"(gptr));
}
__device__ __forceinline__ void cp_commit() {
    asm volatile("cp.async.commit_group;\n");
}
template <int N> __device__ __forceinline__ void cp_wait() {
    asm volatile("cp.async.wait_group %0;\n" :: "n"(N));
}
__device__ __forceinline__ float red4_sum(float v) {
    v += __shfl_xor_sync(0xffffffffu, v, 1);
    v += __shfl_xor_sync(0xffffffffu, v, 2);
    return v;
}

// ---------------------------------------------------------------------------
// K0: repack into fragment-packed layouts
// ---------------------------------------------------------------------------
__global__ __launch_bounds__(256) void repack_kernel(
    const float* __restrict__ Wq, const float* __restrict__ Wk,
    const float* __restrict__ Wv, const float* __restrict__ bq,
    const float* __restrict__ bk, const float* __restrict__ bv,
    const float* __restrict__ x,  const float* __restrict__ Wo)
{
    int idx = blockIdx.x * 256 + threadIdx.x;

    if (idx < XE) {   // x -> A-pack
        int m = idx / D, k = idx - m * D;
        int mt = m >> 7, r = m & 127, kt = k >> 5, c = k & 31;
        int rb = r >> 4, rr = r & 15, lr = rr & 7, hi = rr >> 3;
        int ks = c >> 3, c8 = c & 7, lc = c8 & 3, chi = c8 >> 2;
        int word = ((rb * 4 + ks) * 32 + lr * 4 + lc) * 4 + hi + 2 * chi;
        g_xrp[(size_t)(mt * KTILES + kt) * 4096 + word] = f2tf(x[idx]);
    }
    if (idx < D * NQKV) {   // Wcat -> B-pack
        int k = idx / NQKV, n = idx - k * NQKV;
        int h = n / 192, rem = n % 192;
        int which = rem >> 6, e = rem & 63;
        const float* wp = (which == 0) ? Wq : (which == 1) ? Wk : Wv;
        uint32_t val = f2tf(wp[((size_t)h * D + k) * DH + e]);
        int nt = n >> 7, n128 = n & 127, kt = k >> 5, c = k & 31;
        int nb = n128 >> 3, lr = n128 & 7;
        int ks = c >> 3, c8 = c & 7, lc = c8 & 3, chi = c8 >> 2;
        int word = ((nb * 4 + ks) * 32 + lr * 4 + lc) * 2 + chi;
        g_wcatp[(size_t)(nt * KTILES + kt) * 4096 + word] = val;
    }
    if (idx < WOE) {   // Wo[n][k] -> B-pack
        int n = idx / D, k = idx - n * D;
        int nt = n >> 6, n64 = n & 63, kt = k >> 5, c = k & 31;
        int nb = n64 >> 3, lr = n64 & 7;
        int ks = c >> 3, c8 = c & 7, lc = c8 & 3, chi = c8 >> 2;
        int word = ((nb * 4 + ks) * 32 + lr * 4 + lc) * 2 + chi;
        g_worp[(size_t)(nt * KTILES + kt) * 2048 + word] = f2tf(Wo[idx]);
    }
    if (idx < NQKV) {
        int h = idx / 192, rem = idx % 192;
        int which = rem >> 6, e = rem & 63;
        const float* bp = (which == 0) ? bq : (which == 1) ? bk : bv;
        g_bcat[idx] = bp[h * DH + e];
    }
}

// ---------------------------------------------------------------------------
// K1: QKV GEMM [8192 x 2304], packed operands, 3-stage ring, one barrier
// ---------------------------------------------------------------------------
#define QKV_STAGE 8192                      // 4096 A + 4096 B words
#define QKV_SMEM  (3 * QKV_STAGE * 4)       // 98304 B

__global__ __launch_bounds__(256, 2) void qkv_kernel()
{
    extern __shared__ uint32_t sm[];
    const uint32_t sb = (uint32_t)__cvta_generic_to_shared(sm);

    const int tid  = threadIdx.x;
    const int lane = tid & 31;
    const int warp = tid >> 5;
    const int wm   = warp & 1;
    const int wn   = warp >> 1;
    const int mt   = blockIdx.x;
    const int nt   = blockIdx.y;
    const int lr   = lane >> 2;
    const int lc   = lane & 3;

    const uint32_t* gA = g_xrp  + (size_t)(mt * KTILES) * 4096;
    const uint32_t* gB = g_wcatp + (size_t)(nt * KTILES) * 4096;

    auto issue = [&](int kt, int stg) {
        uint32_t as = sb + (uint32_t)(stg * QKV_STAGE) * 4;
        uint32_t bs = as + 4096 * 4;
        #pragma unroll
        for (int i = 0; i < 4; i++) {
            int linear = tid + i * 256;
            cp16(as + linear * 16, gA + (size_t)kt * 4096 + linear * 4);
            cp16(bs + linear * 16, gB + (size_t)kt * 4096 + linear * 4);
        }
        cp_commit();
    };

    float acc[4][4][4];
    #pragma unroll
    for (int i = 0; i < 4; i++)
        #pragma unroll
        for (int j = 0; j < 4; j++)
            #pragma unroll
            for (int t = 0; t < 4; t++) acc[i][j][t] = 0.f;

    issue(0, 0);
    for (int kt = 0; kt < KTILES; kt++) {
        int cur = kt % 3;
        if (kt + 1 < KTILES) { issue(kt + 1, (kt + 1) % 3); cp_wait<1>(); }
        else                 cp_wait<0>();
        __syncthreads();

        const uint32_t* As = sm + cur * QKV_STAGE;
        const uint32_t* Bs = As + 4096;

        #pragma unroll
        for (int ks8 = 0; ks8 < 4; ks8++) {
            uint32_t af[4][4], bf[4][2];
            #pragma unroll
            for (int mi = 0; mi < 4; mi++) {
                uint4 v = *(const uint4*)&As[((wm * 4 + mi) * 4 + ks8) * 128 + lane * 4];
                af[mi][0] = v.x; af[mi][1] = v.y; af[mi][2] = v.z; af[mi][3] = v.w;
            }
            #pragma unroll
            for (int nj = 0; nj < 4; nj++) {
                uint2 v = *(const uint2*)&Bs[((wn * 4 + nj) * 4 + ks8) * 64 + lane * 2];
                bf[nj][0] = v.x; bf[nj][1] = v.y;
            }
            #pragma unroll
            for (int mi = 0; mi < 4; mi++)
                #pragma unroll
                for (int nj = 0; nj < 4; nj++)
                    mma_tf32(acc[mi][nj], af[mi], bf[nj]);
        }
    }

    // epilogue: q/k with k-col pairing perm; v fragment-packed
    #pragma unroll
    for (int mi = 0; mi < 4; mi++) {
        #pragma unroll
        for (int nj = 0; nj < 4; nj++) {
            #pragma unroll
            for (int t = 0; t < 4; t++) {
                int r  = mt * 128 + wm * 64 + mi * 16 + lr + ((t >= 2) ? 8 : 0);
                int gn = nt * 128 + wn * 32 + nj * 8 + (lc << 1) + (t & 1);
                int b = r >> 10, s = r & 1023;
                int h = gn / 192, rem = gn % 192;
                int which = rem >> 6, e = rem & 63;
                uint32_t val = f2tf(acc[mi][nj][t] + g_bcat[gn]);
                if (which < 2) {
                    int e8 = e & 7;
                    int ep = (e & ~7) | (((e8 & 3) << 1) | (e8 >> 2));
                    float* dst = (which == 0) ? g_q : g_k;
                    dst[(((size_t)b * H + h) * S + s) * DH + ep] =
                        __uint_as_float(val);
                } else {
                    int tt = s >> 5, t32 = s & 31;
                    int ks = t32 >> 3, t8 = t32 & 7;
                    int lct = t8 & 3, chit = t8 >> 2;
                    int nb = e >> 3, lre = e & 7;
                    int word = ((nb * 4 + ks) * 32 + lre * 4 + lct) * 2 + chit;
                    g_vp[((size_t)(b * H + h) * 32 + tt) * 2048 + word] = val;
                }
            }
        }
    }
}

// ---------------------------------------------------------------------------
// K2: fused attention, max-free softmax, P via register shuffles (no smem P)
// grid (S/128, BH), 256 thr, 8 warps; warp w owns rows w*16..w*16+15.
// ---------------------------------------------------------------------------
#define NT 32                               // S / 32
#define K_WORDS (32 * 72)                   // 2304 (stride-72 rows)
#define KV_STAGE (K_WORDS + 2048)           // 4352
#define ATTN_SMEM (4 * KV_STAGE * 4)        // 69632 B (Q staging 9216w aliased)
#define C_L2E8 0.18033688f                  // 0.125 * log2(e)

__global__ __launch_bounds__(256, 2) void attn_kernel(float* __restrict__ probs)
{
    extern __shared__ uint32_t sm[];
    const uint32_t sb = (uint32_t)__cvta_generic_to_shared(sm);

    const int tid  = threadIdx.x;
    const int lane = tid & 31;
    const int warp = tid >> 5;
    const int lr   = lane >> 2;
    const int lc   = lane & 3;
    const int s0   = blockIdx.x * 128;
    const int bh   = blockIdx.y;
    const int r0   = warp * 16;

    const float* qp = g_q + (size_t)bh * S * DH;
    const float* kp = g_k + (size_t)bh * S * DH;
    const uint32_t* vp = g_vp + (size_t)bh * 32 * 2048;

    // stage Q (stride 72, aliased over KV stages), hoist frags to registers
    #pragma unroll
    for (int i = 0; i < 8; i++) {
        int linear = tid + i * 256;
        int r = linear >> 4, c4 = (linear & 15) << 2;
        float4 v = *(const float4*)&qp[(size_t)(s0 + r) * DH + c4];
        *(float4*)&sm[r * 72 + c4] = v;
    }
    __syncthreads();
    uint32_t qf[8][4];
    #pragma unroll
    for (int ks8 = 0; ks8 < 8; ks8++) {
        uint2 qa = *(const uint2*)&sm[(r0 + lr) * 72 + ks8 * 8 + 2 * lc];
        uint2 qb = *(const uint2*)&sm[(r0 + 8 + lr) * 72 + ks8 * 8 + 2 * lc];
        qf[ks8][0] = qa.x; qf[ks8][1] = qb.x; qf[ks8][2] = qa.y; qf[ks8][3] = qb.y;
    }
    __syncthreads();

    auto issueKV = [&](int it, int stg) {
        uint32_t kb = sb + (uint32_t)(stg * KV_STAGE) * 4;
        uint32_t vb = kb + (uint32_t)K_WORDS * 4;
        #pragma unroll
        for (int i = 0; i < 2; i++) {
            int linear = tid + i * 256;
            int n = linear >> 4, k4 = (linear & 15) << 2;
            cp16(kb + (uint32_t)(n * 72 + k4) * 4,
                 &kp[(size_t)(it * 32 + n) * DH + k4]);
            cp16(vb + (uint32_t)linear * 16, vp + (size_t)it * 2048 + linear * 4);
        }
        cp_commit();
    };
    auto issueK = [&](int it, int stg) {
        uint32_t kb = sb + (uint32_t)(stg * KV_STAGE) * 4;
        #pragma unroll
        for (int i = 0; i < 2; i++) {
            int linear = tid + i * 256;
            int n = linear >> 4, k4 = (linear & 15) << 2;
            cp16(kb + (uint32_t)(n * 72 + k4) * 4,
                 &kp[(size_t)(it * 32 + n) * DH + k4]);
        }
        cp_commit();
    };

    const int src0 = (lane & ~3) | (lc >> 1);   // quad-local shuffle sources
    const int src2 = src0 + 2;
    const bool odd = lc & 1;

    float l0 = 0.f, l1 = 0.f;               // per-thread partials
    float co[8][4];
    #pragma unroll
    for (int nj = 0; nj < 8; nj++)
        #pragma unroll
        for (int t = 0; t < 4; t++) co[nj][t] = 0.f;

    // ---------------- Pass A ----------------
    issueKV(0, 0); issueKV(1, 1);
    for (int it = 0; it < NT; it++) {
        int cur = it & 3;
        if (it + 2 < NT)      { issueKV(it + 2, (it + 2) & 3); cp_wait<2>(); }
        else if (it + 1 < NT) cp_wait<1>();
        else                  cp_wait<0>();
        __syncthreads();

        const uint32_t* KT_ = sm + cur * KV_STAGE;
        const uint32_t* VS_ = KT_ + K_WORDS;

        float sa[4][4];
        #pragma unroll
        for (int nj = 0; nj < 4; nj++)
            #pragma unroll
            for (int t = 0; t < 4; t++) sa[nj][t] = 0.f;

        #pragma unroll
        for (int ks8 = 0; ks8 < 8; ks8++) {
            #pragma unroll
            for (int nj = 0; nj < 4; nj++) {
                uint2 kk = *(const uint2*)&KT_[(nj * 8 + lr) * 72 + ks8 * 8 + 2 * lc];
                uint32_t bf[2] = {kk.x, kk.y};
                mma_tf32(sa[nj], qf[ks8], bf);
            }
        }

        // max-free softmax: p = exp2(s * C); accumulate per-thread l; tf32 bits
        uint32_t su[4][4];
        #pragma unroll
        for (int nj = 0; nj < 4; nj++) {
            sa[nj][0] = ex2(sa[nj][0] * C_L2E8); l0 += sa[nj][0];
            sa[nj][1] = ex2(sa[nj][1] * C_L2E8); l0 += sa[nj][1];
            sa[nj][2] = ex2(sa[nj][2] * C_L2E8); l1 += sa[nj][2];
            sa[nj][3] = ex2(sa[nj][3] * C_L2E8); l1 += sa[nj][3];
            su[nj][0] = f2tf(sa[nj][0]); su[nj][1] = f2tf(sa[nj][1]);
            su[nj][2] = f2tf(sa[nj][2]); su[nj][3] = f2tf(sa[nj][3]);
        }

        // PV: A-frags built by quad-local shuffles (C-frag -> A-frag permute)
        #pragma unroll
        for (int kk = 0; kk < 4; kk++) {
            uint32_t v0 = __shfl_sync(0xffffffffu, su[kk][0], src0);
            uint32_t v1 = __shfl_sync(0xffffffffu, su[kk][1], src0);
            uint32_t u0 = __shfl_sync(0xffffffffu, su[kk][2], src0);
            uint32_t u1 = __shfl_sync(0xffffffffu, su[kk][3], src0);
            uint32_t w0 = __shfl_sync(0xffffffffu, su[kk][0], src2);
            uint32_t w1 = __shfl_sync(0xffffffffu, su[kk][1], src2);
            uint32_t x0 = __shfl_sync(0xffffffffu, su[kk][2], src2);
            uint32_t x1 = __shfl_sync(0xffffffffu, su[kk][3], src2);
            uint32_t af[4];
            af[0] = odd ? v1 : v0;
            af[1] = odd ? u1 : u0;
            af[2] = odd ? w1 : w0;
            af[3] = odd ? x1 : x0;
            #pragma unroll
            for (int nj8 = 0; nj8 < 8; nj8++) {
                uint2 vv = *(const uint2*)&VS_[((nj8 * 4 + kk) * 32 + lane) * 2];
                uint32_t bf[2] = {vv.x, vv.y};
                mma_tf32(co[nj8], af, bf);
            }
        }
    }

    l0 = red4_sum(l0); l1 = red4_sum(l1);
    const float invl0 = 1.f / l0, invl1 = 1.f / l1;
    const int b = bh / H, h = bh % H;
    const int mt = b * 8 + (s0 >> 7);

    // write ctx fragment-packed for out_kernel
    #pragma unroll
    for (int nj = 0; nj < 8; nj++) {
        int kt = h * 2 + (nj >> 2);
        int ks = nj & 3;
        size_t tbase = ((size_t)mt * KTILES + kt) * 4096;
        #pragma unroll
        for (int t = 0; t < 4; t++) {
            int hi = t >> 1, bb = t & 1;
            int c8 = 2 * lc + bb;
            int lcb = c8 & 3, chi = c8 >> 2;
            int word = ((warp * 4 + ks) * 32 + lr * 4 + lcb) * 4 + hi + 2 * chi;
            float inv = hi ? invl1 : invl0;
            g_ctxp[tbase + word] = f2tf(co[nj][t] * inv);
        }
    }

    // ---------------- Pass B: recompute scores, write probs ----------------
    float* prow = probs + (size_t)bh * S * S;
    issueK(0, 0); issueK(1, 1);
    for (int it = 0; it < NT; it++) {
        int cur = it & 3;
        if (it + 2 < NT)      { issueK(it + 2, (it + 2) & 3); cp_wait<2>(); }
        else if (it + 1 < NT) cp_wait<1>();
        else                  cp_wait<0>();
        __syncthreads();

        const uint32_t* KT_ = sm + cur * KV_STAGE;

        float sa[4][4];
        #pragma unroll
        for (int nj = 0; nj < 4; nj++)
            #pragma unroll
            for (int t = 0; t < 4; t++) sa[nj][t] = 0.f;

        #pragma unroll
        for (int ks8 = 0; ks8 < 8; ks8++) {
            #pragma unroll
            for (int nj = 0; nj < 4; nj++) {
                uint2 kk = *(const uint2*)&KT_[(nj * 8 + lr) * 72 + ks8 * 8 + 2 * lc];
                uint32_t bf[2] = {kk.x, kk.y};
                mma_tf32(sa[nj], qf[ks8], bf);
            }
        }

        #pragma unroll
        for (int nj = 0; nj < 4; nj++) {
            int t = it * 32 + nj * 8 + 2 * lc;
            float2 v0, v1;
            v0.x = ex2(sa[nj][0] * C_L2E8) * invl0;
            v0.y = ex2(sa[nj][1] * C_L2E8) * invl0;
            v1.x = ex2(sa[nj][2] * C_L2E8) * invl1;
            v1.y = ex2(sa[nj][3] * C_L2E8) * invl1;
            *(float2*)&prow[(size_t)(s0 + r0 + lr) * S + t] = v0;
            *(float2*)&prow[(size_t)(s0 + r0 + 8 + lr) * S + t] = v1;
        }
    }
}

// ---------------------------------------------------------------------------
// K3: out = ctx @ Wo^T + bo, packed operands, 128x64 tiles, 3-stage ring
// 3 CTAs/SM for latency hiding
// ---------------------------------------------------------------------------
#define OUT_STAGE 6144                      // 4096 A + 2048 B words
#define OUT_SMEM  (3 * OUT_STAGE * 4)       // 73728 B

__global__ __launch_bounds__(256, 3) void out_kernel(
    const float* __restrict__ bo, float* __restrict__ out)
{
    extern __shared__ uint32_t sm[];
    const uint32_t sb = (uint32_t)__cvta_generic_to_shared(sm);

    const int tid  = threadIdx.x;
    const int lane = tid & 31;
    const int warp = tid >> 5;
    const int wm   = warp & 3;
    const int wn   = warp >> 2;
    const int mt   = blockIdx.x;
    const int nt   = blockIdx.y;
    const int lr   = lane >> 2;
    const int lc   = lane & 3;

    const uint32_t* gA = g_ctxp + (size_t)(mt * KTILES) * 4096;
    const uint32_t* gB = g_worp + (size_t)(nt * KTILES) * 2048;

    auto issue = [&](int kt, int stg) {
        uint32_t as = sb + (uint32_t)(stg * OUT_STAGE) * 4;
        uint32_t bs = as + 4096 * 4;
        #pragma unroll
        for (int i = 0; i < 4; i++) {
            int linear = tid + i * 256;
            cp16(as + linear * 16, gA + (size_t)kt * 4096 + linear * 4);
        }
        #pragma unroll
        for (int i = 0; i < 2; i++) {
            int linear = tid + i * 256;
            cp16(bs + linear * 16, gB + (size_t)kt * 2048 + linear * 4);
        }
        cp_commit();
    };

    float acc[2][4][4];
    #pragma unroll
    for (int i = 0; i < 2; i++)
        #pragma unroll
        for (int j = 0; j < 4; j++)
            #pragma unroll
            for (int t = 0; t < 4; t++) acc[i][j][t] = 0.f;

    issue(0, 0);
    for (int kt = 0; kt < KTILES; kt++) {
        int cur = kt % 3;
        if (kt + 1 < KTILES) { issue(kt + 1, (kt + 1) % 3); cp_wait<1>(); }
        else                 cp_wait<0>();
        __syncthreads();

        const uint32_t* As = sm + cur * OUT_STAGE;
        const uint32_t* Bs = As + 4096;

        #pragma unroll
        for (int ks8 = 0; ks8 < 4; ks8++) {
            uint32_t af[2][4], bf[4][2];
            #pragma unroll
            for (int mi = 0; mi < 2; mi++) {
                uint4 v = *(const uint4*)&As[((wm * 2 + mi) * 4 + ks8) * 128 + lane * 4];
                af[mi][0] = v.x; af[mi][1] = v.y; af[mi][2] = v.z; af[mi][3] = v.w;
            }
            #pragma unroll
            for (int nj = 0; nj < 4; nj++) {
                uint2 v = *(const uint2*)&Bs[((wn * 4 + nj) * 4 + ks8) * 64 + lane * 2];
                bf[nj][0] = v.x; bf[nj][1] = v.y;
            }
            #pragma unroll
            for (int mi = 0; mi < 2; mi++)
                #pragma unroll
                for (int nj = 0; nj < 4; nj++)
                    mma_tf32(acc[mi][nj], af[mi], bf[nj]);
        }
    }

    #pragma unroll
    for (int mi = 0; mi < 2; mi++) {
        #pragma unroll
        for (int nj = 0; nj < 4; nj++) {
            #pragma unroll
            for (int half = 0; half < 2; half++) {
                int m = mt * 128 + wm * 32 + mi * 16 + lr + half * 8;
                int n = nt * 64 + wn * 32 + nj * 8 + (lc << 1);
                float2 v;
                v.x = acc[mi][nj][half * 2 + 0] + bo[n];
                v.y = acc[mi][nj][half * 2 + 1] + bo[n + 1];
                *(float2*)&out[(size_t)m * D + n] = v;
            }
        }
    }
}

// ---------------------------------------------------------------------------
extern "C" void kernel_launch(void* const* d_in, const int* in_sizes, int n_in,
                              void* d_out, int out_size)
{
    const float* x  = (const float*)d_in[0];
    const float* Wq = (const float*)d_in[1];
    const float* bq = (const float*)d_in[2];
    const float* Wk = (const float*)d_in[3];
    const float* bk = (const float*)d_in[4];
    const float* Wv = (const float*)d_in[5];
    const float* bv = (const float*)d_in[6];
    const float* Wo = (const float*)d_in[7];
    const float* bo = (const float*)d_in[8];

    float* out   = (float*)d_out;
    float* probs = out + OUT_ELEMS;

    static bool attr_done = false;
    if (!attr_done) {
        cudaFuncSetAttribute(qkv_kernel,
                             cudaFuncAttributeMaxDynamicSharedMemorySize, QKV_SMEM);
        cudaFuncSetAttribute(attn_kernel,
                             cudaFuncAttributeMaxDynamicSharedMemorySize, ATTN_SMEM);
        cudaFuncSetAttribute(out_kernel,
                             cudaFuncAttributeMaxDynamicSharedMemorySize, OUT_SMEM);
        attr_done = true;
    }

    repack_kernel<<<(XE + 255) / 256, 256>>>(Wq, Wk, Wv, bq, bk, bv, x, Wo);
    qkv_kernel<<<dim3(M_TOT / 128, NQKV / 128), 256, QKV_SMEM>>>();
    attn_kernel<<<dim3(S / 128, BH), 256, ATTN_SMEM>>>(probs);
    out_kernel<<<dim3(M_TOT / 128, D / 64), 256, OUT_SMEM>>>(bo, out);
}

// round 12
// speedup vs baseline: 3.6935x; 1.0163x over previous
#include <cuda_runtime.h>
#include <cstdint>

// Problem constants
#define H 12
#define D 768
#define DH 64
#define B 8
#define S 1024
#define M_TOT (B * S)            // 8192
#define BH (B * H)               // 96
#define OUT_ELEMS (B * S * D)    // 6291456
#define NQKV (H * 3 * DH)        // 2304
#define XE (M_TOT * D)           // 6291456
#define WOE (D * D)              // 589824
#define KTILES (D / 32)          // 24

// Packed-layout scratch (device globals — allocation-free per harness rules)
__device__ float    g_q[BH * S * DH];          // k-col-paired within 8-groups
__device__ float    g_k[BH * S * DH];          // k-col-paired within 8-groups
__device__ uint32_t g_vp[BH * S * DH];         // B-frag packed per (bh, t-tile32)
__device__ uint32_t g_ctxp[(size_t)M_TOT * D]; // A-frag packed per (mt, kt)
__device__ uint32_t g_xrp[XE];                 // A-frag packed x
__device__ uint32_t g_wcatp[(size_t)D * NQKV]; // B-frag packed Wcat
__device__ uint32_t g_worp[WOE];               // B-frag packed Wo
__device__ float    g_bcat[NQKV];

// ---------------------------------------------------------------------------
__device__ __forceinline__ uint32_t f2tf(float x) {
    uint32_t r;
    asm("cvt.rna.tf32.f32 %0, %1;" : "=r"(r) : "f"(x));
    return r;
}
__device__ __forceinline__ float ex2(float x) {
    float y;
    asm("ex2.approx.ftz.f32 %0, %1;" : "=f"(y) : "f"(x));
    return y;
}
__device__ __forceinline__ void mma_tf32(float c[4], const uint32_t a[4],
                                         const uint32_t b[2]) {
    asm volatile(
        "mma.sync.aligned.m16n8k8.row.col.f32.tf32.tf32.f32 "
        "{%0,%1,%2,%3}, {%4,%5,%6,%7}, {%8,%9}, {%0,%1,%2,%3};\n"
        : "+f"(c[0]), "+f"(c[1]), "+f"(c[2]), "+f"(c[3])
        : "r"(a[0]), "r"(a[1]), "r"(a[2]), "r"(a[3]), "r"(b[0]), "r"(b[1]));
}
__device__ __forceinline__ void cp16(uint32_t saddr, const void* gptr) {
    asm volatile("cp.async.ca.shared.global [%0], [%1], 16;\n"
                 :: "r"(saddr), "l"(gptr));
}
__device__ __forceinline__ void cp_commit() {
    asm volatile("cp.async.commit_group;\n");
}
template <int N> __device__ __forceinline__ void cp_wait() {
    asm volatile("cp.async.wait_group %0;\n" :: "n"(N));
}
__device__ __forceinline__ float red4_sum(float v) {
    v += __shfl_xor_sync(0xffffffffu, v, 1);
    v += __shfl_xor_sync(0xffffffffu, v, 2);
    return v;
}

// ---------------------------------------------------------------------------
// K0: repack into fragment-packed layouts
// ---------------------------------------------------------------------------
__global__ __launch_bounds__(256) void repack_kernel(
    const float* __restrict__ Wq, const float* __restrict__ Wk,
    const float* __restrict__ Wv, const float* __restrict__ bq,
    const float* __restrict__ bk, const float* __restrict__ bv,
    const float* __restrict__ x,  const float* __restrict__ Wo)
{
    int idx = blockIdx.x * 256 + threadIdx.x;

    if (idx < XE) {   // x -> A-pack
        int m = idx / D, k = idx - m * D;
        int mt = m >> 7, r = m & 127, kt = k >> 5, c = k & 31;
        int rb = r >> 4, rr = r & 15, lr = rr & 7, hi = rr >> 3;
        int ks = c >> 3, c8 = c & 7, lc = c8 & 3, chi = c8 >> 2;
        int word = ((rb * 4 + ks) * 32 + lr * 4 + lc) * 4 + hi + 2 * chi;
        g_xrp[(size_t)(mt * KTILES + kt) * 4096 + word] = f2tf(x[idx]);
    }
    if (idx < D * NQKV) {   // Wcat -> B-pack
        int k = idx / NQKV, n = idx - k * NQKV;
        int h = n / 192, rem = n % 192;
        int which = rem >> 6, e = rem & 63;
        const float* wp = (which == 0) ? Wq : (which == 1) ? Wk : Wv;
        uint32_t val = f2tf(wp[((size_t)h * D + k) * DH + e]);
        int nt = n >> 7, n128 = n & 127, kt = k >> 5, c = k & 31;
        int nb = n128 >> 3, lr = n128 & 7;
        int ks = c >> 3, c8 = c & 7, lc = c8 & 3, chi = c8 >> 2;
        int word = ((nb * 4 + ks) * 32 + lr * 4 + lc) * 2 + chi;
        g_wcatp[(size_t)(nt * KTILES + kt) * 4096 + word] = val;
    }
    if (idx < WOE) {   // Wo[n][k] -> B-pack (64-wide n-tiles)
        int n = idx / D, k = idx - n * D;
        int nt = n >> 6, n64 = n & 63, kt = k >> 5, c = k & 31;
        int nb = n64 >> 3, lr = n64 & 7;
        int ks = c >> 3, c8 = c & 7, lc = c8 & 3, chi = c8 >> 2;
        int word = ((nb * 4 + ks) * 32 + lr * 4 + lc) * 2 + chi;
        g_worp[(size_t)(nt * KTILES + kt) * 2048 + word] = f2tf(Wo[idx]);
    }
    if (idx < NQKV) {
        int h = idx / 192, rem = idx % 192;
        int which = rem >> 6, e = rem & 63;
        const float* bp = (which == 0) ? bq : (which == 1) ? bk : bv;
        g_bcat[idx] = bp[h * DH + e];
    }
}

// ---------------------------------------------------------------------------
// K1: QKV GEMM [8192 x 2304], packed operands, 3-stage ring, one barrier
// ---------------------------------------------------------------------------
#define QKV_STAGE 8192                      // 4096 A + 4096 B words
#define QKV_SMEM  (3 * QKV_STAGE * 4)       // 98304 B

__global__ __launch_bounds__(256, 2) void qkv_kernel()
{
    extern __shared__ uint32_t sm[];
    const uint32_t sb = (uint32_t)__cvta_generic_to_shared(sm);

    const int tid  = threadIdx.x;
    const int lane = tid & 31;
    const int warp = tid >> 5;
    const int wm   = warp & 1;
    const int wn   = warp >> 1;
    const int mt   = blockIdx.x;
    const int nt   = blockIdx.y;
    const int lr   = lane >> 2;
    const int lc   = lane & 3;

    const uint32_t* gA = g_xrp  + (size_t)(mt * KTILES) * 4096;
    const uint32_t* gB = g_wcatp + (size_t)(nt * KTILES) * 4096;

    auto issue = [&](int kt, int stg) {
        uint32_t as = sb + (uint32_t)(stg * QKV_STAGE) * 4;
        uint32_t bs = as + 4096 * 4;
        #pragma unroll
        for (int i = 0; i < 4; i++) {
            int linear = tid + i * 256;
            cp16(as + linear * 16, gA + (size_t)kt * 4096 + linear * 4);
            cp16(bs + linear * 16, gB + (size_t)kt * 4096 + linear * 4);
        }
        cp_commit();
    };

    float acc[4][4][4];
    #pragma unroll
    for (int i = 0; i < 4; i++)
        #pragma unroll
        for (int j = 0; j < 4; j++)
            #pragma unroll
            for (int t = 0; t < 4; t++) acc[i][j][t] = 0.f;

    issue(0, 0);
    for (int kt = 0; kt < KTILES; kt++) {
        int cur = kt % 3;
        if (kt + 1 < KTILES) { issue(kt + 1, (kt + 1) % 3); cp_wait<1>(); }
        else                 cp_wait<0>();
        __syncthreads();

        const uint32_t* As = sm + cur * QKV_STAGE;
        const uint32_t* Bs = As + 4096;

        #pragma unroll
        for (int ks8 = 0; ks8 < 4; ks8++) {
            uint32_t af[4][4], bf[4][2];
            #pragma unroll
            for (int mi = 0; mi < 4; mi++) {
                uint4 v = *(const uint4*)&As[((wm * 4 + mi) * 4 + ks8) * 128 + lane * 4];
                af[mi][0] = v.x; af[mi][1] = v.y; af[mi][2] = v.z; af[mi][3] = v.w;
            }
            #pragma unroll
            for (int nj = 0; nj < 4; nj++) {
                uint2 v = *(const uint2*)&Bs[((wn * 4 + nj) * 4 + ks8) * 64 + lane * 2];
                bf[nj][0] = v.x; bf[nj][1] = v.y;
            }
            #pragma unroll
            for (int mi = 0; mi < 4; mi++)
                #pragma unroll
                for (int nj = 0; nj < 4; nj++)
                    mma_tf32(acc[mi][nj], af[mi], bf[nj]);
        }
    }

    // epilogue: q/k with k-col pairing perm; v fragment-packed
    #pragma unroll
    for (int mi = 0; mi < 4; mi++) {
        #pragma unroll
        for (int nj = 0; nj < 4; nj++) {
            #pragma unroll
            for (int t = 0; t < 4; t++) {
                int r  = mt * 128 + wm * 64 + mi * 16 + lr + ((t >= 2) ? 8 : 0);
                int gn = nt * 128 + wn * 32 + nj * 8 + (lc << 1) + (t & 1);
                int b = r >> 10, s = r & 1023;
                int h = gn / 192, rem = gn % 192;
                int which = rem >> 6, e = rem & 63;
                uint32_t val = f2tf(acc[mi][nj][t] + g_bcat[gn]);
                if (which < 2) {
                    int e8 = e & 7;
                    int ep = (e & ~7) | (((e8 & 3) << 1) | (e8 >> 2));
                    float* dst = (which == 0) ? g_q : g_k;
                    dst[(((size_t)b * H + h) * S + s) * DH + ep] =
                        __uint_as_float(val);
                } else {
                    int tt = s >> 5, t32 = s & 31;
                    int ks = t32 >> 3, t8 = t32 & 7;
                    int lct = t8 & 3, chit = t8 >> 2;
                    int nb = e >> 3, lre = e & 7;
                    int word = ((nb * 4 + ks) * 32 + lre * 4 + lct) * 2 + chit;
                    g_vp[((size_t)(b * H + h) * 32 + tt) * 2048 + word] = val;
                }
            }
        }
    }
}

// ---------------------------------------------------------------------------
// K2: fused attention, max-free softmax, P via register shuffles.
// Paired-tile ring: 6 stages (3 pair-stages), ONE barrier per TWO tiles.
// grid (S/128, BH), 256 thr, 8 warps; warp w owns rows w*16..w*16+15.
// ---------------------------------------------------------------------------
#define NT 32                               // S / 32
#define NPAIR 16
#define K_WORDS (32 * 72)                   // 2304 (stride-72 rows)
#define KV_STAGE (K_WORDS + 2048)           // 4352
#define ATTN_SMEM (6 * KV_STAGE * 4)        // 104448 B (Q staging aliased)
#define C_L2E8 0.18033688f                  // 0.125 * log2(e)

__global__ __launch_bounds__(256, 2) void attn_kernel(float* __restrict__ probs)
{
    extern __shared__ uint32_t sm[];
    const uint32_t sb = (uint32_t)__cvta_generic_to_shared(sm);

    const int tid  = threadIdx.x;
    const int lane = tid & 31;
    const int warp = tid >> 5;
    const int lr   = lane >> 2;
    const int lc   = lane & 3;
    const int s0   = blockIdx.x * 128;
    const int bh   = blockIdx.y;
    const int r0   = warp * 16;

    const float* qp = g_q + (size_t)bh * S * DH;
    const float* kp = g_k + (size_t)bh * S * DH;
    const uint32_t* vp = g_vp + (size_t)bh * 32 * 2048;

    // stage Q (stride 72, aliased over KV stages), hoist frags to registers
    #pragma unroll
    for (int i = 0; i < 8; i++) {
        int linear = tid + i * 256;
        int r = linear >> 4, c4 = (linear & 15) << 2;
        float4 v = *(const float4*)&qp[(size_t)(s0 + r) * DH + c4];
        *(float4*)&sm[r * 72 + c4] = v;
    }
    __syncthreads();
    uint32_t qf[8][4];
    #pragma unroll
    for (int ks8 = 0; ks8 < 8; ks8++) {
        uint2 qa = *(const uint2*)&sm[(r0 + lr) * 72 + ks8 * 8 + 2 * lc];
        uint2 qb = *(const uint2*)&sm[(r0 + 8 + lr) * 72 + ks8 * 8 + 2 * lc];
        qf[ks8][0] = qa.x; qf[ks8][1] = qb.x; qf[ks8][2] = qa.y; qf[ks8][3] = qb.y;
    }
    __syncthreads();

    // no-commit issuers (caller commits per pair)
    auto issueKVx = [&](int it, int slot) {
        uint32_t kb = sb + (uint32_t)(slot * KV_STAGE) * 4;
        uint32_t vb = kb + (uint32_t)K_WORDS * 4;
        #pragma unroll
        for (int i = 0; i < 2; i++) {
            int linear = tid + i * 256;
            int n = linear >> 4, k4 = (linear & 15) << 2;
            cp16(kb + (uint32_t)(n * 72 + k4) * 4,
                 &kp[(size_t)(it * 32 + n) * DH + k4]);
            cp16(vb + (uint32_t)linear * 16, vp + (size_t)it * 2048 + linear * 4);
        }
    };
    auto issueKx = [&](int it, int slot) {
        uint32_t kb = sb + (uint32_t)(slot * KV_STAGE) * 4;
        #pragma unroll
        for (int i = 0; i < 2; i++) {
            int linear = tid + i * 256;
            int n = linear >> 4, k4 = (linear & 15) << 2;
            cp16(kb + (uint32_t)(n * 72 + k4) * 4,
                 &kp[(size_t)(it * 32 + n) * DH + k4]);
        }
    };

    const int src0 = (lane & ~3) | (lc >> 1);   // quad-local shuffle sources
    const int src2 = src0 + 2;
    const bool odd = lc & 1;

    float l0 = 0.f, l1 = 0.f;               // per-thread partials
    float co[8][4];
    #pragma unroll
    for (int nj = 0; nj < 8; nj++)
        #pragma unroll
        for (int t = 0; t < 4; t++) co[nj][t] = 0.f;

    auto processA = [&](int slot) {
        const uint32_t* KT_ = sm + slot * KV_STAGE;
        const uint32_t* VS_ = KT_ + K_WORDS;

        float sa[4][4];
        #pragma unroll
        for (int nj = 0; nj < 4; nj++)
            #pragma unroll
            for (int t = 0; t < 4; t++) sa[nj][t] = 0.f;

        #pragma unroll
        for (int ks8 = 0; ks8 < 8; ks8++) {
            #pragma unroll
            for (int nj = 0; nj < 4; nj++) {
                uint2 kk = *(const uint2*)&KT_[(nj * 8 + lr) * 72 + ks8 * 8 + 2 * lc];
                uint32_t bf[2] = {kk.x, kk.y};
                mma_tf32(sa[nj], qf[ks8], bf);
            }
        }

        uint32_t su[4][4];
        #pragma unroll
        for (int nj = 0; nj < 4; nj++) {
            sa[nj][0] = ex2(sa[nj][0] * C_L2E8); l0 += sa[nj][0];
            sa[nj][1] = ex2(sa[nj][1] * C_L2E8); l0 += sa[nj][1];
            sa[nj][2] = ex2(sa[nj][2] * C_L2E8); l1 += sa[nj][2];
            sa[nj][3] = ex2(sa[nj][3] * C_L2E8); l1 += sa[nj][3];
            su[nj][0] = f2tf(sa[nj][0]); su[nj][1] = f2tf(sa[nj][1]);
            su[nj][2] = f2tf(sa[nj][2]); su[nj][3] = f2tf(sa[nj][3]);
        }

        #pragma unroll
        for (int kk = 0; kk < 4; kk++) {
            uint32_t v0 = __shfl_sync(0xffffffffu, su[kk][0], src0);
            uint32_t v1 = __shfl_sync(0xffffffffu, su[kk][1], src0);
            uint32_t u0 = __shfl_sync(0xffffffffu, su[kk][2], src0);
            uint32_t u1 = __shfl_sync(0xffffffffu, su[kk][3], src0);
            uint32_t w0 = __shfl_sync(0xffffffffu, su[kk][0], src2);
            uint32_t w1 = __shfl_sync(0xffffffffu, su[kk][1], src2);
            uint32_t x0 = __shfl_sync(0xffffffffu, su[kk][2], src2);
            uint32_t x1 = __shfl_sync(0xffffffffu, su[kk][3], src2);
            uint32_t af[4];
            af[0] = odd ? v1 : v0;
            af[1] = odd ? u1 : u0;
            af[2] = odd ? w1 : w0;
            af[3] = odd ? x1 : x0;
            #pragma unroll
            for (int nj8 = 0; nj8 < 8; nj8++) {
                uint2 vv = *(const uint2*)&VS_[((nj8 * 4 + kk) * 32 + lane) * 2];
                uint32_t bf[2] = {vv.x, vv.y};
                mma_tf32(co[nj8], af, bf);
            }
        }
    };

    // ---------------- Pass A: 16 pairs, one barrier per pair ----------------
    issueKVx(0, 0); issueKVx(1, 1); cp_commit();
    issueKVx(2, 2); issueKVx(3, 3); cp_commit();
    for (int p = 0; p < NPAIR; p++) {
        if (p + 1 < NPAIR) cp_wait<1>(); else cp_wait<0>();
        __syncthreads();
        if (p + 2 < NPAIR) {
            int q = p + 2, qs = (q % 3) * 2;
            issueKVx(2 * q, qs); issueKVx(2 * q + 1, qs + 1); cp_commit();
        }
        int ps = (p % 3) * 2;
        processA(ps);
        processA(ps + 1);
    }

    l0 = red4_sum(l0); l1 = red4_sum(l1);
    const float invl0 = 1.f / l0, invl1 = 1.f / l1;
    const int b = bh / H, h = bh % H;
    const int mt = b * 8 + (s0 >> 7);

    // write ctx fragment-packed for out_kernel
    #pragma unroll
    for (int nj = 0; nj < 8; nj++) {
        int kt = h * 2 + (nj >> 2);
        int ks = nj & 3;
        size_t tbase = ((size_t)mt * KTILES + kt) * 4096;
        #pragma unroll
        for (int t = 0; t < 4; t++) {
            int hi = t >> 1, bb = t & 1;
            int c8 = 2 * lc + bb;
            int lcb = c8 & 3, chi = c8 >> 2;
            int word = ((warp * 4 + ks) * 32 + lr * 4 + lcb) * 4 + hi + 2 * chi;
            float inv = hi ? invl1 : invl0;
            g_ctxp[tbase + word] = f2tf(co[nj][t] * inv);
        }
    }
    __syncthreads();   // all warps done with pass-A stages before reuse

    // ---------------- Pass B: recompute scores, write probs ----------------
    float* prow = probs + (size_t)bh * S * S;

    auto processB = [&](int it, int slot) {
        const uint32_t* KT_ = sm + slot * KV_STAGE;

        float sa[4][4];
        #pragma unroll
        for (int nj = 0; nj < 4; nj++)
            #pragma unroll
            for (int t = 0; t < 4; t++) sa[nj][t] = 0.f;

        #pragma unroll
        for (int ks8 = 0; ks8 < 8; ks8++) {
            #pragma unroll
            for (int nj = 0; nj < 4; nj++) {
                uint2 kk = *(const uint2*)&KT_[(nj * 8 + lr) * 72 + ks8 * 8 + 2 * lc];
                uint32_t bf[2] = {kk.x, kk.y};
                mma_tf32(sa[nj], qf[ks8], bf);
            }
        }

        #pragma unroll
        for (int nj = 0; nj < 4; nj++) {
            int t = it * 32 + nj * 8 + 2 * lc;
            float2 v0, v1;
            v0.x = ex2(sa[nj][0] * C_L2E8) * invl0;
            v0.y = ex2(sa[nj][1] * C_L2E8) * invl0;
            v1.x = ex2(sa[nj][2] * C_L2E8) * invl1;
            v1.y = ex2(sa[nj][3] * C_L2E8) * invl1;
            *(float2*)&prow[(size_t)(s0 + r0 + lr) * S + t] = v0;
            *(float2*)&prow[(size_t)(s0 + r0 + 8 + lr) * S + t] = v1;
        }
    };

    issueKx(0, 0); issueKx(1, 1); cp_commit();
    issueKx(2, 2); issueKx(3, 3); cp_commit();
    for (int p = 0; p < NPAIR; p++) {
        if (p + 1 < NPAIR) cp_wait<1>(); else cp_wait<0>();
        __syncthreads();
        if (p + 2 < NPAIR) {
            int q = p + 2, qs = (q % 3) * 2;
            issueKx(2 * q, qs); issueKx(2 * q + 1, qs + 1); cp_commit();
        }
        int ps = (p % 3) * 2;
        processB(2 * p, ps);
        processB(2 * p + 1, ps + 1);
    }
}

// ---------------------------------------------------------------------------
// K3: out = ctx @ Wo^T + bo, packed operands, 128x128 tiles (best measured),
// 3-stage ring, one barrier, 2 CTAs/SM (no reg cap)
// ---------------------------------------------------------------------------
#define OUT_STAGE 8192                      // 4096 A + 2*2048 B words
#define OUT_SMEM  (3 * OUT_STAGE * 4)       // 98304 B

__global__ __launch_bounds__(256, 2) void out_kernel(
    const float* __restrict__ bo, float* __restrict__ out)
{
    extern __shared__ uint32_t sm[];
    const uint32_t sb = (uint32_t)__cvta_generic_to_shared(sm);

    const int tid  = threadIdx.x;
    const int lane = tid & 31;
    const int warp = tid >> 5;
    const int wm   = warp & 1;
    const int wn   = warp >> 1;
    const int mt   = blockIdx.x;
    const int nt   = blockIdx.y;              // 128-wide n-tile (0..5)
    const int lr   = lane >> 2;
    const int lc   = lane & 3;

    const uint32_t* gA  = g_ctxp + (size_t)(mt * KTILES) * 4096;
    const uint32_t* gBe = g_worp + (size_t)((2 * nt)     * KTILES) * 2048;
    const uint32_t* gBo = g_worp + (size_t)((2 * nt + 1) * KTILES) * 2048;

    auto issue = [&](int kt, int stg) {
        uint32_t as = sb + (uint32_t)(stg * OUT_STAGE) * 4;
        uint32_t bs = as + 4096 * 4;
        #pragma unroll
        for (int i = 0; i < 4; i++) {
            int linear = tid + i * 256;
            cp16(as + linear * 16, gA + (size_t)kt * 4096 + linear * 4);
        }
        #pragma unroll
        for (int i = 0; i < 2; i++) {
            int linear = tid + i * 256;
            cp16(bs + linear * 16, gBe + (size_t)kt * 2048 + linear * 4);
            cp16(bs + 2048 * 4 + linear * 16, gBo + (size_t)kt * 2048 + linear * 4);
        }
        cp_commit();
    };

    float acc[4][4][4];
    #pragma unroll
    for (int i = 0; i < 4; i++)
        #pragma unroll
        for (int j = 0; j < 4; j++)
            #pragma unroll
            for (int t = 0; t < 4; t++) acc[i][j][t] = 0.f;

    const int half = wn >> 1;                 // which 64-wide B half
    const int nbl  = (wn & 1) * 4;            // local n-block base within half

    issue(0, 0);
    for (int kt = 0; kt < KTILES; kt++) {
        int cur = kt % 3;
        if (kt + 1 < KTILES) { issue(kt + 1, (kt + 1) % 3); cp_wait<1>(); }
        else                 cp_wait<0>();
        __syncthreads();

        const uint32_t* As = sm + cur * OUT_STAGE;
        const uint32_t* Bs = As + 4096 + half * 2048;

        #pragma unroll
        for (int ks8 = 0; ks8 < 4; ks8++) {
            uint32_t af[4][4], bf[4][2];
            #pragma unroll
            for (int mi = 0; mi < 4; mi++) {
                uint4 v = *(const uint4*)&As[((wm * 4 + mi) * 4 + ks8) * 128 + lane * 4];
                af[mi][0] = v.x; af[mi][1] = v.y; af[mi][2] = v.z; af[mi][3] = v.w;
            }
            #pragma unroll
            for (int nj = 0; nj < 4; nj++) {
                uint2 v = *(const uint2*)&Bs[(((nbl + nj) * 4 + ks8) * 64) + lane * 2];
                bf[nj][0] = v.x; bf[nj][1] = v.y;
            }
            #pragma unroll
            for (int mi = 0; mi < 4; mi++)
                #pragma unroll
                for (int nj = 0; nj < 4; nj++)
                    mma_tf32(acc[mi][nj], af[mi], bf[nj]);
        }
    }

    #pragma unroll
    for (int mi = 0; mi < 4; mi++) {
        #pragma unroll
        for (int nj = 0; nj < 4; nj++) {
            #pragma unroll
            for (int hf = 0; hf < 2; hf++) {
                int m = mt * 128 + wm * 64 + mi * 16 + lr + hf * 8;
                int n = nt * 128 + wn * 32 + nj * 8 + (lc << 1);
                float2 v;
                v.x = acc[mi][nj][hf * 2 + 0] + bo[n];
                v.y = acc[mi][nj][hf * 2 + 1] + bo[n + 1];
                *(float2*)&out[(size_t)m * D + n] = v;
            }
        }
    }
}

// ---------------------------------------------------------------------------
extern "C" void kernel_launch(void* const* d_in, const int* in_sizes, int n_in,
                              void* d_out, int out_size)
{
    const float* x  = (const float*)d_in[0];
    const float* Wq = (const float*)d_in[1];
    const float* bq = (const float*)d_in[2];
    const float* Wk = (const float*)d_in[3];
    const float* bk = (const float*)d_in[4];
    const float* Wv = (const float*)d_in[5];
    const float* bv = (const float*)d_in[6];
    const float* Wo = (const float*)d_in[7];
    const float* bo = (const float*)d_in[8];

    float* out   = (float*)d_out;
    float* probs = out + OUT_ELEMS;

    static bool attr_done = false;
    if (!attr_done) {
        cudaFuncSetAttribute(qkv_kernel,
                             cudaFuncAttributeMaxDynamicSharedMemorySize, QKV_SMEM);
        cudaFuncSetAttribute(attn_kernel,
                             cudaFuncAttributeMaxDynamicSharedMemorySize, ATTN_SMEM);
        cudaFuncSetAttribute(out_kernel,
                             cudaFuncAttributeMaxDynamicSharedMemorySize, OUT_SMEM);
        attr_done = true;
    }

    repack_kernel<<<(XE + 255) / 256, 256>>>(Wq, Wk, Wv, bq, bk, bv, x, Wo);
    qkv_kernel<<<dim3(M_TOT / 128, NQKV / 128), 256, QKV_SMEM>>>();
    attn_kernel<<<dim3(S / 128, BH), 256, ATTN_SMEM>>>(probs);
    out_kernel<<<dim3(M_TOT / 128, D / 128), 256, OUT_SMEM>>>(bo, out);
}